// round 4
// baseline (speedup 1.0000x reference)
#include <cuda_runtime.h>
#include <math.h>

// ---------------- problem constants ----------------
#define D_MODELc 1024
#define SEQc     2048
#define BATCHc   2
#define NTOK     (BATCHc*SEQc)     // 4096 tokens
#define D_HEADc  64
#define N_HEADc  16
#define D_MLPc   4096
#define LN_EPSc  1e-5f

// ---------------- device scratch (no runtime allocation allowed) ----------------
__device__ float g_wqkv[(size_t)D_MODELc * 3 * D_MODELc];       // [1024][3072] repacked
__device__ float g_qkv [(size_t)NTOK * 3 * D_MODELc];           // [4096][3072] q|k|v
__device__ float g_att [(size_t)NTOK * D_MODELc];               // [4096][1024] head_out (concat)
__device__ float g_proj[(size_t)NTOK * D_MODELc];               // head_out @ wo
__device__ float g_x1  [(size_t)NTOK * D_MODELc];               // x + LN1(proj)
__device__ float g_mlph[(size_t)NTOK * D_MLPc];                 // relu(x1@w_in+b_in)
__device__ float g_mlp [(size_t)NTOK * D_MODELc];               // mlp output

// ---------------- repack wq/wk/wv [H,D,dh] -> W [D, 3*D] ----------------
__global__ void repack_qkv_kernel(const float* __restrict__ wq,
                                  const float* __restrict__ wk,
                                  const float* __restrict__ wv) {
    int idx = blockIdx.x * blockDim.x + threadIdx.x;
    if (idx >= D_MODELc * 3 * D_MODELc) return;
    int d  = idx / 3072;
    int c  = idx - d * 3072;
    int p  = c >> 10;          // 0=q,1=k,2=v
    int hc = c & 1023;
    int h  = hc >> 6;
    int e  = hc & 63;
    const float* w = (p == 0) ? wq : (p == 1 ? wk : wv);
    // w[h][d][e] with shape [16,1024,64]
    g_wqkv[idx] = w[((size_t)(h << 10) + d) * 64 + e];
}

// ---------------- SGEMM: C[M,N] = A[M,K] @ B[K,N] (+bias)(+relu), all row-major ----------------
// BM=BN=128, BK=8, 256 threads, 8x8 per-thread microtile. M,N%128==0, K%8==0 guaranteed.
template<bool RELU>
__global__ __launch_bounds__(256, 2)
void sgemm_kernel(const float* __restrict__ A, const float* __restrict__ B,
                  const float* __restrict__ bias, float* __restrict__ C,
                  int M, int N, int K) {
    __shared__ float As[8][128];
    __shared__ float Bs[8][128];
    const int tid = threadIdx.x;
    const int tx = tid & 15, ty = tid >> 4;
    const float* Ap = A + (size_t)blockIdx.y * 128 * K;
    const float* Bp = B + (size_t)blockIdx.x * 128;
    const int aRow = tid >> 1,  aCol = (tid & 1) << 2;    // 128 rows x 8 cols via float4
    const int bRow = tid >> 5,  bCol = (tid & 31) << 2;   // 8 rows x 128 cols via float4

    float acc[8][8];
#pragma unroll
    for (int i = 0; i < 8; i++)
#pragma unroll
        for (int j = 0; j < 8; j++) acc[i][j] = 0.f;

    for (int k0 = 0; k0 < K; k0 += 8) {
        float4 a4 = *(const float4*)(Ap + (size_t)aRow * K + k0 + aCol);
        As[aCol + 0][aRow] = a4.x; As[aCol + 1][aRow] = a4.y;
        As[aCol + 2][aRow] = a4.z; As[aCol + 3][aRow] = a4.w;
        *(float4*)(&Bs[bRow][bCol]) = *(const float4*)(Bp + (size_t)(k0 + bRow) * N + bCol);
        __syncthreads();
#pragma unroll
        for (int k = 0; k < 8; k++) {
            float4 a0 = *(const float4*)(&As[k][ty << 3]);
            float4 a1 = *(const float4*)(&As[k][(ty << 3) + 4]);
            float4 b0 = *(const float4*)(&Bs[k][tx << 3]);
            float4 b1 = *(const float4*)(&Bs[k][(tx << 3) + 4]);
            float ra[8] = {a0.x, a0.y, a0.z, a0.w, a1.x, a1.y, a1.z, a1.w};
            float rb[8] = {b0.x, b0.y, b0.z, b0.w, b1.x, b1.y, b1.z, b1.w};
#pragma unroll
            for (int i = 0; i < 8; i++)
#pragma unroll
                for (int j = 0; j < 8; j++) acc[i][j] += ra[i] * rb[j];
        }
        __syncthreads();
    }

    const int crow0 = blockIdx.y * 128 + (ty << 3);
    const int ccol0 = blockIdx.x * 128 + (tx << 3);
    float bv[8];
#pragma unroll
    for (int j = 0; j < 8; j++) bv[j] = bias ? bias[ccol0 + j] : 0.f;
#pragma unroll
    for (int i = 0; i < 8; i++) {
#pragma unroll
        for (int j = 0; j < 8; j++) {
            float v = acc[i][j] + bv[j];
            if (RELU) v = fmaxf(v, 0.f);
            acc[i][j] = v;
        }
        *(float4*)(C + (size_t)(crow0 + i) * N + ccol0)     = make_float4(acc[i][0], acc[i][1], acc[i][2], acc[i][3]);
        *(float4*)(C + (size_t)(crow0 + i) * N + ccol0 + 4) = make_float4(acc[i][4], acc[i][5], acc[i][6], acc[i][7]);
    }
}

// ---------------- flash attention (causal), fp32 ----------------
// grid: (SEQ/64, B*H); block 256 threads. Br=Bc=64, online softmax.
// qkv layout: [token][3072] = q(1024)|k(1024)|v(1024), per-head 64 contiguous.
#define ATT_AS 65                                   // smem row stride (pad)
#define ATT_SMEM (4 * 64 * ATT_AS * 4)              // Qs,Ks,Vs,Ps

__global__ __launch_bounds__(256, 2)
void attn_kernel(const float* __restrict__ qkv, float* __restrict__ out) {
    extern __shared__ float sm[];
    float* Qs = sm;                      // [r][e]
    float* Ks = Qs + 64 * ATT_AS;        // [c][e]
    float* Vs = Ks + 64 * ATT_AS;        // [j][d]
    float* Ps = Vs + 64 * ATT_AS;        // [r][j]

    const int b  = blockIdx.y >> 4;
    const int h  = blockIdx.y & 15;
    const int rt = blockIdx.x;
    const int r0 = rt * 64;
    const int tid = threadIdx.x, tx = tid & 15, ty = tid >> 4;

    const size_t base = (size_t)b * SEQc * 3072 + (size_t)h * 64;
    const float* qg = qkv + base;
    const float* kg = qkv + base + 1024;
    const float* vg = qkv + base + 2048;

    // load Q tile [64 rows][64 e], natural layout
#pragma unroll
    for (int it = 0; it < 4; it++) {
        int li = tid + it * 256;         // 0..1023 float4s
        int r  = li >> 4;
        int e4 = (li & 15) << 2;
        float4 q = *(const float4*)(qg + (size_t)(r0 + r) * 3072 + e4);
        Qs[r * ATT_AS + e4 + 0] = q.x; Qs[r * ATT_AS + e4 + 1] = q.y;
        Qs[r * ATT_AS + e4 + 2] = q.z; Qs[r * ATT_AS + e4 + 3] = q.w;
    }

    float m[4], l[4], acc[4][4];
#pragma unroll
    for (int i = 0; i < 4; i++) {
        m[i] = -1e30f; l[i] = 0.f;
#pragma unroll
        for (int j = 0; j < 4; j++) acc[i][j] = 0.f;
    }

    for (int kc = 0; kc <= rt; kc++) {
        __syncthreads();   // prev iter's PV done; Q visible (first iter)
        // load K,V tiles
#pragma unroll
        for (int it = 0; it < 4; it++) {
            int li = tid + it * 256;
            int r  = li >> 4;
            int e4 = (li & 15) << 2;
            size_t go = (size_t)(kc * 64 + r) * 3072 + e4;
            float4 kk = *(const float4*)(kg + go);
            Ks[r * ATT_AS + e4 + 0] = kk.x; Ks[r * ATT_AS + e4 + 1] = kk.y;
            Ks[r * ATT_AS + e4 + 2] = kk.z; Ks[r * ATT_AS + e4 + 3] = kk.w;
            float4 vv = *(const float4*)(vg + go);
            Vs[r * ATT_AS + e4 + 0] = vv.x; Vs[r * ATT_AS + e4 + 1] = vv.y;
            Vs[r * ATT_AS + e4 + 2] = vv.z; Vs[r * ATT_AS + e4 + 3] = vv.w;
        }
        __syncthreads();

        // S = Q K^T (4x4 microtile per thread)
        float s[4][4];
#pragma unroll
        for (int i = 0; i < 4; i++)
#pragma unroll
            for (int j = 0; j < 4; j++) s[i][j] = 0.f;
        for (int k = 0; k < 64; k++) {
            float qr[4], kr[4];
#pragma unroll
            for (int i = 0; i < 4; i++) qr[i] = Qs[(ty * 4 + i) * ATT_AS + k];
#pragma unroll
            for (int j = 0; j < 4; j++) kr[j] = Ks[(tx * 4 + j) * ATT_AS + k];
#pragma unroll
            for (int i = 0; i < 4; i++)
#pragma unroll
                for (int j = 0; j < 4; j++) s[i][j] += qr[i] * kr[j];
        }
        const float scale = 0.125f;   // 1/sqrt(64)
#pragma unroll
        for (int i = 0; i < 4; i++)
#pragma unroll
            for (int j = 0; j < 4; j++) s[i][j] *= scale;
        if (kc == rt) {               // diagonal tile: mask col>row (local==global offsets)
#pragma unroll
            for (int i = 0; i < 4; i++)
#pragma unroll
                for (int j = 0; j < 4; j++)
                    if (tx * 4 + j > ty * 4 + i) s[i][j] = -1e30f;
        }

        // online softmax per row (row owned by 16 tx-threads; reduce via shfl within 16-lane group)
#pragma unroll
        for (int i = 0; i < 4; i++) {
            float tmax = fmaxf(fmaxf(s[i][0], s[i][1]), fmaxf(s[i][2], s[i][3]));
#pragma unroll
            for (int o = 8; o; o >>= 1) tmax = fmaxf(tmax, __shfl_xor_sync(0xffffffffu, tmax, o));
            float newm = fmaxf(m[i], tmax);
            float tl = 0.f;
#pragma unroll
            for (int j = 0; j < 4; j++) { float p = __expf(s[i][j] - newm); s[i][j] = p; tl += p; }
#pragma unroll
            for (int o = 8; o; o >>= 1) tl += __shfl_xor_sync(0xffffffffu, tl, o);
            float alpha = __expf(m[i] - newm);
            m[i] = newm;
            l[i] = l[i] * alpha + tl;
#pragma unroll
            for (int j = 0; j < 4; j++) acc[i][j] *= alpha;
#pragma unroll
            for (int j = 0; j < 4; j++) Ps[(ty * 4 + i) * ATT_AS + tx * 4 + j] = s[i][j];
        }
        __syncthreads();

        // acc += P @ V
        for (int j = 0; j < 64; j++) {
            float vr[4];
#pragma unroll
            for (int d = 0; d < 4; d++) vr[d] = Vs[j * ATT_AS + tx * 4 + d];
#pragma unroll
            for (int i = 0; i < 4; i++) {
                float p = Ps[(ty * 4 + i) * ATT_AS + j];
#pragma unroll
                for (int d = 0; d < 4; d++) acc[i][d] += p * vr[d];
            }
        }
    }

    // write head_out in concat layout [token][h*64 + d]
#pragma unroll
    for (int i = 0; i < 4; i++) {
        float inv = 1.f / l[i];
        float4 o4 = make_float4(acc[i][0] * inv, acc[i][1] * inv, acc[i][2] * inv, acc[i][3] * inv);
        *(float4*)(out + (size_t)(b * SEQc + r0 + ty * 4 + i) * D_MODELc + h * 64 + tx * 4) = o4;
    }
}

// ---------------- LayerNorm + residual: out = resid + LN(v)*g + b ----------------
__global__ void ln_residual_kernel(const float* __restrict__ resid,
                                   const float* __restrict__ v,
                                   const float* __restrict__ g,
                                   const float* __restrict__ beta,
                                   float* __restrict__ out) {
    __shared__ float red[16];
    const int row = blockIdx.x;
    const int t = threadIdx.x;
    const float* vr = v + (size_t)row * D_MODELc;
    float4 xv = *(const float4*)(vr + t * 4);
    float s  = xv.x + xv.y + xv.z + xv.w;
    float s2 = xv.x * xv.x + xv.y * xv.y + xv.z * xv.z + xv.w * xv.w;
#pragma unroll
    for (int o = 16; o; o >>= 1) {
        s  += __shfl_xor_sync(0xffffffffu, s,  o);
        s2 += __shfl_xor_sync(0xffffffffu, s2, o);
    }
    int wid = t >> 5;
    if ((t & 31) == 0) { red[wid] = s; red[8 + wid] = s2; }
    __syncthreads();
    float S = 0.f, S2 = 0.f;
#pragma unroll
    for (int i = 0; i < 8; i++) { S += red[i]; S2 += red[8 + i]; }
    float mu   = S * (1.f / D_MODELc);
    float var  = S2 * (1.f / D_MODELc) - mu * mu;
    float rstd = rsqrtf(var + LN_EPSc);

    int c = t * 4;
    float4 rr = *(const float4*)(resid + (size_t)row * D_MODELc + c);
    float4 gg = *(const float4*)(g + c);
    float4 bb = *(const float4*)(beta + c);
    float4 o;
    o.x = rr.x + (xv.x - mu) * rstd * gg.x + bb.x;
    o.y = rr.y + (xv.y - mu) * rstd * gg.y + bb.y;
    o.z = rr.z + (xv.z - mu) * rstd * gg.z + bb.z;
    o.w = rr.w + (xv.w - mu) * rstd * gg.w + bb.w;
    *(float4*)(out + (size_t)row * D_MODELc + c) = o;
}

// ---------------- launch ----------------
extern "C" void kernel_launch(void* const* d_in, const int* in_sizes, int n_in,
                              void* d_out, int out_size) {
    (void)in_sizes; (void)n_in; (void)out_size;
    const float* x     = (const float*)d_in[0];
    const float* wq    = (const float*)d_in[1];
    const float* wk    = (const float*)d_in[2];
    const float* wv    = (const float*)d_in[3];
    const float* wo    = (const float*)d_in[4];
    const float* w_in  = (const float*)d_in[5];
    const float* b_in  = (const float*)d_in[6];
    const float* w_out = (const float*)d_in[7];
    const float* b_out = (const float*)d_in[8];
    const float* g1    = (const float*)d_in[9];
    const float* bt1   = (const float*)d_in[10];
    const float* g2    = (const float*)d_in[11];
    const float* bt2   = (const float*)d_in[12];
    float* out = (float*)d_out;

    float *wqkv, *qkv, *att, *proj, *x1, *mlph, *mlp;
    cudaGetSymbolAddress((void**)&wqkv, g_wqkv);
    cudaGetSymbolAddress((void**)&qkv,  g_qkv);
    cudaGetSymbolAddress((void**)&att,  g_att);
    cudaGetSymbolAddress((void**)&proj, g_proj);
    cudaGetSymbolAddress((void**)&x1,   g_x1);
    cudaGetSymbolAddress((void**)&mlph, g_mlph);
    cudaGetSymbolAddress((void**)&mlp,  g_mlp);

    cudaFuncSetAttribute(attn_kernel, cudaFuncAttributeMaxDynamicSharedMemorySize, ATT_SMEM);

    // 1. repack qkv weights -> [1024, 3072]
    repack_qkv_kernel<<<(D_MODELc * 3 * D_MODELc + 255) / 256, 256>>>(wq, wk, wv);
    // 2. fused QKV projection: [4096,1024] @ [1024,3072]
    sgemm_kernel<false><<<dim3(3072 / 128, NTOK / 128), 256>>>(x, wqkv, nullptr, qkv, NTOK, 3072, 1024);
    // 3. causal flash attention -> head_out [4096,1024]
    attn_kernel<<<dim3(SEQc / 64, BATCHc * N_HEADc), 256, ATT_SMEM>>>(qkv, att);
    // 4. output projection: head_out @ wo
    sgemm_kernel<false><<<dim3(D_MODELc / 128, NTOK / 128), 256>>>(att, wo, nullptr, proj, NTOK, D_MODELc, D_MODELc);
    // 5. x1 = x + LN(proj)
    ln_residual_kernel<<<NTOK, 256>>>(x, proj, g1, bt1, x1);
    // 6. mlp hidden: relu(x1 @ w_in + b_in)
    sgemm_kernel<true><<<dim3(D_MLPc / 128, NTOK / 128), 256>>>(x1, w_in, b_in, mlph, NTOK, D_MLPc, D_MODELc);
    // 7. mlp out: mlph @ w_out + b_out
    sgemm_kernel<false><<<dim3(D_MODELc / 128, NTOK / 128), 256>>>(mlph, w_out, b_out, mlp, NTOK, D_MODELc, D_MLPc);
    // 8. out = x1 + LN(mlp)
    ln_residual_kernel<<<NTOK, 256>>>(x1, mlp, g2, bt2, out);
}

// round 6
// speedup vs baseline: 1.7777x; 1.7777x over previous
#include <cuda_runtime.h>
#include <cuda_bf16.h>
#include <cstdint>
#include <math.h>

// ---------------- problem constants ----------------
#define D_MODELc 1024
#define SEQc     2048
#define BATCHc   2
#define NTOK     (BATCHc*SEQc)     // 4096 tokens
#define D_HEADc  64
#define N_HEADc  16
#define D_MLPc   4096
#define LN_EPSc  1e-5f

// ---------------- device scratch (no runtime allocation allowed) ----------------
__device__ float g_qkv [(size_t)NTOK * 3 * D_MODELc];           // [4096][3072] q|k|v
__device__ float g_att [(size_t)NTOK * D_MODELc];               // [4096][1024] head_out (concat)
__device__ float g_proj[(size_t)NTOK * D_MODELc];               // head_out @ wo
__device__ float g_x1  [(size_t)NTOK * D_MODELc];               // x + LN1(proj)
__device__ float g_mlph[(size_t)NTOK * D_MLPc];                 // relu(x1@w_in+b_in)
__device__ float g_mlp [(size_t)NTOK * D_MODELc];               // mlp output
// bf16 split operand buffers (reused per-GEMM; launches are stream-ordered)
__device__ __nv_bfloat16 g_ahi[(size_t)NTOK * D_MLPc];
__device__ __nv_bfloat16 g_alo[(size_t)NTOK * D_MLPc];
__device__ __nv_bfloat16 g_bhi[(size_t)D_MLPc * D_MODELc];
__device__ __nv_bfloat16 g_blo[(size_t)D_MLPc * D_MODELc];

// ================= PTX helpers (baseline sm_80+ features only) =================
__device__ __forceinline__ uint32_t smem_u32(const void* p) {
    uint32_t a;
    asm("{ .reg .u64 t; cvta.to.shared.u64 t, %1; cvt.u32.u64 %0, t; }" : "=r"(a) : "l"(p));
    return a;
}
#define CP_ASYNC16(dst, src) \
    asm volatile("cp.async.cg.shared.global [%0], [%1], 16;" :: "r"(dst), "l"(src))
#define CP_COMMIT()  asm volatile("cp.async.commit_group;" ::: "memory")
#define CP_WAIT0()   asm volatile("cp.async.wait_group 0;" ::: "memory")
#define LDSM_X4(r0, r1, r2, r3, addr) \
    asm volatile("ldmatrix.sync.aligned.m8n8.x4.shared.b16 {%0,%1,%2,%3}, [%4];" \
        : "=r"(r0), "=r"(r1), "=r"(r2), "=r"(r3) : "r"(addr))
#define MMA_BF16(d, a, b) \
    asm volatile("mma.sync.aligned.m16n8k16.row.col.f32.bf16.bf16.f32 " \
        "{%0,%1,%2,%3},{%4,%5,%6,%7},{%8,%9},{%0,%1,%2,%3};" \
        : "+f"((d)[0]), "+f"((d)[1]), "+f"((d)[2]), "+f"((d)[3]) \
        : "r"((a)[0]), "r"((a)[1]), "r"((a)[2]), "r"((a)[3]), "r"((b)[0]), "r"((b)[1]))

// ================= split / transpose kernels =================
__global__ void asplit_kernel(const float* __restrict__ src,
                              __nv_bfloat16* __restrict__ dhi,
                              __nv_bfloat16* __restrict__ dlo, int n4) {
    int i = blockIdx.x * blockDim.x + threadIdx.x;
    if (i >= n4) return;
    float4 v = ((const float4*)src)[i];
    __nv_bfloat16 hx = __float2bfloat16(v.x), hy = __float2bfloat16(v.y);
    __nv_bfloat16 hz = __float2bfloat16(v.z), hw = __float2bfloat16(v.w);
    __nv_bfloat16 lx = __float2bfloat16(v.x - __bfloat162float(hx));
    __nv_bfloat16 ly = __float2bfloat16(v.y - __bfloat162float(hy));
    __nv_bfloat16 lz = __float2bfloat16(v.z - __bfloat162float(hz));
    __nv_bfloat16 lw = __float2bfloat16(v.w - __bfloat162float(hw));
    ((__nv_bfloat162*)dhi)[2*i]   = __nv_bfloat162(hx, hy);
    ((__nv_bfloat162*)dhi)[2*i+1] = __nv_bfloat162(hz, hw);
    ((__nv_bfloat162*)dlo)[2*i]   = __nv_bfloat162(lx, ly);
    ((__nv_bfloat162*)dlo)[2*i+1] = __nv_bfloat162(lz, lw);
}

// tiled transpose+split: src [R][C] fp32 -> dst [C][R] bf16 hi/lo
__global__ void tsplit_kernel(const float* __restrict__ src,
                              __nv_bfloat16* __restrict__ dhi,
                              __nv_bfloat16* __restrict__ dlo, int R, int C) {
    __shared__ float t[32][33];
    int c0 = blockIdx.x * 32, r0 = blockIdx.y * 32;
#pragma unroll
    for (int i = 0; i < 4; i++)
        t[threadIdx.y + i*8][threadIdx.x] = src[(size_t)(r0 + threadIdx.y + i*8) * C + c0 + threadIdx.x];
    __syncthreads();
#pragma unroll
    for (int i = 0; i < 4; i++) {
        float v = t[threadIdx.x][threadIdx.y + i*8];
        __nv_bfloat16 h = __float2bfloat16(v);
        size_t o = (size_t)(c0 + threadIdx.y + i*8) * R + r0 + threadIdx.x;
        dhi[o] = h;
        dlo[o] = __float2bfloat16(v - __bfloat162float(h));
    }
}

// wq/wk/wv [16][1024][64] -> Wt [3072][1024] bf16 hi/lo (n = p*1024 + h*64 + e, k = d_model)
__global__ void qkv_tsplit_kernel(const float* __restrict__ wq, const float* __restrict__ wk,
                                  const float* __restrict__ wv,
                                  __nv_bfloat16* __restrict__ dhi,
                                  __nv_bfloat16* __restrict__ dlo) {
    __shared__ float t[32][33];
    int z = blockIdx.z, p = z >> 4, h = z & 15;
    const float* src = (p == 0 ? wq : (p == 1 ? wk : wv)) + (size_t)h * 1024 * 64;
    int c0 = blockIdx.x * 32, r0 = blockIdx.y * 32;
#pragma unroll
    for (int i = 0; i < 4; i++)
        t[threadIdx.y + i*8][threadIdx.x] = src[(size_t)(r0 + threadIdx.y + i*8) * 64 + c0 + threadIdx.x];
    __syncthreads();
    int nbase = (p << 10) + (h << 6);
#pragma unroll
    for (int i = 0; i < 4; i++) {
        float v = t[threadIdx.x][threadIdx.y + i*8];
        __nv_bfloat16 hh = __float2bfloat16(v);
        size_t o = (size_t)(nbase + c0 + threadIdx.y + i*8) * 1024 + r0 + threadIdx.x;
        dhi[o] = hh;
        dlo[o] = __float2bfloat16(v - __bfloat162float(hh));
    }
}

// ================= HMMA split-bf16 GEMM (mma.sync m16n8k16) =================
// C[M,N] = (Ahi+Alo)[M,K] @ (Bhi+Blo)[N,K]^T (+bias)(+relu), fp32 accumulate.
// 128x128 C-tile, BK=32, 256 threads (8 warps, 64x32 each), cp.async double buffer.
// SMEM tile: [128 rows][32 bf16], row stride 40 bf16 (80B) -> conflict-free ldmatrix.
#define TGP_STRIDE_B 80                 // bytes per smem row
#define TGP_MAT      10240              // bytes per matrix tile (128*80)
#define TGP_STAGE    40960              // 4 matrices per stage
#define TGP_SMEM     81920              // 2 stages

__device__ __forceinline__ void tg_load_stage(
        const __nv_bfloat16* __restrict__ s0, const __nv_bfloat16* __restrict__ s1,
        const __nv_bfloat16* __restrict__ s2, const __nv_bfloat16* __restrict__ s3,
        int K, int k0, uint32_t sbase, int tid) {
    const __nv_bfloat16* srcs[4] = {s0, s1, s2, s3};
#pragma unroll
    for (int m = 0; m < 4; m++) {
        const __nv_bfloat16* s = srcs[m];
        uint32_t mb = sbase + m * TGP_MAT;
#pragma unroll
        for (int j = 0; j < 2; j++) {
            int id  = tid + (j << 8);      // 0..511 chunks (16B each)
            int row = id >> 2, kc = id & 3;
            const void* g = s + (size_t)row * K + k0 + (kc << 3);
            CP_ASYNC16(mb + row * TGP_STRIDE_B + (kc << 4), g);
        }
    }
}

template<bool RELU>
__global__ __launch_bounds__(256)
void tc_gemm_kernel(const __nv_bfloat16* __restrict__ Ahi, const __nv_bfloat16* __restrict__ Alo,
                    const __nv_bfloat16* __restrict__ Bhi, const __nv_bfloat16* __restrict__ Blo,
                    const float* __restrict__ bias, float* __restrict__ C,
                    int M, int N, int K) {
    extern __shared__ char smem[];
    const uint32_t sb = smem_u32(smem);
    const int tid = threadIdx.x, wid = tid >> 5, lane = tid & 31;
    const int wm = wid >> 2, wn = wid & 3;            // warp grid 2 x 4
    const int m0 = blockIdx.y * 128, n0 = blockIdx.x * 128;

    const __nv_bfloat16* pAh = Ahi + (size_t)m0 * K;
    const __nv_bfloat16* pAl = Alo + (size_t)m0 * K;
    const __nv_bfloat16* pBh = Bhi + (size_t)n0 * K;
    const __nv_bfloat16* pBl = Blo + (size_t)n0 * K;

    float acc[4][4][4];
#pragma unroll
    for (int i = 0; i < 4; i++)
#pragma unroll
        for (int j = 0; j < 4; j++)
#pragma unroll
            for (int r = 0; r < 4; r++) acc[i][j][r] = 0.f;

    const int nchunk = K >> 5;

    tg_load_stage(pAh, pAl, pBh, pBl, K, 0, sb, tid);
    CP_COMMIT();

    // precomputed ldmatrix lane addressing (byte offsets within a tile)
    const uint32_t a_row = (uint32_t)(wm * 64 + (lane & 15));           // + mt*16
    const uint32_t a_koff = (uint32_t)((lane >> 4) << 4);               // 16B half
    const uint32_t b_row = (uint32_t)(wn * 32 + ((lane >> 4) << 3) + (lane & 7));  // + p*16
    const uint32_t b_koff = (uint32_t)(((lane >> 3) & 1) << 4);

    for (int c = 0; c < nchunk; c++) {
        CP_WAIT0();
        __syncthreads();
        if (c + 1 < nchunk)
            tg_load_stage(pAh, pAl, pBh, pBl, K, (c + 1) << 5,
                          sb + ((c + 1) & 1) * TGP_STAGE, tid);
        CP_COMMIT();

        const uint32_t st = sb + (c & 1) * TGP_STAGE;
#pragma unroll
        for (int ks = 0; ks < 2; ks++) {
            uint32_t ahi[4][4], alo[4][4], bhi[4][2], blo[4][2];
#pragma unroll
            for (int mt = 0; mt < 4; mt++) {
                uint32_t ad = st + (a_row + mt * 16) * TGP_STRIDE_B + ks * 32 + a_koff;
                LDSM_X4(ahi[mt][0], ahi[mt][1], ahi[mt][2], ahi[mt][3], ad);
                LDSM_X4(alo[mt][0], alo[mt][1], alo[mt][2], alo[mt][3], ad + TGP_MAT);
            }
#pragma unroll
            for (int p = 0; p < 2; p++) {
                uint32_t bd = st + 2 * TGP_MAT + (b_row + p * 16) * TGP_STRIDE_B + ks * 32 + b_koff;
                LDSM_X4(bhi[2*p][0], bhi[2*p][1], bhi[2*p+1][0], bhi[2*p+1][1], bd);
                LDSM_X4(blo[2*p][0], blo[2*p][1], blo[2*p+1][0], blo[2*p+1][1], bd + TGP_MAT);
            }
#pragma unroll
            for (int mt = 0; mt < 4; mt++)
#pragma unroll
                for (int nt = 0; nt < 4; nt++) {
                    MMA_BF16(acc[mt][nt], ahi[mt], bhi[nt]);
                    MMA_BF16(acc[mt][nt], ahi[mt], blo[nt]);
                    MMA_BF16(acc[mt][nt], alo[mt], bhi[nt]);
                }
        }
        __syncthreads();
    }

    // epilogue: direct register -> gmem
#pragma unroll
    for (int mt = 0; mt < 4; mt++) {
        const int r0 = m0 + wm * 64 + mt * 16 + (lane >> 2);
#pragma unroll
        for (int nt = 0; nt < 4; nt++) {
            const int c0 = n0 + wn * 32 + nt * 8 + ((lane & 3) << 1);
            float bx = bias ? bias[c0]     : 0.f;
            float by = bias ? bias[c0 + 1] : 0.f;
            float v0 = acc[mt][nt][0] + bx, v1 = acc[mt][nt][1] + by;
            float v2 = acc[mt][nt][2] + bx, v3 = acc[mt][nt][3] + by;
            if (RELU) {
                v0 = fmaxf(v0, 0.f); v1 = fmaxf(v1, 0.f);
                v2 = fmaxf(v2, 0.f); v3 = fmaxf(v3, 0.f);
            }
            *(float2*)(C + (size_t)r0 * N + c0)       = make_float2(v0, v1);
            *(float2*)(C + (size_t)(r0 + 8) * N + c0) = make_float2(v2, v3);
        }
    }
}

// ---------------- flash attention (causal), fp32 (unchanged, known-good) ----------------
#define ATT_AS 65
#define ATT_SMEM (4 * 64 * ATT_AS * 4)

__global__ __launch_bounds__(256, 2)
void attn_kernel(const float* __restrict__ qkv, float* __restrict__ out) {
    extern __shared__ float sm[];
    float* Qs = sm;
    float* Ks = Qs + 64 * ATT_AS;
    float* Vs = Ks + 64 * ATT_AS;
    float* Ps = Vs + 64 * ATT_AS;

    const int b  = blockIdx.y >> 4;
    const int h  = blockIdx.y & 15;
    const int rt = blockIdx.x;
    const int r0 = rt * 64;
    const int tid = threadIdx.x, tx = tid & 15, ty = tid >> 4;

    const size_t base = (size_t)b * SEQc * 3072 + (size_t)h * 64;
    const float* qg = qkv + base;
    const float* kg = qkv + base + 1024;
    const float* vg = qkv + base + 2048;

#pragma unroll
    for (int it = 0; it < 4; it++) {
        int li = tid + it * 256;
        int r  = li >> 4;
        int e4 = (li & 15) << 2;
        float4 q = *(const float4*)(qg + (size_t)(r0 + r) * 3072 + e4);
        Qs[r * ATT_AS + e4 + 0] = q.x; Qs[r * ATT_AS + e4 + 1] = q.y;
        Qs[r * ATT_AS + e4 + 2] = q.z; Qs[r * ATT_AS + e4 + 3] = q.w;
    }

    float m[4], l[4], acc[4][4];
#pragma unroll
    for (int i = 0; i < 4; i++) {
        m[i] = -1e30f; l[i] = 0.f;
#pragma unroll
        for (int j = 0; j < 4; j++) acc[i][j] = 0.f;
    }

    for (int kc = 0; kc <= rt; kc++) {
        __syncthreads();
#pragma unroll
        for (int it = 0; it < 4; it++) {
            int li = tid + it * 256;
            int r  = li >> 4;
            int e4 = (li & 15) << 2;
            size_t go = (size_t)(kc * 64 + r) * 3072 + e4;
            float4 kk = *(const float4*)(kg + go);
            Ks[r * ATT_AS + e4 + 0] = kk.x; Ks[r * ATT_AS + e4 + 1] = kk.y;
            Ks[r * ATT_AS + e4 + 2] = kk.z; Ks[r * ATT_AS + e4 + 3] = kk.w;
            float4 vv = *(const float4*)(vg + go);
            Vs[r * ATT_AS + e4 + 0] = vv.x; Vs[r * ATT_AS + e4 + 1] = vv.y;
            Vs[r * ATT_AS + e4 + 2] = vv.z; Vs[r * ATT_AS + e4 + 3] = vv.w;
        }
        __syncthreads();

        float s[4][4];
#pragma unroll
        for (int i = 0; i < 4; i++)
#pragma unroll
            for (int j = 0; j < 4; j++) s[i][j] = 0.f;
        for (int k = 0; k < 64; k++) {
            float qr[4], kr[4];
#pragma unroll
            for (int i = 0; i < 4; i++) qr[i] = Qs[(ty * 4 + i) * ATT_AS + k];
#pragma unroll
            for (int j = 0; j < 4; j++) kr[j] = Ks[(tx * 4 + j) * ATT_AS + k];
#pragma unroll
            for (int i = 0; i < 4; i++)
#pragma unroll
                for (int j = 0; j < 4; j++) s[i][j] += qr[i] * kr[j];
        }
        const float scale = 0.125f;
#pragma unroll
        for (int i = 0; i < 4; i++)
#pragma unroll
            for (int j = 0; j < 4; j++) s[i][j] *= scale;
        if (kc == rt) {
#pragma unroll
            for (int i = 0; i < 4; i++)
#pragma unroll
                for (int j = 0; j < 4; j++)
                    if (tx * 4 + j > ty * 4 + i) s[i][j] = -1e30f;
        }

#pragma unroll
        for (int i = 0; i < 4; i++) {
            float tmax = fmaxf(fmaxf(s[i][0], s[i][1]), fmaxf(s[i][2], s[i][3]));
#pragma unroll
            for (int o = 8; o; o >>= 1) tmax = fmaxf(tmax, __shfl_xor_sync(0xffffffffu, tmax, o));
            float newm = fmaxf(m[i], tmax);
            float tl = 0.f;
#pragma unroll
            for (int j = 0; j < 4; j++) { float p = __expf(s[i][j] - newm); s[i][j] = p; tl += p; }
#pragma unroll
            for (int o = 8; o; o >>= 1) tl += __shfl_xor_sync(0xffffffffu, tl, o);
            float alpha = __expf(m[i] - newm);
            m[i] = newm;
            l[i] = l[i] * alpha + tl;
#pragma unroll
            for (int j = 0; j < 4; j++) acc[i][j] *= alpha;
#pragma unroll
            for (int j = 0; j < 4; j++) Ps[(ty * 4 + i) * ATT_AS + tx * 4 + j] = s[i][j];
        }
        __syncthreads();

        for (int j = 0; j < 64; j++) {
            float vr[4];
#pragma unroll
            for (int d = 0; d < 4; d++) vr[d] = Vs[j * ATT_AS + tx * 4 + d];
#pragma unroll
            for (int i = 0; i < 4; i++) {
                float p = Ps[(ty * 4 + i) * ATT_AS + j];
#pragma unroll
                for (int d = 0; d < 4; d++) acc[i][d] += p * vr[d];
            }
        }
    }

#pragma unroll
    for (int i = 0; i < 4; i++) {
        float inv = 1.f / l[i];
        float4 o4 = make_float4(acc[i][0] * inv, acc[i][1] * inv, acc[i][2] * inv, acc[i][3] * inv);
        *(float4*)(out + (size_t)(b * SEQc + r0 + ty * 4 + i) * D_MODELc + h * 64 + tx * 4) = o4;
    }
}

// ---------------- LayerNorm + residual (unchanged) ----------------
__global__ void ln_residual_kernel(const float* __restrict__ resid,
                                   const float* __restrict__ v,
                                   const float* __restrict__ g,
                                   const float* __restrict__ beta,
                                   float* __restrict__ out) {
    __shared__ float red[16];
    const int row = blockIdx.x;
    const int t = threadIdx.x;
    const float* vr = v + (size_t)row * D_MODELc;
    float4 xv = *(const float4*)(vr + t * 4);
    float s  = xv.x + xv.y + xv.z + xv.w;
    float s2 = xv.x * xv.x + xv.y * xv.y + xv.z * xv.z + xv.w * xv.w;
#pragma unroll
    for (int o = 16; o; o >>= 1) {
        s  += __shfl_xor_sync(0xffffffffu, s,  o);
        s2 += __shfl_xor_sync(0xffffffffu, s2, o);
    }
    int wid = t >> 5;
    if ((t & 31) == 0) { red[wid] = s; red[8 + wid] = s2; }
    __syncthreads();
    float S = 0.f, S2 = 0.f;
#pragma unroll
    for (int i = 0; i < 8; i++) { S += red[i]; S2 += red[8 + i]; }
    float mu   = S * (1.f / D_MODELc);
    float var  = S2 * (1.f / D_MODELc) - mu * mu;
    float rstd = rsqrtf(var + LN_EPSc);

    int c = t * 4;
    float4 rr = *(const float4*)(resid + (size_t)row * D_MODELc + c);
    float4 gg = *(const float4*)(g + c);
    float4 bb = *(const float4*)(beta + c);
    float4 o;
    o.x = rr.x + (xv.x - mu) * rstd * gg.x + bb.x;
    o.y = rr.y + (xv.y - mu) * rstd * gg.y + bb.y;
    o.z = rr.z + (xv.z - mu) * rstd * gg.z + bb.z;
    o.w = rr.w + (xv.w - mu) * rstd * gg.w + bb.w;
    *(float4*)(out + (size_t)row * D_MODELc + c) = o;
}

// ---------------- launch ----------------
extern "C" void kernel_launch(void* const* d_in, const int* in_sizes, int n_in,
                              void* d_out, int out_size) {
    (void)in_sizes; (void)n_in; (void)out_size;
    const float* x     = (const float*)d_in[0];
    const float* wq    = (const float*)d_in[1];
    const float* wk    = (const float*)d_in[2];
    const float* wv    = (const float*)d_in[3];
    const float* wo    = (const float*)d_in[4];
    const float* w_in  = (const float*)d_in[5];
    const float* b_in  = (const float*)d_in[6];
    const float* w_out = (const float*)d_in[7];
    const float* b_out = (const float*)d_in[8];
    const float* g1    = (const float*)d_in[9];
    const float* bt1   = (const float*)d_in[10];
    const float* g2    = (const float*)d_in[11];
    const float* bt2   = (const float*)d_in[12];
    float* out = (float*)d_out;

    float *qkv, *att, *proj, *x1, *mlph, *mlp;
    __nv_bfloat16 *ahi, *alo, *bhi, *blo;
    cudaGetSymbolAddress((void**)&qkv,  g_qkv);
    cudaGetSymbolAddress((void**)&att,  g_att);
    cudaGetSymbolAddress((void**)&proj, g_proj);
    cudaGetSymbolAddress((void**)&x1,   g_x1);
    cudaGetSymbolAddress((void**)&mlph, g_mlph);
    cudaGetSymbolAddress((void**)&mlp,  g_mlp);
    cudaGetSymbolAddress((void**)&ahi,  g_ahi);
    cudaGetSymbolAddress((void**)&alo,  g_alo);
    cudaGetSymbolAddress((void**)&bhi,  g_bhi);
    cudaGetSymbolAddress((void**)&blo,  g_blo);

    cudaFuncSetAttribute(attn_kernel, cudaFuncAttributeMaxDynamicSharedMemorySize, ATT_SMEM);
    cudaFuncSetAttribute(tc_gemm_kernel<false>, cudaFuncAttributeMaxDynamicSharedMemorySize, TGP_SMEM);
    cudaFuncSetAttribute(tc_gemm_kernel<true>,  cudaFuncAttributeMaxDynamicSharedMemorySize, TGP_SMEM);

    dim3 tsb(32, 8);

    // ---- QKV projection: [4096,1024] @ [1024,3072] ----
    qkv_tsplit_kernel<<<dim3(2, 32, 48), tsb>>>(wq, wk, wv, bhi, blo);
    asplit_kernel<<<(NTOK * D_MODELc / 4 + 255) / 256, 256>>>(x, ahi, alo, NTOK * D_MODELc / 4);
    tc_gemm_kernel<false><<<dim3(3072 / 128, NTOK / 128), 256, TGP_SMEM>>>(
        ahi, alo, bhi, blo, nullptr, qkv, NTOK, 3072, 1024);

    // ---- causal flash attention ----
    attn_kernel<<<dim3(SEQc / 64, BATCHc * N_HEADc), 256, ATT_SMEM>>>(qkv, att);

    // ---- output projection: att @ wo ----
    tsplit_kernel<<<dim3(1024 / 32, 1024 / 32), tsb>>>(wo, bhi, blo, 1024, 1024);
    asplit_kernel<<<(NTOK * D_MODELc / 4 + 255) / 256, 256>>>(att, ahi, alo, NTOK * D_MODELc / 4);
    tc_gemm_kernel<false><<<dim3(1024 / 128, NTOK / 128), 256, TGP_SMEM>>>(
        ahi, alo, bhi, blo, nullptr, proj, NTOK, 1024, 1024);

    // ---- x1 = x + LN(proj) ----
    ln_residual_kernel<<<NTOK, 256>>>(x, proj, g1, bt1, x1);

    // ---- MLP in: relu(x1 @ w_in + b_in) ----
    tsplit_kernel<<<dim3(4096 / 32, 1024 / 32), tsb>>>(w_in, bhi, blo, 1024, 4096);
    asplit_kernel<<<(NTOK * D_MODELc / 4 + 255) / 256, 256>>>(x1, ahi, alo, NTOK * D_MODELc / 4);
    tc_gemm_kernel<true><<<dim3(4096 / 128, NTOK / 128), 256, TGP_SMEM>>>(
        ahi, alo, bhi, blo, b_in, mlph, NTOK, 4096, 1024);

    // ---- MLP out: mlph @ w_out + b_out ----
    tsplit_kernel<<<dim3(1024 / 32, 4096 / 32), tsb>>>(w_out, bhi, blo, 4096, 1024);
    asplit_kernel<<<(NTOK * D_MLPc / 4 + 255) / 256, 256>>>(mlph, ahi, alo, NTOK * D_MLPc / 4);
    tc_gemm_kernel<false><<<dim3(1024 / 128, NTOK / 128), 256, TGP_SMEM>>>(
        ahi, alo, bhi, blo, b_out, mlp, NTOK, 1024, 4096);

    // ---- out = x1 + LN(mlp) ----
    ln_residual_kernel<<<NTOK, 256>>>(x1, mlp, g2, bt2, out);
}

// round 7
// speedup vs baseline: 2.2654x; 1.2744x over previous
#include <cuda_runtime.h>
#include <cuda_bf16.h>
#include <cstdint>
#include <math.h>

// ---------------- problem constants ----------------
#define D_MODELc 1024
#define SEQc     2048
#define BATCHc   2
#define NTOK     (BATCHc*SEQc)     // 4096 tokens
#define D_MLPc   4096
#define LN_EPSc  1e-5f

// ---------------- device scratch (no runtime allocation allowed) ----------------
__device__ float g_qkv [(size_t)NTOK * 3 * D_MODELc];           // [4096][3072] q|k|v fp32
__device__ float g_proj[(size_t)NTOK * D_MODELc];               // head_out @ wo
__device__ float g_x1  [(size_t)NTOK * D_MODELc];               // x + LN1(proj)
__device__ float g_mlp [(size_t)NTOK * D_MODELc];               // mlp output
__device__ __nv_bfloat16 g_mlph_hi[(size_t)NTOK * D_MLPc];      // relu(x1@w_in+b_in) split
__device__ __nv_bfloat16 g_mlph_lo[(size_t)NTOK * D_MLPc];
__device__ __nv_bfloat16 g_ahi[(size_t)NTOK * D_MODELc];        // activation split (reused)
__device__ __nv_bfloat16 g_alo[(size_t)NTOK * D_MODELc];
__device__ __nv_bfloat16 g_bhi[(size_t)D_MLPc * D_MODELc];      // weight split (reused)
__device__ __nv_bfloat16 g_blo[(size_t)D_MLPc * D_MODELc];

// ================= PTX helpers (baseline sm_80+ features only) =================
__device__ __forceinline__ uint32_t smem_u32(const void* p) {
    uint32_t a;
    asm("{ .reg .u64 t; cvta.to.shared.u64 t, %1; cvt.u32.u64 %0, t; }" : "=r"(a) : "l"(p));
    return a;
}
#define CP_ASYNC16(dst, src) \
    asm volatile("cp.async.cg.shared.global [%0], [%1], 16;" :: "r"(dst), "l"(src))
#define CP_COMMIT()  asm volatile("cp.async.commit_group;" ::: "memory")
#define CP_WAIT0()   asm volatile("cp.async.wait_group 0;" ::: "memory")
#define LDSM_X4(r0, r1, r2, r3, addr) \
    asm volatile("ldmatrix.sync.aligned.m8n8.x4.shared.b16 {%0,%1,%2,%3}, [%4];" \
        : "=r"(r0), "=r"(r1), "=r"(r2), "=r"(r3) : "r"(addr))
#define MMA_BF16(d, a, b) \
    asm volatile("mma.sync.aligned.m16n8k16.row.col.f32.bf16.bf16.f32 " \
        "{%0,%1,%2,%3},{%4,%5,%6,%7},{%8,%9},{%0,%1,%2,%3};" \
        : "+f"((d)[0]), "+f"((d)[1]), "+f"((d)[2]), "+f"((d)[3]) \
        : "r"((a)[0]), "r"((a)[1]), "r"((a)[2]), "r"((a)[3]), "r"((b)[0]), "r"((b)[1]))

// split two fp32 into packed bf16 hi pair + lo (residual) pair
__device__ __forceinline__ void split2(float a, float b, uint32_t& hi, uint32_t& lo) {
    __nv_bfloat16 ha = __float2bfloat16(a), hb = __float2bfloat16(b);
    __nv_bfloat16 la = __float2bfloat16(a - __bfloat162float(ha));
    __nv_bfloat16 lb = __float2bfloat16(b - __bfloat162float(hb));
    __nv_bfloat162 H(ha, hb), L(la, lb);
    hi = *(uint32_t*)&H; lo = *(uint32_t*)&L;
}

// ================= split / transpose kernels =================
__global__ void asplit_kernel(const float* __restrict__ src,
                              __nv_bfloat16* __restrict__ dhi,
                              __nv_bfloat16* __restrict__ dlo, int n4) {
    int i = blockIdx.x * blockDim.x + threadIdx.x;
    if (i >= n4) return;
    float4 v = ((const float4*)src)[i];
    uint32_t h0, l0, h1, l1;
    split2(v.x, v.y, h0, l0);
    split2(v.z, v.w, h1, l1);
    ((uint2*)dhi)[i] = make_uint2(h0, h1);
    ((uint2*)dlo)[i] = make_uint2(l0, l1);
}

// tiled transpose+split: src [R][C] fp32 -> dst [C][R] bf16 hi/lo
__global__ void tsplit_kernel(const float* __restrict__ src,
                              __nv_bfloat16* __restrict__ dhi,
                              __nv_bfloat16* __restrict__ dlo, int R, int C) {
    __shared__ float t[32][33];
    int c0 = blockIdx.x * 32, r0 = blockIdx.y * 32;
#pragma unroll
    for (int i = 0; i < 4; i++)
        t[threadIdx.y + i*8][threadIdx.x] = src[(size_t)(r0 + threadIdx.y + i*8) * C + c0 + threadIdx.x];
    __syncthreads();
#pragma unroll
    for (int i = 0; i < 4; i++) {
        float v = t[threadIdx.x][threadIdx.y + i*8];
        __nv_bfloat16 h = __float2bfloat16(v);
        size_t o = (size_t)(c0 + threadIdx.y + i*8) * R + r0 + threadIdx.x;
        dhi[o] = h;
        dlo[o] = __float2bfloat16(v - __bfloat162float(h));
    }
}

// wq/wk/wv [16][1024][64] -> Wt [3072][1024] bf16 hi/lo
__global__ void qkv_tsplit_kernel(const float* __restrict__ wq, const float* __restrict__ wk,
                                  const float* __restrict__ wv,
                                  __nv_bfloat16* __restrict__ dhi,
                                  __nv_bfloat16* __restrict__ dlo) {
    __shared__ float t[32][33];
    int z = blockIdx.z, p = z >> 4, h = z & 15;
    const float* src = (p == 0 ? wq : (p == 1 ? wk : wv)) + (size_t)h * 1024 * 64;
    int c0 = blockIdx.x * 32, r0 = blockIdx.y * 32;
#pragma unroll
    for (int i = 0; i < 4; i++)
        t[threadIdx.y + i*8][threadIdx.x] = src[(size_t)(r0 + threadIdx.y + i*8) * 64 + c0 + threadIdx.x];
    __syncthreads();
    int nbase = (p << 10) + (h << 6);
#pragma unroll
    for (int i = 0; i < 4; i++) {
        float v = t[threadIdx.x][threadIdx.y + i*8];
        __nv_bfloat16 hh = __float2bfloat16(v);
        size_t o = (size_t)(nbase + c0 + threadIdx.y + i*8) * 1024 + r0 + threadIdx.x;
        dhi[o] = hh;
        dlo[o] = __float2bfloat16(v - __bfloat162float(hh));
    }
}

// ================= HMMA split-bf16 GEMM (mma.sync m16n8k16) =================
#define TGP_STRIDE_B 80
#define TGP_MAT      10240
#define TGP_STAGE    40960
#define TGP_SMEM     81920

__device__ __forceinline__ void tg_load_stage(
        const __nv_bfloat16* __restrict__ s0, const __nv_bfloat16* __restrict__ s1,
        const __nv_bfloat16* __restrict__ s2, const __nv_bfloat16* __restrict__ s3,
        int K, int k0, uint32_t sbase, int tid) {
    const __nv_bfloat16* srcs[4] = {s0, s1, s2, s3};
#pragma unroll
    for (int m = 0; m < 4; m++) {
        const __nv_bfloat16* s = srcs[m];
        uint32_t mb = sbase + m * TGP_MAT;
#pragma unroll
        for (int j = 0; j < 2; j++) {
            int id  = tid + (j << 8);
            int row = id >> 2, kc = id & 3;
            const void* g = s + (size_t)row * K + k0 + (kc << 3);
            CP_ASYNC16(mb + row * TGP_STRIDE_B + (kc << 4), g);
        }
    }
}

template<bool RELU, bool SPLITO>
__global__ __launch_bounds__(256)
void tc_gemm_kernel(const __nv_bfloat16* __restrict__ Ahi, const __nv_bfloat16* __restrict__ Alo,
                    const __nv_bfloat16* __restrict__ Bhi, const __nv_bfloat16* __restrict__ Blo,
                    const float* __restrict__ bias, float* __restrict__ C,
                    __nv_bfloat16* __restrict__ Chi, __nv_bfloat16* __restrict__ Clo,
                    int M, int N, int K) {
    extern __shared__ char smem[];
    const uint32_t sb = smem_u32(smem);
    const int tid = threadIdx.x, wid = tid >> 5, lane = tid & 31;
    const int wm = wid >> 2, wn = wid & 3;
    const int m0 = blockIdx.y * 128, n0 = blockIdx.x * 128;

    const __nv_bfloat16* pAh = Ahi + (size_t)m0 * K;
    const __nv_bfloat16* pAl = Alo + (size_t)m0 * K;
    const __nv_bfloat16* pBh = Bhi + (size_t)n0 * K;
    const __nv_bfloat16* pBl = Blo + (size_t)n0 * K;

    float acc[4][4][4];
#pragma unroll
    for (int i = 0; i < 4; i++)
#pragma unroll
        for (int j = 0; j < 4; j++)
#pragma unroll
            for (int r = 0; r < 4; r++) acc[i][j][r] = 0.f;

    const int nchunk = K >> 5;
    tg_load_stage(pAh, pAl, pBh, pBl, K, 0, sb, tid);
    CP_COMMIT();

    const uint32_t a_row = (uint32_t)(wm * 64 + (lane & 15));
    const uint32_t a_koff = (uint32_t)((lane >> 4) << 4);
    const uint32_t b_row = (uint32_t)(wn * 32 + ((lane >> 4) << 3) + (lane & 7));
    const uint32_t b_koff = (uint32_t)(((lane >> 3) & 1) << 4);

    for (int c = 0; c < nchunk; c++) {
        CP_WAIT0();
        __syncthreads();
        if (c + 1 < nchunk)
            tg_load_stage(pAh, pAl, pBh, pBl, K, (c + 1) << 5,
                          sb + ((c + 1) & 1) * TGP_STAGE, tid);
        CP_COMMIT();

        const uint32_t st = sb + (c & 1) * TGP_STAGE;
#pragma unroll
        for (int ks = 0; ks < 2; ks++) {
            uint32_t ahi[4][4], alo[4][4], bhi[4][2], blo[4][2];
#pragma unroll
            for (int mt = 0; mt < 4; mt++) {
                uint32_t ad = st + (a_row + mt * 16) * TGP_STRIDE_B + ks * 32 + a_koff;
                LDSM_X4(ahi[mt][0], ahi[mt][1], ahi[mt][2], ahi[mt][3], ad);
                LDSM_X4(alo[mt][0], alo[mt][1], alo[mt][2], alo[mt][3], ad + TGP_MAT);
            }
#pragma unroll
            for (int p = 0; p < 2; p++) {
                uint32_t bd = st + 2 * TGP_MAT + (b_row + p * 16) * TGP_STRIDE_B + ks * 32 + b_koff;
                LDSM_X4(bhi[2*p][0], bhi[2*p][1], bhi[2*p+1][0], bhi[2*p+1][1], bd);
                LDSM_X4(blo[2*p][0], blo[2*p][1], blo[2*p+1][0], blo[2*p+1][1], bd + TGP_MAT);
            }
#pragma unroll
            for (int mt = 0; mt < 4; mt++)
#pragma unroll
                for (int nt = 0; nt < 4; nt++) {
                    MMA_BF16(acc[mt][nt], ahi[mt], bhi[nt]);
                    MMA_BF16(acc[mt][nt], ahi[mt], blo[nt]);
                    MMA_BF16(acc[mt][nt], alo[mt], bhi[nt]);
                }
        }
        __syncthreads();
    }

#pragma unroll
    for (int mt = 0; mt < 4; mt++) {
        const int r0 = m0 + wm * 64 + mt * 16 + (lane >> 2);
#pragma unroll
        for (int nt = 0; nt < 4; nt++) {
            const int c0 = n0 + wn * 32 + nt * 8 + ((lane & 3) << 1);
            float bx = bias ? bias[c0]     : 0.f;
            float by = bias ? bias[c0 + 1] : 0.f;
            float v0 = acc[mt][nt][0] + bx, v1 = acc[mt][nt][1] + by;
            float v2 = acc[mt][nt][2] + bx, v3 = acc[mt][nt][3] + by;
            if (RELU) {
                v0 = fmaxf(v0, 0.f); v1 = fmaxf(v1, 0.f);
                v2 = fmaxf(v2, 0.f); v3 = fmaxf(v3, 0.f);
            }
            if (SPLITO) {
                uint32_t hi, lo;
                split2(v0, v1, hi, lo);
                *(uint32_t*)(Chi + (size_t)r0 * N + c0) = hi;
                *(uint32_t*)(Clo + (size_t)r0 * N + c0) = lo;
                split2(v2, v3, hi, lo);
                *(uint32_t*)(Chi + (size_t)(r0 + 8) * N + c0) = hi;
                *(uint32_t*)(Clo + (size_t)(r0 + 8) * N + c0) = lo;
            } else {
                *(float2*)(C + (size_t)r0 * N + c0)       = make_float2(v0, v1);
                *(float2*)(C + (size_t)(r0 + 8) * N + c0) = make_float2(v2, v3);
            }
        }
    }
}

// ================= tensor-core flash attention (causal, split-bf16) =================
// Br=128 rows per CTA, Bc=64 cols per iter, dh=64. 8 warps x 16 rows.
// Output written directly as bf16 hi/lo (A operand for the Wo GEMM).
#define AT_STRB 144            // smem row stride bytes (72 bf16)
#define AT_K_HI 0
#define AT_K_LO 9216
#define AT_V_HI 18432
#define AT_V_LO 27648
#define AT_SMEM 36864          // Q staging reuses entire region: hi@0, lo@18432

__global__ __launch_bounds__(256)
void attn_mma_kernel(const float* __restrict__ qkv,
                     __nv_bfloat16* __restrict__ ohi,
                     __nv_bfloat16* __restrict__ olo) {
    extern __shared__ char smc[];
    const uint32_t sb = smem_u32(smc);
    const int b = blockIdx.y >> 4, h = blockIdx.y & 15;
    const int it = (int)gridDim.x - 1 - (int)blockIdx.x;    // heavy tiles first
    const int r0 = it * 128;
    const int tid = threadIdx.x, w = tid >> 5, lane = tid & 31;

    const size_t base = (size_t)b * SEQc * 3072 + (size_t)(h * 64);
    const float* qg = qkv + base;
    const float* kg = qkv + base + 1024;
    const float* vg = qkv + base + 2048;

    // ---- stage Q (128x64) hi/lo into smem ----
#pragma unroll
    for (int i = 0; i < 8; i++) {
        int idx = tid + (i << 8);             // 0..2047 float4
        int r = idx >> 4, c4 = (idx & 15) << 2;
        float4 v = *(const float4*)(qg + (size_t)(r0 + r) * 3072 + c4);
        uint32_t h0, l0, h1, l1;
        split2(v.x, v.y, h0, l0);
        split2(v.z, v.w, h1, l1);
        uint32_t off = (uint32_t)(r * AT_STRB + (c4 << 1));
        *(uint2*)(smc + off)         = make_uint2(h0, h1);
        *(uint2*)(smc + 18432 + off) = make_uint2(l0, l1);
    }
    __syncthreads();

    // Q fragments (register-resident for the whole row tile)
    uint32_t qh[4][4], ql[4][4];
    {
        uint32_t qa = sb + (uint32_t)((w * 16 + (lane & 15)) * AT_STRB) + (uint32_t)(((lane >> 4) << 4));
#pragma unroll
        for (int kt = 0; kt < 4; kt++) {
            LDSM_X4(qh[kt][0], qh[kt][1], qh[kt][2], qh[kt][3], qa + kt * 32);
            LDSM_X4(ql[kt][0], ql[kt][1], ql[kt][2], ql[kt][3], qa + 18432 + kt * 32);
        }
    }

    float acc[8][4];
#pragma unroll
    for (int nt = 0; nt < 8; nt++)
#pragma unroll
        for (int r = 0; r < 4; r++) acc[nt][r] = 0.f;
    float m0 = -1e30f, m1 = -1e30f, l0 = 0.f, l1 = 0.f;

    const int row0 = r0 + w * 16 + (lane >> 2);
    const int row1 = row0 + 8;
    const int ktiles = 2 * it + 2;
    const int diag0 = 2 * it;
    const uint32_t brow = (uint32_t)(((lane >> 4) << 3) + (lane & 7));
    const uint32_t bko  = (uint32_t)(((lane >> 3) & 1) << 4);

    for (int kc = 0; kc < ktiles; kc++) {
        __syncthreads();          // previous tile consumed (or Q frags loaded)
        // ---- stage K (K-major) and V^T hi/lo ----
#pragma unroll
        for (int i = 0; i < 4; i++) {
            int idx = tid + (i << 8);         // 0..1023 float4
            int r = idx >> 4, c4 = (idx & 15) << 2;
            size_t go = (size_t)(kc * 64 + r) * 3072 + c4;
            float4 kv = *(const float4*)(kg + go);
            uint32_t h0, lo0, h1, lo1;
            split2(kv.x, kv.y, h0, lo0);
            split2(kv.z, kv.w, h1, lo1);
            uint32_t off = (uint32_t)(r * AT_STRB + (c4 << 1));
            *(uint2*)(smc + AT_K_HI + off) = make_uint2(h0, h1);
            *(uint2*)(smc + AT_K_LO + off) = make_uint2(lo0, lo1);
            float4 vv = *(const float4*)(vg + go);
            float va[4] = {vv.x, vv.y, vv.z, vv.w};
#pragma unroll
            for (int q = 0; q < 4; q++) {
                __nv_bfloat16 vh = __float2bfloat16(va[q]);
                __nv_bfloat16 vl = __float2bfloat16(va[q] - __bfloat162float(vh));
                *(__nv_bfloat16*)(smc + AT_V_HI + (c4 + q) * AT_STRB + r * 2) = vh;
                *(__nv_bfloat16*)(smc + AT_V_LO + (c4 + q) * AT_STRB + r * 2) = vl;
            }
        }
        __syncthreads();

        // ---- S = Q K^T (split, 3 terms) ----
        float s[8][4];
#pragma unroll
        for (int nt = 0; nt < 8; nt++)
#pragma unroll
            for (int r = 0; r < 4; r++) s[nt][r] = 0.f;
#pragma unroll
        for (int kt = 0; kt < 4; kt++) {
            uint32_t bh[8][2], bl[8][2];
#pragma unroll
            for (int p = 0; p < 4; p++) {
                uint32_t bd = sb + AT_K_HI + (p * 16 + brow) * AT_STRB + kt * 32 + bko;
                LDSM_X4(bh[2*p][0], bh[2*p][1], bh[2*p+1][0], bh[2*p+1][1], bd);
                LDSM_X4(bl[2*p][0], bl[2*p][1], bl[2*p+1][0], bl[2*p+1][1], bd + 9216);
            }
#pragma unroll
            for (int nt = 0; nt < 8; nt++) {
                MMA_BF16(s[nt], qh[kt], bh[nt]);
                MMA_BF16(s[nt], qh[kt], bl[nt]);
                MMA_BF16(s[nt], ql[kt], bh[nt]);
            }
        }
#pragma unroll
        for (int nt = 0; nt < 8; nt++)
#pragma unroll
            for (int r = 0; r < 4; r++) s[nt][r] *= 0.125f;

        // ---- causal mask (diagonal tiles only) ----
        if (kc >= diag0) {
            int colb = kc * 64 + ((lane & 3) << 1);
#pragma unroll
            for (int nt = 0; nt < 8; nt++) {
                int c0 = colb + nt * 8;
                if (c0     > row0) s[nt][0] = -1e30f;
                if (c0 + 1 > row0) s[nt][1] = -1e30f;
                if (c0     > row1) s[nt][2] = -1e30f;
                if (c0 + 1 > row1) s[nt][3] = -1e30f;
            }
        }

        // ---- online softmax (rows r and r+8; 4-lane group reductions) ----
        float mx0 = -1e30f, mx1 = -1e30f;
#pragma unroll
        for (int nt = 0; nt < 8; nt++) {
            mx0 = fmaxf(mx0, fmaxf(s[nt][0], s[nt][1]));
            mx1 = fmaxf(mx1, fmaxf(s[nt][2], s[nt][3]));
        }
        mx0 = fmaxf(mx0, __shfl_xor_sync(0xffffffffu, mx0, 1));
        mx0 = fmaxf(mx0, __shfl_xor_sync(0xffffffffu, mx0, 2));
        mx1 = fmaxf(mx1, __shfl_xor_sync(0xffffffffu, mx1, 1));
        mx1 = fmaxf(mx1, __shfl_xor_sync(0xffffffffu, mx1, 2));
        float nm0 = fmaxf(m0, mx0), nm1 = fmaxf(m1, mx1);
        float sum0 = 0.f, sum1 = 0.f;
#pragma unroll
        for (int nt = 0; nt < 8; nt++) {
            s[nt][0] = __expf(s[nt][0] - nm0); sum0 += s[nt][0];
            s[nt][1] = __expf(s[nt][1] - nm0); sum0 += s[nt][1];
            s[nt][2] = __expf(s[nt][2] - nm1); sum1 += s[nt][2];
            s[nt][3] = __expf(s[nt][3] - nm1); sum1 += s[nt][3];
        }
        sum0 += __shfl_xor_sync(0xffffffffu, sum0, 1);
        sum0 += __shfl_xor_sync(0xffffffffu, sum0, 2);
        sum1 += __shfl_xor_sync(0xffffffffu, sum1, 1);
        sum1 += __shfl_xor_sync(0xffffffffu, sum1, 2);
        float a0 = __expf(m0 - nm0), a1 = __expf(m1 - nm1);
        m0 = nm0; m1 = nm1;
        l0 = l0 * a0 + sum0; l1 = l1 * a1 + sum1;
#pragma unroll
        for (int nt = 0; nt < 8; nt++) {
            acc[nt][0] *= a0; acc[nt][1] *= a0;
            acc[nt][2] *= a1; acc[nt][3] *= a1;
        }

        // ---- repack S accumulator fragments into P A-fragments (hi/lo) ----
        uint32_t ph[4][4], pl[4][4];
#pragma unroll
        for (int kt = 0; kt < 4; kt++) {
            int e = 2 * kt, o = 2 * kt + 1;
            split2(s[e][0], s[e][1], ph[kt][0], pl[kt][0]);
            split2(s[e][2], s[e][3], ph[kt][1], pl[kt][1]);
            split2(s[o][0], s[o][1], ph[kt][2], pl[kt][2]);
            split2(s[o][2], s[o][3], ph[kt][3], pl[kt][3]);
        }

        // ---- O += P @ V (split, 3 terms) ----
#pragma unroll
        for (int kt = 0; kt < 4; kt++) {
            uint32_t vh[8][2], vl[8][2];
#pragma unroll
            for (int p = 0; p < 4; p++) {
                uint32_t bd = sb + AT_V_HI + (p * 16 + brow) * AT_STRB + kt * 32 + bko;
                LDSM_X4(vh[2*p][0], vh[2*p][1], vh[2*p+1][0], vh[2*p+1][1], bd);
                LDSM_X4(vl[2*p][0], vl[2*p][1], vl[2*p+1][0], vl[2*p+1][1], bd + 9216);
            }
#pragma unroll
            for (int nt = 0; nt < 8; nt++) {
                MMA_BF16(acc[nt], ph[kt], vh[nt]);
                MMA_BF16(acc[nt], ph[kt], vl[nt]);
                MMA_BF16(acc[nt], pl[kt], vh[nt]);
            }
        }
    }

    // ---- epilogue: normalize and write bf16 hi/lo (concat head layout) ----
    float inv0 = 1.f / l0, inv1 = 1.f / l1;
    const int tok0 = b * SEQc + row0;
#pragma unroll
    for (int nt = 0; nt < 8; nt++) {
        int col = h * 64 + nt * 8 + ((lane & 3) << 1);
        uint32_t hi, lo;
        split2(acc[nt][0] * inv0, acc[nt][1] * inv0, hi, lo);
        *(uint32_t*)(ohi + (size_t)tok0 * 1024 + col) = hi;
        *(uint32_t*)(olo + (size_t)tok0 * 1024 + col) = lo;
        split2(acc[nt][2] * inv1, acc[nt][3] * inv1, hi, lo);
        *(uint32_t*)(ohi + (size_t)(tok0 + 8) * 1024 + col) = hi;
        *(uint32_t*)(olo + (size_t)(tok0 + 8) * 1024 + col) = lo;
    }
}

// ---------------- LayerNorm + residual ----------------
template<bool SPLITO>
__global__ void ln_residual_kernel(const float* __restrict__ resid,
                                   const float* __restrict__ v,
                                   const float* __restrict__ g,
                                   const float* __restrict__ beta,
                                   float* __restrict__ out,
                                   __nv_bfloat16* __restrict__ ohi,
                                   __nv_bfloat16* __restrict__ olo) {
    __shared__ float red[16];
    const int row = blockIdx.x;
    const int t = threadIdx.x;
    const float* vr = v + (size_t)row * D_MODELc;
    float4 xv = *(const float4*)(vr + t * 4);
    float s  = xv.x + xv.y + xv.z + xv.w;
    float s2 = xv.x * xv.x + xv.y * xv.y + xv.z * xv.z + xv.w * xv.w;
#pragma unroll
    for (int o = 16; o; o >>= 1) {
        s  += __shfl_xor_sync(0xffffffffu, s,  o);
        s2 += __shfl_xor_sync(0xffffffffu, s2, o);
    }
    int wid = t >> 5;
    if ((t & 31) == 0) { red[wid] = s; red[8 + wid] = s2; }
    __syncthreads();
    float S = 0.f, S2 = 0.f;
#pragma unroll
    for (int i = 0; i < 8; i++) { S += red[i]; S2 += red[8 + i]; }
    float mu   = S * (1.f / D_MODELc);
    float var  = S2 * (1.f / D_MODELc) - mu * mu;
    float rstd = rsqrtf(var + LN_EPSc);

    int c = t * 4;
    float4 rr = *(const float4*)(resid + (size_t)row * D_MODELc + c);
    float4 gg = *(const float4*)(g + c);
    float4 bb = *(const float4*)(beta + c);
    float4 o;
    o.x = rr.x + (xv.x - mu) * rstd * gg.x + bb.x;
    o.y = rr.y + (xv.y - mu) * rstd * gg.y + bb.y;
    o.z = rr.z + (xv.z - mu) * rstd * gg.z + bb.z;
    o.w = rr.w + (xv.w - mu) * rstd * gg.w + bb.w;
    *(float4*)(out + (size_t)row * D_MODELc + c) = o;
    if (SPLITO) {
        uint32_t h0, l0, h1, l1;
        split2(o.x, o.y, h0, l0);
        split2(o.z, o.w, h1, l1);
        *(uint2*)(ohi + (size_t)row * D_MODELc + c) = make_uint2(h0, h1);
        *(uint2*)(olo + (size_t)row * D_MODELc + c) = make_uint2(l0, l1);
    }
}

// ---------------- launch ----------------
extern "C" void kernel_launch(void* const* d_in, const int* in_sizes, int n_in,
                              void* d_out, int out_size) {
    (void)in_sizes; (void)n_in; (void)out_size;
    const float* x     = (const float*)d_in[0];
    const float* wq    = (const float*)d_in[1];
    const float* wk    = (const float*)d_in[2];
    const float* wv    = (const float*)d_in[3];
    const float* wo    = (const float*)d_in[4];
    const float* w_in  = (const float*)d_in[5];
    const float* b_in  = (const float*)d_in[6];
    const float* w_out = (const float*)d_in[7];
    const float* b_out = (const float*)d_in[8];
    const float* g1    = (const float*)d_in[9];
    const float* bt1   = (const float*)d_in[10];
    const float* g2    = (const float*)d_in[11];
    const float* bt2   = (const float*)d_in[12];
    float* out = (float*)d_out;

    float *qkv, *proj, *x1, *mlp;
    __nv_bfloat16 *ahi, *alo, *bhi, *blo, *mh, *ml;
    cudaGetSymbolAddress((void**)&qkv,  g_qkv);
    cudaGetSymbolAddress((void**)&proj, g_proj);
    cudaGetSymbolAddress((void**)&x1,   g_x1);
    cudaGetSymbolAddress((void**)&mlp,  g_mlp);
    cudaGetSymbolAddress((void**)&ahi,  g_ahi);
    cudaGetSymbolAddress((void**)&alo,  g_alo);
    cudaGetSymbolAddress((void**)&bhi,  g_bhi);
    cudaGetSymbolAddress((void**)&blo,  g_blo);
    cudaGetSymbolAddress((void**)&mh,   g_mlph_hi);
    cudaGetSymbolAddress((void**)&ml,   g_mlph_lo);

    cudaFuncSetAttribute(tc_gemm_kernel<false, false>, cudaFuncAttributeMaxDynamicSharedMemorySize, TGP_SMEM);
    cudaFuncSetAttribute(tc_gemm_kernel<true,  true>,  cudaFuncAttributeMaxDynamicSharedMemorySize, TGP_SMEM);
    cudaFuncSetAttribute(attn_mma_kernel, cudaFuncAttributeMaxDynamicSharedMemorySize, AT_SMEM);

    dim3 tsb(32, 8);

    // ---- QKV projection: [4096,1024] @ [1024,3072] ----
    qkv_tsplit_kernel<<<dim3(2, 32, 48), tsb>>>(wq, wk, wv, bhi, blo);
    asplit_kernel<<<(NTOK * D_MODELc / 4 + 255) / 256, 256>>>(x, ahi, alo, NTOK * D_MODELc / 4);
    tc_gemm_kernel<false, false><<<dim3(24, 32), 256, TGP_SMEM>>>(
        ahi, alo, bhi, blo, nullptr, qkv, nullptr, nullptr, NTOK, 3072, 1024);

    // ---- tensor-core causal flash attention -> bf16 hi/lo (overwrites ahi/alo) ----
    attn_mma_kernel<<<dim3(SEQc / 128, BATCHc * 16), 256, AT_SMEM>>>(qkv, ahi, alo);

    // ---- output projection: att @ wo ----
    tsplit_kernel<<<dim3(32, 32), tsb>>>(wo, bhi, blo, 1024, 1024);
    tc_gemm_kernel<false, false><<<dim3(8, 32), 256, TGP_SMEM>>>(
        ahi, alo, bhi, blo, nullptr, proj, nullptr, nullptr, NTOK, 1024, 1024);

    // ---- x1 = x + LN(proj), fused split into ahi/alo ----
    ln_residual_kernel<true><<<NTOK, 256>>>(x, proj, g1, bt1, x1, ahi, alo);

    // ---- MLP in: relu(x1 @ w_in + b_in), fused split output ----
    tsplit_kernel<<<dim3(128, 32), tsb>>>(w_in, bhi, blo, 1024, 4096);
    tc_gemm_kernel<true, true><<<dim3(32, 32), 256, TGP_SMEM>>>(
        ahi, alo, bhi, blo, b_in, nullptr, mh, ml, NTOK, 4096, 1024);

    // ---- MLP out: mlph @ w_out + b_out ----
    tsplit_kernel<<<dim3(32, 128), tsb>>>(w_out, bhi, blo, 4096, 1024);
    tc_gemm_kernel<false, false><<<dim3(8, 32), 256, TGP_SMEM>>>(
        mh, ml, bhi, blo, b_out, mlp, nullptr, nullptr, NTOK, 1024, 4096);

    // ---- out = x1 + LN(mlp) ----
    ln_residual_kernel<false><<<NTOK, 256>>>(x1, mlp, g2, bt2, out, nullptr, nullptr);
}

// round 8
// speedup vs baseline: 2.3695x; 1.0459x over previous
#include <cuda_runtime.h>
#include <cuda_bf16.h>
#include <cstdint>
#include <math.h>

// ---------------- problem constants ----------------
#define D_MODELc 1024
#define SEQc     2048
#define BATCHc   2
#define NTOK     (BATCHc*SEQc)     // 4096 tokens
#define D_MLPc   4096
#define LN_EPSc  1e-5f

// ---------------- device scratch (no runtime allocation allowed) ----------------
__device__ float g_qkv [(size_t)NTOK * 3 * D_MODELc];           // [4096][3072] q|k|v fp32
__device__ float g_proj[(size_t)NTOK * D_MODELc];               // head_out @ wo
__device__ float g_x1  [(size_t)NTOK * D_MODELc];               // x + LN1(proj)
__device__ float g_mlp [(size_t)NTOK * D_MODELc];               // mlp output
__device__ __nv_bfloat16 g_mlph_hi[(size_t)NTOK * D_MLPc];      // relu(x1@w_in+b_in) split
__device__ __nv_bfloat16 g_mlph_lo[(size_t)NTOK * D_MLPc];
__device__ __nv_bfloat16 g_ahi[(size_t)NTOK * D_MODELc];        // activation split (reused)
__device__ __nv_bfloat16 g_alo[(size_t)NTOK * D_MODELc];
__device__ __nv_bfloat16 g_bhi[(size_t)D_MLPc * D_MODELc];      // weight split (reused)
__device__ __nv_bfloat16 g_blo[(size_t)D_MLPc * D_MODELc];

// ================= PTX helpers (baseline sm_80+ features only) =================
__device__ __forceinline__ uint32_t smem_u32(const void* p) {
    uint32_t a;
    asm("{ .reg .u64 t; cvta.to.shared.u64 t, %1; cvt.u32.u64 %0, t; }" : "=r"(a) : "l"(p));
    return a;
}
#define CP_ASYNC16(dst, src) \
    asm volatile("cp.async.cg.shared.global [%0], [%1], 16;" :: "r"(dst), "l"(src))
#define CP_COMMIT()  asm volatile("cp.async.commit_group;" ::: "memory")
#define CP_WAIT0()   asm volatile("cp.async.wait_group 0;" ::: "memory")
#define CP_WAIT1()   asm volatile("cp.async.wait_group 1;" ::: "memory")
#define LDSM_X4(r0, r1, r2, r3, addr) \
    asm volatile("ldmatrix.sync.aligned.m8n8.x4.shared.b16 {%0,%1,%2,%3}, [%4];" \
        : "=r"(r0), "=r"(r1), "=r"(r2), "=r"(r3) : "r"(addr))
#define MMA_BF16(d, a, b) \
    asm volatile("mma.sync.aligned.m16n8k16.row.col.f32.bf16.bf16.f32 " \
        "{%0,%1,%2,%3},{%4,%5,%6,%7},{%8,%9},{%0,%1,%2,%3};" \
        : "+f"((d)[0]), "+f"((d)[1]), "+f"((d)[2]), "+f"((d)[3]) \
        : "r"((a)[0]), "r"((a)[1]), "r"((a)[2]), "r"((a)[3]), "r"((b)[0]), "r"((b)[1]))

// split two fp32 into packed bf16 hi pair + lo (residual) pair
__device__ __forceinline__ void split2(float a, float b, uint32_t& hi, uint32_t& lo) {
    __nv_bfloat16 ha = __float2bfloat16(a), hb = __float2bfloat16(b);
    __nv_bfloat16 la = __float2bfloat16(a - __bfloat162float(ha));
    __nv_bfloat16 lb = __float2bfloat16(b - __bfloat162float(hb));
    __nv_bfloat162 H(ha, hb), L(la, lb);
    hi = *(uint32_t*)&H; lo = *(uint32_t*)&L;
}

// ================= split / transpose kernels =================
__global__ void asplit_kernel(const float* __restrict__ src,
                              __nv_bfloat16* __restrict__ dhi,
                              __nv_bfloat16* __restrict__ dlo, int n4) {
    int i = blockIdx.x * blockDim.x + threadIdx.x;
    if (i >= n4) return;
    float4 v = ((const float4*)src)[i];
    uint32_t h0, l0, h1, l1;
    split2(v.x, v.y, h0, l0);
    split2(v.z, v.w, h1, l1);
    ((uint2*)dhi)[i] = make_uint2(h0, h1);
    ((uint2*)dlo)[i] = make_uint2(l0, l1);
}

// tiled transpose+split: src [R][C] fp32 -> dst [C][R] bf16 hi/lo
__global__ void tsplit_kernel(const float* __restrict__ src,
                              __nv_bfloat16* __restrict__ dhi,
                              __nv_bfloat16* __restrict__ dlo, int R, int C) {
    __shared__ float t[32][33];
    int c0 = blockIdx.x * 32, r0 = blockIdx.y * 32;
#pragma unroll
    for (int i = 0; i < 4; i++)
        t[threadIdx.y + i*8][threadIdx.x] = src[(size_t)(r0 + threadIdx.y + i*8) * C + c0 + threadIdx.x];
    __syncthreads();
#pragma unroll
    for (int i = 0; i < 4; i++) {
        float v = t[threadIdx.x][threadIdx.y + i*8];
        __nv_bfloat16 h = __float2bfloat16(v);
        size_t o = (size_t)(c0 + threadIdx.y + i*8) * R + r0 + threadIdx.x;
        dhi[o] = h;
        dlo[o] = __float2bfloat16(v - __bfloat162float(h));
    }
}

// wq/wk/wv [16][1024][64] -> Wt [3072][1024] bf16 hi/lo
__global__ void qkv_tsplit_kernel(const float* __restrict__ wq, const float* __restrict__ wk,
                                  const float* __restrict__ wv,
                                  __nv_bfloat16* __restrict__ dhi,
                                  __nv_bfloat16* __restrict__ dlo) {
    __shared__ float t[32][33];
    int z = blockIdx.z, p = z >> 4, h = z & 15;
    const float* src = (p == 0 ? wq : (p == 1 ? wk : wv)) + (size_t)h * 1024 * 64;
    int c0 = blockIdx.x * 32, r0 = blockIdx.y * 32;
#pragma unroll
    for (int i = 0; i < 4; i++)
        t[threadIdx.y + i*8][threadIdx.x] = src[(size_t)(r0 + threadIdx.y + i*8) * 64 + c0 + threadIdx.x];
    __syncthreads();
    int nbase = (p << 10) + (h << 6);
#pragma unroll
    for (int i = 0; i < 4; i++) {
        float v = t[threadIdx.x][threadIdx.y + i*8];
        __nv_bfloat16 hh = __float2bfloat16(v);
        size_t o = (size_t)(nbase + c0 + threadIdx.y + i*8) * 1024 + r0 + threadIdx.x;
        dhi[o] = hh;
        dlo[o] = __float2bfloat16(v - __bfloat162float(hh));
    }
}

// ================= HMMA split-bf16 GEMM (mma.sync m16n8k16), 3-stage pipeline =================
#define TGP_STRIDE_B 80
#define TGP_MAT      10240
#define TGP_STAGE    40960
#define TGP_SMEM     122880   // 3 stages

__device__ __forceinline__ void tg_load_stage(
        const __nv_bfloat16* __restrict__ s0, const __nv_bfloat16* __restrict__ s1,
        const __nv_bfloat16* __restrict__ s2, const __nv_bfloat16* __restrict__ s3,
        int K, int k0, uint32_t sbase, int tid) {
    const __nv_bfloat16* srcs[4] = {s0, s1, s2, s3};
#pragma unroll
    for (int m = 0; m < 4; m++) {
        const __nv_bfloat16* s = srcs[m];
        uint32_t mb = sbase + m * TGP_MAT;
#pragma unroll
        for (int j = 0; j < 2; j++) {
            int id  = tid + (j << 8);
            int row = id >> 2, kc = id & 3;
            const void* g = s + (size_t)row * K + k0 + (kc << 3);
            CP_ASYNC16(mb + row * TGP_STRIDE_B + (kc << 4), g);
        }
    }
}

template<bool RELU, bool SPLITO>
__global__ __launch_bounds__(256)
void tc_gemm_kernel(const __nv_bfloat16* __restrict__ Ahi, const __nv_bfloat16* __restrict__ Alo,
                    const __nv_bfloat16* __restrict__ Bhi, const __nv_bfloat16* __restrict__ Blo,
                    const float* __restrict__ bias, float* __restrict__ C,
                    __nv_bfloat16* __restrict__ Chi, __nv_bfloat16* __restrict__ Clo,
                    int M, int N, int K) {
    extern __shared__ char smem[];
    const uint32_t sb = smem_u32(smem);
    const int tid = threadIdx.x, wid = tid >> 5, lane = tid & 31;
    const int wm = wid >> 2, wn = wid & 3;
    const int m0 = blockIdx.y * 128, n0 = blockIdx.x * 128;

    const __nv_bfloat16* pAh = Ahi + (size_t)m0 * K;
    const __nv_bfloat16* pAl = Alo + (size_t)m0 * K;
    const __nv_bfloat16* pBh = Bhi + (size_t)n0 * K;
    const __nv_bfloat16* pBl = Blo + (size_t)n0 * K;

    float acc[4][4][4];
#pragma unroll
    for (int i = 0; i < 4; i++)
#pragma unroll
        for (int j = 0; j < 4; j++)
#pragma unroll
            for (int r = 0; r < 4; r++) acc[i][j][r] = 0.f;

    const int nchunk = K >> 5;
    tg_load_stage(pAh, pAl, pBh, pBl, K, 0, sb, tid);
    CP_COMMIT();
    if (nchunk > 1) {
        tg_load_stage(pAh, pAl, pBh, pBl, K, 32, sb + TGP_STAGE, tid);
        CP_COMMIT();
    }

    const uint32_t a_row = (uint32_t)(wm * 64 + (lane & 15));
    const uint32_t a_koff = (uint32_t)((lane >> 4) << 4);
    const uint32_t b_row = (uint32_t)(wn * 32 + ((lane >> 4) << 3) + (lane & 7));
    const uint32_t b_koff = (uint32_t)(((lane >> 3) & 1) << 4);

    for (int c = 0; c < nchunk; c++) {
        if (c + 1 < nchunk) { CP_WAIT1(); } else { CP_WAIT0(); }
        __syncthreads();
        if (c + 2 < nchunk) {
            tg_load_stage(pAh, pAl, pBh, pBl, K, (c + 2) << 5,
                          sb + (uint32_t)((c + 2) % 3) * TGP_STAGE, tid);
            CP_COMMIT();
        }

        const uint32_t st = sb + (uint32_t)(c % 3) * TGP_STAGE;
#pragma unroll
        for (int ks = 0; ks < 2; ks++) {
            uint32_t ahi[4][4], alo[4][4], bhi[4][2], blo[4][2];
#pragma unroll
            for (int mt = 0; mt < 4; mt++) {
                uint32_t ad = st + (a_row + mt * 16) * TGP_STRIDE_B + ks * 32 + a_koff;
                LDSM_X4(ahi[mt][0], ahi[mt][1], ahi[mt][2], ahi[mt][3], ad);
                LDSM_X4(alo[mt][0], alo[mt][1], alo[mt][2], alo[mt][3], ad + TGP_MAT);
            }
#pragma unroll
            for (int p = 0; p < 2; p++) {
                uint32_t bd = st + 2 * TGP_MAT + (b_row + p * 16) * TGP_STRIDE_B + ks * 32 + b_koff;
                LDSM_X4(bhi[2*p][0], bhi[2*p][1], bhi[2*p+1][0], bhi[2*p+1][1], bd);
                LDSM_X4(blo[2*p][0], blo[2*p][1], blo[2*p+1][0], blo[2*p+1][1], bd + TGP_MAT);
            }
#pragma unroll
            for (int mt = 0; mt < 4; mt++)
#pragma unroll
                for (int nt = 0; nt < 4; nt++) {
                    MMA_BF16(acc[mt][nt], ahi[mt], bhi[nt]);
                    MMA_BF16(acc[mt][nt], ahi[mt], blo[nt]);
                    MMA_BF16(acc[mt][nt], alo[mt], bhi[nt]);
                }
        }
    }

#pragma unroll
    for (int mt = 0; mt < 4; mt++) {
        const int r0 = m0 + wm * 64 + mt * 16 + (lane >> 2);
#pragma unroll
        for (int nt = 0; nt < 4; nt++) {
            const int c0 = n0 + wn * 32 + nt * 8 + ((lane & 3) << 1);
            float bx = bias ? bias[c0]     : 0.f;
            float by = bias ? bias[c0 + 1] : 0.f;
            float v0 = acc[mt][nt][0] + bx, v1 = acc[mt][nt][1] + by;
            float v2 = acc[mt][nt][2] + bx, v3 = acc[mt][nt][3] + by;
            if (RELU) {
                v0 = fmaxf(v0, 0.f); v1 = fmaxf(v1, 0.f);
                v2 = fmaxf(v2, 0.f); v3 = fmaxf(v3, 0.f);
            }
            if (SPLITO) {
                uint32_t hi, lo;
                split2(v0, v1, hi, lo);
                *(uint32_t*)(Chi + (size_t)r0 * N + c0) = hi;
                *(uint32_t*)(Clo + (size_t)r0 * N + c0) = lo;
                split2(v2, v3, hi, lo);
                *(uint32_t*)(Chi + (size_t)(r0 + 8) * N + c0) = hi;
                *(uint32_t*)(Clo + (size_t)(r0 + 8) * N + c0) = lo;
            } else {
                *(float2*)(C + (size_t)r0 * N + c0)       = make_float2(v0, v1);
                *(float2*)(C + (size_t)(r0 + 8) * N + c0) = make_float2(v2, v3);
            }
        }
    }
}

// ================= tensor-core flash attention (causal, split-bf16) =================
// Br=128 rows per CTA, Bc=64 cols per iter, dh=64. 8 warps x 16 rows.
// Register-prefetched K/V staging; V transposed in registers (vectorized stores,
// XOR-16B swizzle on r-offset keyed by (col>>3)&3, matched on the ldmatrix side).
#define AT_STRB 144            // smem row stride bytes (72 bf16)
#define AT_K_HI 0
#define AT_K_LO 9216
#define AT_V_HI 18432
#define AT_V_LO 27648
#define AT_SMEM 36864          // Q staging reuses region: hi@0, lo@18432

__device__ __forceinline__ void at_prefetch(const float* __restrict__ kg,
                                            const float* __restrict__ vg,
                                            int kc, int tid,
                                            float4 kpre[4], float4 vpre[4]) {
    const int rgv = tid >> 4, cgv = tid & 15;
#pragma unroll
    for (int i = 0; i < 4; i++) {
        int idx = tid + (i << 8);
        int r = idx >> 4, c4 = (idx & 15) << 2;
        kpre[i] = *(const float4*)(kg + (size_t)(kc * 64 + r) * 3072 + c4);
        vpre[i] = *(const float4*)(vg + (size_t)(kc * 64 + 4 * rgv + i) * 3072 + (cgv << 2));
    }
}

__global__ __launch_bounds__(256)
void attn_mma_kernel(const float* __restrict__ qkv,
                     __nv_bfloat16* __restrict__ ohi,
                     __nv_bfloat16* __restrict__ olo) {
    extern __shared__ char smc[];
    const uint32_t sb = smem_u32(smc);
    const int b = blockIdx.y >> 4, h = blockIdx.y & 15;
    const int it = (int)gridDim.x - 1 - (int)blockIdx.x;    // heavy tiles first
    const int r0 = it * 128;
    const int tid = threadIdx.x, w = tid >> 5, lane = tid & 31;

    const size_t base = (size_t)b * SEQc * 3072 + (size_t)(h * 64);
    const float* qg = qkv + base;
    const float* kg = qkv + base + 1024;
    const float* vg = qkv + base + 2048;

    // ---- stage Q (128x64) hi/lo into smem ----
#pragma unroll
    for (int i = 0; i < 8; i++) {
        int idx = tid + (i << 8);
        int r = idx >> 4, c4 = (idx & 15) << 2;
        float4 v = *(const float4*)(qg + (size_t)(r0 + r) * 3072 + c4);
        uint32_t h0, l0, h1, l1;
        split2(v.x, v.y, h0, l0);
        split2(v.z, v.w, h1, l1);
        uint32_t off = (uint32_t)(r * AT_STRB + (c4 << 1));
        *(uint2*)(smc + off)         = make_uint2(h0, h1);
        *(uint2*)(smc + 18432 + off) = make_uint2(l0, l1);
    }
    __syncthreads();

    // Q fragments (register-resident for the whole row tile)
    uint32_t qh[4][4], ql[4][4];
    {
        uint32_t qa = sb + (uint32_t)((w * 16 + (lane & 15)) * AT_STRB) + (uint32_t)(((lane >> 4) << 4));
#pragma unroll
        for (int kt = 0; kt < 4; kt++) {
            LDSM_X4(qh[kt][0], qh[kt][1], qh[kt][2], qh[kt][3], qa + kt * 32);
            LDSM_X4(ql[kt][0], ql[kt][1], ql[kt][2], ql[kt][3], qa + 18432 + kt * 32);
        }
    }

    float acc[8][4];
#pragma unroll
    for (int nt = 0; nt < 8; nt++)
#pragma unroll
        for (int r = 0; r < 4; r++) acc[nt][r] = 0.f;
    float m0 = -1e30f, m1 = -1e30f, l0 = 0.f, l1 = 0.f;

    const int row0 = r0 + w * 16 + (lane >> 2);
    const int row1 = row0 + 8;
    const int ktiles = 2 * it + 2;
    const int diag0 = 2 * it;
    const uint32_t brow = (uint32_t)(((lane >> 4) << 3) + (lane & 7));
    const uint32_t bko  = (uint32_t)(((lane >> 3) & 1) << 4);
    const int rgv = tid >> 4, cgv = tid & 15;

    float4 kpre[4], vpre[4];
    at_prefetch(kg, vg, 0, tid, kpre, vpre);

    for (int kc = 0; kc < ktiles; kc++) {
        __syncthreads();          // previous tile consumed (or Q frags loaded)

        // ---- store prefetched K (K-major) hi/lo ----
#pragma unroll
        for (int i = 0; i < 4; i++) {
            int idx = tid + (i << 8);
            int r = idx >> 4, c4 = (idx & 15) << 2;
            uint32_t h0, lo0, h1, lo1;
            split2(kpre[i].x, kpre[i].y, h0, lo0);
            split2(kpre[i].z, kpre[i].w, h1, lo1);
            uint32_t off = (uint32_t)(r * AT_STRB + (c4 << 1));
            *(uint2*)(smc + AT_K_HI + off) = make_uint2(h0, h1);
            *(uint2*)(smc + AT_K_LO + off) = make_uint2(lo0, lo1);
        }
        // ---- store prefetched V transposed (4x4 register transpose, vectorized) ----
        {
            float vv[4][4];
#pragma unroll
            for (int i = 0; i < 4; i++) {
                vv[i][0] = vpre[i].x; vv[i][1] = vpre[i].y;
                vv[i][2] = vpre[i].z; vv[i][3] = vpre[i].w;
            }
#pragma unroll
            for (int dd = 0; dd < 4; dd++) {
                int col = (cgv << 2) + dd;                 // dh index 0..63
                uint32_t h0, lo0, h1, lo1;
                split2(vv[0][dd], vv[1][dd], h0, lo0);
                split2(vv[2][dd], vv[3][dd], h1, lo1);
                uint32_t sw = (uint32_t)(((col >> 3) & 3) << 4);
                uint32_t byte = (uint32_t)(col * AT_STRB) + (((uint32_t)(rgv << 3)) ^ sw);
                *(uint2*)(smc + AT_V_HI + byte) = make_uint2(h0, h1);
                *(uint2*)(smc + AT_V_LO + byte) = make_uint2(lo0, lo1);
            }
        }
        __syncthreads();

        // prefetch next tile's gmem data (overlaps with MMAs below)
        if (kc + 1 < ktiles) at_prefetch(kg, vg, kc + 1, tid, kpre, vpre);

        // ---- S = Q K^T (split, 3 terms) ----
        float s[8][4];
#pragma unroll
        for (int nt = 0; nt < 8; nt++)
#pragma unroll
            for (int r = 0; r < 4; r++) s[nt][r] = 0.f;
#pragma unroll
        for (int kt = 0; kt < 4; kt++) {
            uint32_t bh[8][2], bl[8][2];
#pragma unroll
            for (int p = 0; p < 4; p++) {
                uint32_t bd = sb + AT_K_HI + (p * 16 + brow) * AT_STRB + kt * 32 + bko;
                LDSM_X4(bh[2*p][0], bh[2*p][1], bh[2*p+1][0], bh[2*p+1][1], bd);
                LDSM_X4(bl[2*p][0], bl[2*p][1], bl[2*p+1][0], bl[2*p+1][1], bd + 9216);
            }
#pragma unroll
            for (int nt = 0; nt < 8; nt++) {
                MMA_BF16(s[nt], qh[kt], bh[nt]);
                MMA_BF16(s[nt], qh[kt], bl[nt]);
                MMA_BF16(s[nt], ql[kt], bh[nt]);
            }
        }
#pragma unroll
        for (int nt = 0; nt < 8; nt++)
#pragma unroll
            for (int r = 0; r < 4; r++) s[nt][r] *= 0.125f;

        // ---- causal mask (diagonal tiles only) ----
        if (kc >= diag0) {
            int colb = kc * 64 + ((lane & 3) << 1);
#pragma unroll
            for (int nt = 0; nt < 8; nt++) {
                int c0 = colb + nt * 8;
                if (c0     > row0) s[nt][0] = -1e30f;
                if (c0 + 1 > row0) s[nt][1] = -1e30f;
                if (c0     > row1) s[nt][2] = -1e30f;
                if (c0 + 1 > row1) s[nt][3] = -1e30f;
            }
        }

        // ---- online softmax (rows r and r+8; 4-lane group reductions) ----
        float mx0 = -1e30f, mx1 = -1e30f;
#pragma unroll
        for (int nt = 0; nt < 8; nt++) {
            mx0 = fmaxf(mx0, fmaxf(s[nt][0], s[nt][1]));
            mx1 = fmaxf(mx1, fmaxf(s[nt][2], s[nt][3]));
        }
        mx0 = fmaxf(mx0, __shfl_xor_sync(0xffffffffu, mx0, 1));
        mx0 = fmaxf(mx0, __shfl_xor_sync(0xffffffffu, mx0, 2));
        mx1 = fmaxf(mx1, __shfl_xor_sync(0xffffffffu, mx1, 1));
        mx1 = fmaxf(mx1, __shfl_xor_sync(0xffffffffu, mx1, 2));
        float nm0 = fmaxf(m0, mx0), nm1 = fmaxf(m1, mx1);
        float sum0 = 0.f, sum1 = 0.f;
#pragma unroll
        for (int nt = 0; nt < 8; nt++) {
            s[nt][0] = __expf(s[nt][0] - nm0); sum0 += s[nt][0];
            s[nt][1] = __expf(s[nt][1] - nm0); sum0 += s[nt][1];
            s[nt][2] = __expf(s[nt][2] - nm1); sum1 += s[nt][2];
            s[nt][3] = __expf(s[nt][3] - nm1); sum1 += s[nt][3];
        }
        sum0 += __shfl_xor_sync(0xffffffffu, sum0, 1);
        sum0 += __shfl_xor_sync(0xffffffffu, sum0, 2);
        sum1 += __shfl_xor_sync(0xffffffffu, sum1, 1);
        sum1 += __shfl_xor_sync(0xffffffffu, sum1, 2);
        float a0 = __expf(m0 - nm0), a1 = __expf(m1 - nm1);
        m0 = nm0; m1 = nm1;
        l0 = l0 * a0 + sum0; l1 = l1 * a1 + sum1;
#pragma unroll
        for (int nt = 0; nt < 8; nt++) {
            acc[nt][0] *= a0; acc[nt][1] *= a0;
            acc[nt][2] *= a1; acc[nt][3] *= a1;
        }

        // ---- repack S accumulator fragments into P A-fragments (hi/lo) ----
        uint32_t ph[4][4], pl[4][4];
#pragma unroll
        for (int kt = 0; kt < 4; kt++) {
            int e = 2 * kt, o = 2 * kt + 1;
            split2(s[e][0], s[e][1], ph[kt][0], pl[kt][0]);
            split2(s[e][2], s[e][3], ph[kt][1], pl[kt][1]);
            split2(s[o][0], s[o][1], ph[kt][2], pl[kt][2]);
            split2(s[o][2], s[o][3], ph[kt][3], pl[kt][3]);
        }

        // ---- O += P @ V (split, 3 terms; swizzled V reads) ----
#pragma unroll
        for (int kt = 0; kt < 4; kt++) {
            uint32_t vh[8][2], vl[8][2];
#pragma unroll
            for (int p = 0; p < 4; p++) {
                uint32_t dlane = (uint32_t)(p * 16) + brow;
                uint32_t sw = ((dlane >> 3) & 3) << 4;
                uint32_t bd = sb + AT_V_HI + dlane * AT_STRB + ((uint32_t)(kt * 32 + bko) ^ sw);
                LDSM_X4(vh[2*p][0], vh[2*p][1], vh[2*p+1][0], vh[2*p+1][1], bd);
                LDSM_X4(vl[2*p][0], vl[2*p][1], vl[2*p+1][0], vl[2*p+1][1], bd + 9216);
            }
#pragma unroll
            for (int nt = 0; nt < 8; nt++) {
                MMA_BF16(acc[nt], ph[kt], vh[nt]);
                MMA_BF16(acc[nt], ph[kt], vl[nt]);
                MMA_BF16(acc[nt], pl[kt], vh[nt]);
            }
        }
    }

    // ---- epilogue: normalize and write bf16 hi/lo (concat head layout) ----
    float inv0 = 1.f / l0, inv1 = 1.f / l1;
    const int tok0 = b * SEQc + row0;
#pragma unroll
    for (int nt = 0; nt < 8; nt++) {
        int col = h * 64 + nt * 8 + ((lane & 3) << 1);
        uint32_t hi, lo;
        split2(acc[nt][0] * inv0, acc[nt][1] * inv0, hi, lo);
        *(uint32_t*)(ohi + (size_t)tok0 * 1024 + col) = hi;
        *(uint32_t*)(olo + (size_t)tok0 * 1024 + col) = lo;
        split2(acc[nt][2] * inv1, acc[nt][3] * inv1, hi, lo);
        *(uint32_t*)(ohi + (size_t)(tok0 + 8) * 1024 + col) = hi;
        *(uint32_t*)(olo + (size_t)(tok0 + 8) * 1024 + col) = lo;
    }
}

// ---------------- LayerNorm + residual ----------------
template<bool SPLITO>
__global__ void ln_residual_kernel(const float* __restrict__ resid,
                                   const float* __restrict__ v,
                                   const float* __restrict__ g,
                                   const float* __restrict__ beta,
                                   float* __restrict__ out,
                                   __nv_bfloat16* __restrict__ ohi,
                                   __nv_bfloat16* __restrict__ olo) {
    __shared__ float red[16];
    const int row = blockIdx.x;
    const int t = threadIdx.x;
    const float* vr = v + (size_t)row * D_MODELc;
    float4 xv = *(const float4*)(vr + t * 4);
    float s  = xv.x + xv.y + xv.z + xv.w;
    float s2 = xv.x * xv.x + xv.y * xv.y + xv.z * xv.z + xv.w * xv.w;
#pragma unroll
    for (int o = 16; o; o >>= 1) {
        s  += __shfl_xor_sync(0xffffffffu, s,  o);
        s2 += __shfl_xor_sync(0xffffffffu, s2, o);
    }
    int wid = t >> 5;
    if ((t & 31) == 0) { red[wid] = s; red[8 + wid] = s2; }
    __syncthreads();
    float S = 0.f, S2 = 0.f;
#pragma unroll
    for (int i = 0; i < 8; i++) { S += red[i]; S2 += red[8 + i]; }
    float mu   = S * (1.f / D_MODELc);
    float var  = S2 * (1.f / D_MODELc) - mu * mu;
    float rstd = rsqrtf(var + LN_EPSc);

    int c = t * 4;
    float4 rr = *(const float4*)(resid + (size_t)row * D_MODELc + c);
    float4 gg = *(const float4*)(g + c);
    float4 bb = *(const float4*)(beta + c);
    float4 o;
    o.x = rr.x + (xv.x - mu) * rstd * gg.x + bb.x;
    o.y = rr.y + (xv.y - mu) * rstd * gg.y + bb.y;
    o.z = rr.z + (xv.z - mu) * rstd * gg.z + bb.z;
    o.w = rr.w + (xv.w - mu) * rstd * gg.w + bb.w;
    *(float4*)(out + (size_t)row * D_MODELc + c) = o;
    if (SPLITO) {
        uint32_t h0, l0, h1, l1;
        split2(o.x, o.y, h0, l0);
        split2(o.z, o.w, h1, l1);
        *(uint2*)(ohi + (size_t)row * D_MODELc + c) = make_uint2(h0, h1);
        *(uint2*)(olo + (size_t)row * D_MODELc + c) = make_uint2(l0, l1);
    }
}

// ---------------- launch ----------------
extern "C" void kernel_launch(void* const* d_in, const int* in_sizes, int n_in,
                              void* d_out, int out_size) {
    (void)in_sizes; (void)n_in; (void)out_size;
    const float* x     = (const float*)d_in[0];
    const float* wq    = (const float*)d_in[1];
    const float* wk    = (const float*)d_in[2];
    const float* wv    = (const float*)d_in[3];
    const float* wo    = (const float*)d_in[4];
    const float* w_in  = (const float*)d_in[5];
    const float* b_in  = (const float*)d_in[6];
    const float* w_out = (const float*)d_in[7];
    const float* b_out = (const float*)d_in[8];
    const float* g1    = (const float*)d_in[9];
    const float* bt1   = (const float*)d_in[10];
    const float* g2    = (const float*)d_in[11];
    const float* bt2   = (const float*)d_in[12];
    float* out = (float*)d_out;

    float *qkv, *proj, *x1, *mlp;
    __nv_bfloat16 *ahi, *alo, *bhi, *blo, *mh, *ml;
    cudaGetSymbolAddress((void**)&qkv,  g_qkv);
    cudaGetSymbolAddress((void**)&proj, g_proj);
    cudaGetSymbolAddress((void**)&x1,   g_x1);
    cudaGetSymbolAddress((void**)&mlp,  g_mlp);
    cudaGetSymbolAddress((void**)&ahi,  g_ahi);
    cudaGetSymbolAddress((void**)&alo,  g_alo);
    cudaGetSymbolAddress((void**)&bhi,  g_bhi);
    cudaGetSymbolAddress((void**)&blo,  g_blo);
    cudaGetSymbolAddress((void**)&mh,   g_mlph_hi);
    cudaGetSymbolAddress((void**)&ml,   g_mlph_lo);

    cudaFuncSetAttribute(tc_gemm_kernel<false, false>, cudaFuncAttributeMaxDynamicSharedMemorySize, TGP_SMEM);
    cudaFuncSetAttribute(tc_gemm_kernel<true,  true>,  cudaFuncAttributeMaxDynamicSharedMemorySize, TGP_SMEM);
    cudaFuncSetAttribute(attn_mma_kernel, cudaFuncAttributeMaxDynamicSharedMemorySize, AT_SMEM);

    dim3 tsb(32, 8);

    // ---- QKV projection: [4096,1024] @ [1024,3072] ----
    qkv_tsplit_kernel<<<dim3(2, 32, 48), tsb>>>(wq, wk, wv, bhi, blo);
    asplit_kernel<<<(NTOK * D_MODELc / 4 + 255) / 256, 256>>>(x, ahi, alo, NTOK * D_MODELc / 4);
    tc_gemm_kernel<false, false><<<dim3(24, 32), 256, TGP_SMEM>>>(
        ahi, alo, bhi, blo, nullptr, qkv, nullptr, nullptr, NTOK, 3072, 1024);

    // ---- tensor-core causal flash attention -> bf16 hi/lo (overwrites ahi/alo) ----
    attn_mma_kernel<<<dim3(SEQc / 128, BATCHc * 16), 256, AT_SMEM>>>(qkv, ahi, alo);

    // ---- output projection: att @ wo ----
    tsplit_kernel<<<dim3(32, 32), tsb>>>(wo, bhi, blo, 1024, 1024);
    tc_gemm_kernel<false, false><<<dim3(8, 32), 256, TGP_SMEM>>>(
        ahi, alo, bhi, blo, nullptr, proj, nullptr, nullptr, NTOK, 1024, 1024);

    // ---- x1 = x + LN(proj), fused split into ahi/alo ----
    ln_residual_kernel<true><<<NTOK, 256>>>(x, proj, g1, bt1, x1, ahi, alo);

    // ---- MLP in: relu(x1 @ w_in + b_in), fused split output ----
    tsplit_kernel<<<dim3(128, 32), tsb>>>(w_in, bhi, blo, 1024, 4096);
    tc_gemm_kernel<true, true><<<dim3(32, 32), 256, TGP_SMEM>>>(
        ahi, alo, bhi, blo, b_in, nullptr, mh, ml, NTOK, 4096, 1024);

    // ---- MLP out: mlph @ w_out + b_out ----
    tsplit_kernel<<<dim3(32, 128), tsb>>>(w_out, bhi, blo, 4096, 1024);
    tc_gemm_kernel<false, false><<<dim3(8, 32), 256, TGP_SMEM>>>(
        mh, ml, bhi, blo, b_out, mlp, nullptr, nullptr, NTOK, 1024, 4096);

    // ---- out = x1 + LN(mlp) ----
    ln_residual_kernel<false><<<NTOK, 256>>>(x1, mlp, g2, bt2, out, nullptr, nullptr);
}

// round 9
// speedup vs baseline: 2.4730x; 1.0437x over previous
#include <cuda_runtime.h>
#include <cuda_bf16.h>
#include <cstdint>
#include <math.h>

// ---------------- problem constants ----------------
#define D_MODELc 1024
#define SEQc     2048
#define BATCHc   2
#define NTOK     (BATCHc*SEQc)     // 4096 tokens
#define D_MLPc   4096
#define LN_EPSc  1e-5f

// ---------------- device scratch (no runtime allocation allowed) ----------------
__device__ float g_proj[(size_t)NTOK * D_MODELc];               // head_out @ wo
__device__ float g_x1  [(size_t)NTOK * D_MODELc];               // x + LN1(proj)
__device__ float g_mlp [(size_t)NTOK * D_MODELc];               // mlp output
__device__ __nv_bfloat16 g_qkvh[(size_t)NTOK * 3 * D_MODELc];   // qkv split hi
__device__ __nv_bfloat16 g_qkvl[(size_t)NTOK * 3 * D_MODELc];   // qkv split lo
__device__ __nv_bfloat16 g_mlph_hi[(size_t)NTOK * D_MLPc];      // relu(x1@w_in+b_in) split
__device__ __nv_bfloat16 g_mlph_lo[(size_t)NTOK * D_MLPc];
__device__ __nv_bfloat16 g_ahi[(size_t)NTOK * D_MODELc];        // activation split (reused)
__device__ __nv_bfloat16 g_alo[(size_t)NTOK * D_MODELc];
__device__ __nv_bfloat16 g_bhi[(size_t)D_MLPc * D_MODELc];      // weight split (reused)
__device__ __nv_bfloat16 g_blo[(size_t)D_MLPc * D_MODELc];

// ================= PTX helpers (baseline sm_80+ features only) =================
__device__ __forceinline__ uint32_t smem_u32(const void* p) {
    uint32_t a;
    asm("{ .reg .u64 t; cvta.to.shared.u64 t, %1; cvt.u32.u64 %0, t; }" : "=r"(a) : "l"(p));
    return a;
}
#define CP_ASYNC16(dst, src) \
    asm volatile("cp.async.cg.shared.global [%0], [%1], 16;" :: "r"(dst), "l"(src))
#define CP_COMMIT()  asm volatile("cp.async.commit_group;" ::: "memory")
#define CP_WAIT0()   asm volatile("cp.async.wait_group 0;" ::: "memory")
#define LDSM_X4(r0, r1, r2, r3, addr) \
    asm volatile("ldmatrix.sync.aligned.m8n8.x4.shared.b16 {%0,%1,%2,%3}, [%4];" \
        : "=r"(r0), "=r"(r1), "=r"(r2), "=r"(r3) : "r"(addr))
#define MMA_BF16(d, a, b) \
    asm volatile("mma.sync.aligned.m16n8k16.row.col.f32.bf16.bf16.f32 " \
        "{%0,%1,%2,%3},{%4,%5,%6,%7},{%8,%9},{%0,%1,%2,%3};" \
        : "+f"((d)[0]), "+f"((d)[1]), "+f"((d)[2]), "+f"((d)[3]) \
        : "r"((a)[0]), "r"((a)[1]), "r"((a)[2]), "r"((a)[3]), "r"((b)[0]), "r"((b)[1]))
#define PRMT(d, a, b, sel) \
    asm("prmt.b32 %0, %1, %2, %3;" : "=r"(d) : "r"(a), "r"(b), "r"(sel))

// split two fp32 into packed bf16 hi pair + lo (residual) pair
__device__ __forceinline__ void split2(float a, float b, uint32_t& hi, uint32_t& lo) {
    __nv_bfloat16 ha = __float2bfloat16(a), hb = __float2bfloat16(b);
    __nv_bfloat16 la = __float2bfloat16(a - __bfloat162float(ha));
    __nv_bfloat16 lb = __float2bfloat16(b - __bfloat162float(hb));
    __nv_bfloat162 H(ha, hb), L(la, lb);
    hi = *(uint32_t*)&H; lo = *(uint32_t*)&L;
}

// ================= split / transpose kernels =================
__global__ void asplit_kernel(const float* __restrict__ src,
                              __nv_bfloat16* __restrict__ dhi,
                              __nv_bfloat16* __restrict__ dlo, int n4) {
    int i = blockIdx.x * blockDim.x + threadIdx.x;
    if (i >= n4) return;
    float4 v = ((const float4*)src)[i];
    uint32_t h0, l0, h1, l1;
    split2(v.x, v.y, h0, l0);
    split2(v.z, v.w, h1, l1);
    ((uint2*)dhi)[i] = make_uint2(h0, h1);
    ((uint2*)dlo)[i] = make_uint2(l0, l1);
}

// tiled transpose+split: src [R][C] fp32 -> dst [C][R] bf16 hi/lo (vectorized stores)
__global__ void tsplit_kernel(const float* __restrict__ src,
                              __nv_bfloat16* __restrict__ dhi,
                              __nv_bfloat16* __restrict__ dlo, int R, int C) {
    __shared__ float t[32][33];
    int c0 = blockIdx.x * 32, r0 = blockIdx.y * 32;
    int tx = threadIdx.x, ty = threadIdx.y;   // (32, 8)
#pragma unroll
    for (int i = 0; i < 4; i++)
        t[ty + i*8][tx] = src[(size_t)(r0 + ty + i*8) * C + c0 + tx];
    __syncthreads();
    int tid = ty * 32 + tx;
    int sy = tid >> 3;        // 0..31 -> c
    int sx = tid & 7;         // 0..7  -> r group of 4
    float v0 = t[sx*4+0][sy], v1 = t[sx*4+1][sy];
    float v2 = t[sx*4+2][sy], v3 = t[sx*4+3][sy];
    uint32_t h0, l0, h1, l1;
    split2(v0, v1, h0, l0);
    split2(v2, v3, h1, l1);
    size_t o = (size_t)(c0 + sy) * R + r0 + sx * 4;
    *(uint2*)(dhi + o) = make_uint2(h0, h1);
    *(uint2*)(dlo + o) = make_uint2(l0, l1);
}

// wq/wk/wv [16][1024][64] -> Wt [3072][1024] bf16 hi/lo
__global__ void qkv_tsplit_kernel(const float* __restrict__ wq, const float* __restrict__ wk,
                                  const float* __restrict__ wv,
                                  __nv_bfloat16* __restrict__ dhi,
                                  __nv_bfloat16* __restrict__ dlo) {
    __shared__ float t[32][33];
    int z = blockIdx.z, p = z >> 4, h = z & 15;
    const float* src = (p == 0 ? wq : (p == 1 ? wk : wv)) + (size_t)h * 1024 * 64;
    int c0 = blockIdx.x * 32, r0 = blockIdx.y * 32;
    int tx = threadIdx.x, ty = threadIdx.y;
#pragma unroll
    for (int i = 0; i < 4; i++)
        t[ty + i*8][tx] = src[(size_t)(r0 + ty + i*8) * 64 + c0 + tx];
    __syncthreads();
    int nbase = (p << 10) + (h << 6);
    int tid = ty * 32 + tx;
    int sy = tid >> 3;
    int sx = tid & 7;
    float v0 = t[sx*4+0][sy], v1 = t[sx*4+1][sy];
    float v2 = t[sx*4+2][sy], v3 = t[sx*4+3][sy];
    uint32_t h0, l0, h1, l1;
    split2(v0, v1, h0, l0);
    split2(v2, v3, h1, l1);
    size_t o = (size_t)(nbase + c0 + sy) * 1024 + r0 + sx * 4;
    *(uint2*)(dhi + o) = make_uint2(h0, h1);
    *(uint2*)(dlo + o) = make_uint2(l0, l1);
}

// ================= HMMA split-bf16 GEMM (mma.sync m16n8k16) =================
// 128x64 CTA tile, 8 warps (32x32 each), BK=32, 2-stage cp.async, 2 CTAs/SM.
#define TG_STRB  80
#define TG_A_MAT 10240      // 128*80
#define TG_B_MAT 5120       // 64*80
#define TG_STAGE 30720      // Ahi+Alo+Bhi+Blo
#define TG_SMEM  61440      // 2 stages

__device__ __forceinline__ void tg_load(
        const __nv_bfloat16* __restrict__ Ah, const __nv_bfloat16* __restrict__ Al,
        const __nv_bfloat16* __restrict__ Bh, const __nv_bfloat16* __restrict__ Bl,
        int K, int k0, uint32_t sbase, int tid) {
#pragma unroll
    for (int j = 0; j < 2; j++) {
        int idx = tid + (j << 8);
        int row = idx >> 2, kc = idx & 3;
        uint32_t d = sbase + row * TG_STRB + (kc << 4);
        const size_t go = (size_t)row * K + k0 + (kc << 3);
        CP_ASYNC16(d,            Ah + go);
        CP_ASYNC16(d + TG_A_MAT, Al + go);
    }
    {
        int row = tid >> 2, kc = tid & 3;
        uint32_t d = sbase + 2 * TG_A_MAT + row * TG_STRB + (kc << 4);
        const size_t go = (size_t)row * K + k0 + (kc << 3);
        CP_ASYNC16(d,            Bh + go);
        CP_ASYNC16(d + TG_B_MAT, Bl + go);
    }
}

template<bool RELU, bool SPLITO>
__global__ __launch_bounds__(256, 2)
void tc_gemm_kernel(const __nv_bfloat16* __restrict__ Ahi, const __nv_bfloat16* __restrict__ Alo,
                    const __nv_bfloat16* __restrict__ Bhi, const __nv_bfloat16* __restrict__ Blo,
                    const float* __restrict__ bias, float* __restrict__ C,
                    __nv_bfloat16* __restrict__ Chi, __nv_bfloat16* __restrict__ Clo,
                    int M, int N, int K) {
    extern __shared__ char smem[];
    const uint32_t sb = smem_u32(smem);
    const int tid = threadIdx.x, wid = tid >> 5, lane = tid & 31;
    const int wm = wid >> 1, wn = wid & 1;           // warp grid 4(m) x 2(n)
    const int m0 = blockIdx.y * 128, n0 = blockIdx.x * 64;

    const __nv_bfloat16* pAh = Ahi + (size_t)m0 * K;
    const __nv_bfloat16* pAl = Alo + (size_t)m0 * K;
    const __nv_bfloat16* pBh = Bhi + (size_t)n0 * K;
    const __nv_bfloat16* pBl = Blo + (size_t)n0 * K;

    float acc[2][4][4];
#pragma unroll
    for (int i = 0; i < 2; i++)
#pragma unroll
        for (int j = 0; j < 4; j++)
#pragma unroll
            for (int r = 0; r < 4; r++) acc[i][j][r] = 0.f;

    const int nchunk = K >> 5;
    tg_load(pAh, pAl, pBh, pBl, K, 0, sb, tid);
    CP_COMMIT();

    const uint32_t a_row  = (uint32_t)(wm * 32 + (lane & 15));
    const uint32_t a_koff = (uint32_t)((lane >> 4) << 4);
    const uint32_t b_rowl = (uint32_t)(((lane >> 4) << 3) + (lane & 7));
    const uint32_t b_koff = (uint32_t)(((lane >> 3) & 1) << 4);

    for (int c = 0; c < nchunk; c++) {
        CP_WAIT0();
        __syncthreads();
        if (c + 1 < nchunk) {
            tg_load(pAh, pAl, pBh, pBl, K, (c + 1) << 5,
                    sb + (uint32_t)((c + 1) & 1) * TG_STAGE, tid);
            CP_COMMIT();
        }

        const uint32_t st = sb + (uint32_t)(c & 1) * TG_STAGE;
#pragma unroll
        for (int ks = 0; ks < 2; ks++) {
            uint32_t ah[2][4], al[2][4], bh[4][2], bl[4][2];
#pragma unroll
            for (int mt = 0; mt < 2; mt++) {
                uint32_t ad = st + (a_row + mt * 16) * TG_STRB + ks * 32 + a_koff;
                LDSM_X4(ah[mt][0], ah[mt][1], ah[mt][2], ah[mt][3], ad);
                LDSM_X4(al[mt][0], al[mt][1], al[mt][2], al[mt][3], ad + TG_A_MAT);
            }
#pragma unroll
            for (int p = 0; p < 2; p++) {
                uint32_t bd = st + 2 * TG_A_MAT +
                              (wn * 32 + p * 16 + b_rowl) * TG_STRB + ks * 32 + b_koff;
                LDSM_X4(bh[2*p][0], bh[2*p][1], bh[2*p+1][0], bh[2*p+1][1], bd);
                LDSM_X4(bl[2*p][0], bl[2*p][1], bl[2*p+1][0], bl[2*p+1][1], bd + TG_B_MAT);
            }
#pragma unroll
            for (int mt = 0; mt < 2; mt++)
#pragma unroll
                for (int nt = 0; nt < 4; nt++) {
                    MMA_BF16(acc[mt][nt], ah[mt], bh[nt]);
                    MMA_BF16(acc[mt][nt], ah[mt], bl[nt]);
                    MMA_BF16(acc[mt][nt], al[mt], bh[nt]);
                }
        }
    }

#pragma unroll
    for (int mt = 0; mt < 2; mt++) {
        const int r0 = m0 + wm * 32 + mt * 16 + (lane >> 2);
#pragma unroll
        for (int nt = 0; nt < 4; nt++) {
            const int c0 = n0 + wn * 32 + nt * 8 + ((lane & 3) << 1);
            float bx = bias ? bias[c0]     : 0.f;
            float by = bias ? bias[c0 + 1] : 0.f;
            float v0 = acc[mt][nt][0] + bx, v1 = acc[mt][nt][1] + by;
            float v2 = acc[mt][nt][2] + bx, v3 = acc[mt][nt][3] + by;
            if (RELU) {
                v0 = fmaxf(v0, 0.f); v1 = fmaxf(v1, 0.f);
                v2 = fmaxf(v2, 0.f); v3 = fmaxf(v3, 0.f);
            }
            if (SPLITO) {
                uint32_t hi, lo;
                split2(v0, v1, hi, lo);
                *(uint32_t*)(Chi + (size_t)r0 * N + c0) = hi;
                *(uint32_t*)(Clo + (size_t)r0 * N + c0) = lo;
                split2(v2, v3, hi, lo);
                *(uint32_t*)(Chi + (size_t)(r0 + 8) * N + c0) = hi;
                *(uint32_t*)(Clo + (size_t)(r0 + 8) * N + c0) = lo;
            } else {
                *(float2*)(C + (size_t)r0 * N + c0)       = make_float2(v0, v1);
                *(float2*)(C + (size_t)(r0 + 8) * N + c0) = make_float2(v2, v3);
            }
        }
    }
}

// ================= tensor-core flash attention (causal, split-bf16) =================
// Br=128 rows per CTA, Bc=64 cols per iter, dh=64. 8 warps x 16 rows.
// Inputs are PRE-SPLIT bf16 hi/lo (from the QKV GEMM epilogue): staging is pure
// copies for Q/K and a PRMT-based 4x4 transpose for V.
#define AT_STRB 144            // smem row stride bytes (72 bf16)
#define AT_K_HI 0
#define AT_K_LO 9216
#define AT_V_HI 18432
#define AT_V_LO 27648
#define AT_SMEM 36864          // Q staging reuses region: hi@0, lo@18432

struct KVPre { uint4 kh[2], kl[2]; uint2 vh[4], vl[4]; };

__device__ __forceinline__ void at_prefetch(
        const __nv_bfloat16* __restrict__ khg, const __nv_bfloat16* __restrict__ klg,
        const __nv_bfloat16* __restrict__ vhg, const __nv_bfloat16* __restrict__ vlg,
        int kc, int tid, KVPre& p) {
    const int rgv = tid >> 4, cgv = tid & 15;
#pragma unroll
    for (int i = 0; i < 2; i++) {
        int idx = tid + (i << 8);
        int row = idx >> 3, c16 = idx & 7;
        size_t o = (size_t)(kc * 64 + row) * 3072 + (c16 << 3);
        p.kh[i] = *(const uint4*)(khg + o);
        p.kl[i] = *(const uint4*)(klg + o);
    }
#pragma unroll
    for (int i = 0; i < 4; i++) {
        size_t o = (size_t)(kc * 64 + 4 * rgv + i) * 3072 + (cgv << 2);
        p.vh[i] = *(const uint2*)(vhg + o);
        p.vl[i] = *(const uint2*)(vlg + o);
    }
}

__global__ __launch_bounds__(256)
void attn_mma_kernel(const __nv_bfloat16* __restrict__ qkvh,
                     const __nv_bfloat16* __restrict__ qkvl,
                     __nv_bfloat16* __restrict__ ohi,
                     __nv_bfloat16* __restrict__ olo) {
    extern __shared__ char smc[];
    const uint32_t sb = smem_u32(smc);
    const int b = blockIdx.y >> 4, h = blockIdx.y & 15;
    const int it = (int)gridDim.x - 1 - (int)blockIdx.x;    // heavy tiles first
    const int r0 = it * 128;
    const int tid = threadIdx.x, w = tid >> 5, lane = tid & 31;

    const size_t base = (size_t)b * SEQc * 3072 + (size_t)(h * 64);
    const __nv_bfloat16* qhg = qkvh + base;
    const __nv_bfloat16* qlg = qkvl + base;
    const __nv_bfloat16* khg = qkvh + base + 1024;
    const __nv_bfloat16* klg = qkvl + base + 1024;
    const __nv_bfloat16* vhg = qkvh + base + 2048;
    const __nv_bfloat16* vlg = qkvl + base + 2048;

    // ---- stage Q (128x64 bf16 hi/lo) into smem: pure copies ----
#pragma unroll
    for (int i = 0; i < 4; i++) {
        int idx = tid + (i << 8);          // 0..1023
        int row = idx >> 3, c16 = idx & 7;
        size_t o = (size_t)(r0 + row) * 3072 + (c16 << 3);
        uint32_t off = (uint32_t)(row * AT_STRB + (c16 << 4));
        *(uint4*)(smc + off)         = *(const uint4*)(qhg + o);
        *(uint4*)(smc + 18432 + off) = *(const uint4*)(qlg + o);
    }
    __syncthreads();

    // Q fragments (register-resident for the whole row tile)
    uint32_t qh[4][4], ql[4][4];
    {
        uint32_t qa = sb + (uint32_t)((w * 16 + (lane & 15)) * AT_STRB) + (uint32_t)(((lane >> 4) << 4));
#pragma unroll
        for (int kt = 0; kt < 4; kt++) {
            LDSM_X4(qh[kt][0], qh[kt][1], qh[kt][2], qh[kt][3], qa + kt * 32);
            LDSM_X4(ql[kt][0], ql[kt][1], ql[kt][2], ql[kt][3], qa + 18432 + kt * 32);
        }
    }

    float acc[8][4];
#pragma unroll
    for (int nt = 0; nt < 8; nt++)
#pragma unroll
        for (int r = 0; r < 4; r++) acc[nt][r] = 0.f;
    float m0 = -1e30f, m1 = -1e30f, l0 = 0.f, l1 = 0.f;

    const int row0 = r0 + w * 16 + (lane >> 2);
    const int row1 = row0 + 8;
    const int ktiles = 2 * it + 2;
    const int diag0 = 2 * it;
    const uint32_t brow = (uint32_t)(((lane >> 4) << 3) + (lane & 7));
    const uint32_t bko  = (uint32_t)(((lane >> 3) & 1) << 4);
    const int rgv = tid >> 4, cgv = tid & 15;

    KVPre pre;
    at_prefetch(khg, klg, vhg, vlg, 0, tid, pre);

    for (int kc = 0; kc < ktiles; kc++) {
        __syncthreads();          // previous tile consumed (or Q frags loaded)

        // ---- store prefetched K (K-major) hi/lo: straight copies ----
#pragma unroll
        for (int i = 0; i < 2; i++) {
            int idx = tid + (i << 8);
            int row = idx >> 3, c16 = idx & 7;
            uint32_t off = (uint32_t)(row * AT_STRB + (c16 << 4));
            *(uint4*)(smc + AT_K_HI + off) = pre.kh[i];
            *(uint4*)(smc + AT_K_LO + off) = pre.kl[i];
        }
        // ---- store prefetched V transposed: PRMT 4x4 bf16 transpose ----
        {
            uint32_t inh[4][2] = {{pre.vh[0].x, pre.vh[0].y}, {pre.vh[1].x, pre.vh[1].y},
                                  {pre.vh[2].x, pre.vh[2].y}, {pre.vh[3].x, pre.vh[3].y}};
            uint32_t inl[4][2] = {{pre.vl[0].x, pre.vl[0].y}, {pre.vl[1].x, pre.vl[1].y},
                                  {pre.vl[2].x, pre.vl[2].y}, {pre.vl[3].x, pre.vl[3].y}};
#pragma unroll
            for (int dd = 0; dd < 4; dd++) {
                int col = (cgv << 2) + dd;
                int q = dd >> 1;
                uint32_t sel = (dd & 1) ? 0x7632u : 0x5410u;
                uint32_t h01, h23, l01, l23;
                PRMT(h01, inh[0][q], inh[1][q], sel);
                PRMT(h23, inh[2][q], inh[3][q], sel);
                PRMT(l01, inl[0][q], inl[1][q], sel);
                PRMT(l23, inl[2][q], inl[3][q], sel);
                uint32_t sw = (uint32_t)(((col >> 3) & 3) << 4);
                uint32_t byte = (uint32_t)(col * AT_STRB) + (((uint32_t)(rgv << 3)) ^ sw);
                *(uint2*)(smc + AT_V_HI + byte) = make_uint2(h01, h23);
                *(uint2*)(smc + AT_V_LO + byte) = make_uint2(l01, l23);
            }
        }
        __syncthreads();

        // prefetch next tile's gmem data (overlaps with MMAs below)
        if (kc + 1 < ktiles) at_prefetch(khg, klg, vhg, vlg, kc + 1, tid, pre);

        // ---- S = Q K^T (split, 3 terms) ----
        float s[8][4];
#pragma unroll
        for (int nt = 0; nt < 8; nt++)
#pragma unroll
            for (int r = 0; r < 4; r++) s[nt][r] = 0.f;
#pragma unroll
        for (int kt = 0; kt < 4; kt++) {
            uint32_t bh[8][2], bl[8][2];
#pragma unroll
            for (int p = 0; p < 4; p++) {
                uint32_t bd = sb + AT_K_HI + (p * 16 + brow) * AT_STRB + kt * 32 + bko;
                LDSM_X4(bh[2*p][0], bh[2*p][1], bh[2*p+1][0], bh[2*p+1][1], bd);
                LDSM_X4(bl[2*p][0], bl[2*p][1], bl[2*p+1][0], bl[2*p+1][1], bd + 9216);
            }
#pragma unroll
            for (int nt = 0; nt < 8; nt++) {
                MMA_BF16(s[nt], qh[kt], bh[nt]);
                MMA_BF16(s[nt], qh[kt], bl[nt]);
                MMA_BF16(s[nt], ql[kt], bh[nt]);
            }
        }
#pragma unroll
        for (int nt = 0; nt < 8; nt++)
#pragma unroll
            for (int r = 0; r < 4; r++) s[nt][r] *= 0.125f;

        // ---- causal mask (diagonal tiles only) ----
        if (kc >= diag0) {
            int colb = kc * 64 + ((lane & 3) << 1);
#pragma unroll
            for (int nt = 0; nt < 8; nt++) {
                int c0 = colb + nt * 8;
                if (c0     > row0) s[nt][0] = -1e30f;
                if (c0 + 1 > row0) s[nt][1] = -1e30f;
                if (c0     > row1) s[nt][2] = -1e30f;
                if (c0 + 1 > row1) s[nt][3] = -1e30f;
            }
        }

        // ---- online softmax (rows r and r+8; 4-lane group reductions) ----
        float mx0 = -1e30f, mx1 = -1e30f;
#pragma unroll
        for (int nt = 0; nt < 8; nt++) {
            mx0 = fmaxf(mx0, fmaxf(s[nt][0], s[nt][1]));
            mx1 = fmaxf(mx1, fmaxf(s[nt][2], s[nt][3]));
        }
        mx0 = fmaxf(mx0, __shfl_xor_sync(0xffffffffu, mx0, 1));
        mx0 = fmaxf(mx0, __shfl_xor_sync(0xffffffffu, mx0, 2));
        mx1 = fmaxf(mx1, __shfl_xor_sync(0xffffffffu, mx1, 1));
        mx1 = fmaxf(mx1, __shfl_xor_sync(0xffffffffu, mx1, 2));
        float nm0 = fmaxf(m0, mx0), nm1 = fmaxf(m1, mx1);
        float sum0 = 0.f, sum1 = 0.f;
#pragma unroll
        for (int nt = 0; nt < 8; nt++) {
            s[nt][0] = __expf(s[nt][0] - nm0); sum0 += s[nt][0];
            s[nt][1] = __expf(s[nt][1] - nm0); sum0 += s[nt][1];
            s[nt][2] = __expf(s[nt][2] - nm1); sum1 += s[nt][2];
            s[nt][3] = __expf(s[nt][3] - nm1); sum1 += s[nt][3];
        }
        sum0 += __shfl_xor_sync(0xffffffffu, sum0, 1);
        sum0 += __shfl_xor_sync(0xffffffffu, sum0, 2);
        sum1 += __shfl_xor_sync(0xffffffffu, sum1, 1);
        sum1 += __shfl_xor_sync(0xffffffffu, sum1, 2);
        float a0 = __expf(m0 - nm0), a1 = __expf(m1 - nm1);
        m0 = nm0; m1 = nm1;
        l0 = l0 * a0 + sum0; l1 = l1 * a1 + sum1;
#pragma unroll
        for (int nt = 0; nt < 8; nt++) {
            acc[nt][0] *= a0; acc[nt][1] *= a0;
            acc[nt][2] *= a1; acc[nt][3] *= a1;
        }

        // ---- repack S accumulator fragments into P A-fragments (hi/lo) ----
        uint32_t ph[4][4], pl[4][4];
#pragma unroll
        for (int kt = 0; kt < 4; kt++) {
            int e = 2 * kt, o = 2 * kt + 1;
            split2(s[e][0], s[e][1], ph[kt][0], pl[kt][0]);
            split2(s[e][2], s[e][3], ph[kt][1], pl[kt][1]);
            split2(s[o][0], s[o][1], ph[kt][2], pl[kt][2]);
            split2(s[o][2], s[o][3], ph[kt][3], pl[kt][3]);
        }

        // ---- O += P @ V (split, 3 terms; swizzled V reads) ----
#pragma unroll
        for (int kt = 0; kt < 4; kt++) {
            uint32_t vh[8][2], vl[8][2];
#pragma unroll
            for (int p = 0; p < 4; p++) {
                uint32_t dlane = (uint32_t)(p * 16) + brow;
                uint32_t sw = ((dlane >> 3) & 3) << 4;
                uint32_t bd = sb + AT_V_HI + dlane * AT_STRB + ((uint32_t)(kt * 32 + bko) ^ sw);
                LDSM_X4(vh[2*p][0], vh[2*p][1], vh[2*p+1][0], vh[2*p+1][1], bd);
                LDSM_X4(vl[2*p][0], vl[2*p][1], vl[2*p+1][0], vl[2*p+1][1], bd + 9216);
            }
#pragma unroll
            for (int nt = 0; nt < 8; nt++) {
                MMA_BF16(acc[nt], ph[kt], vh[nt]);
                MMA_BF16(acc[nt], ph[kt], vl[nt]);
                MMA_BF16(acc[nt], pl[kt], vh[nt]);
            }
        }
    }

    // ---- epilogue: normalize and write bf16 hi/lo (concat head layout) ----
    float inv0 = 1.f / l0, inv1 = 1.f / l1;
    const int tok0 = b * SEQc + row0;
#pragma unroll
    for (int nt = 0; nt < 8; nt++) {
        int col = h * 64 + nt * 8 + ((lane & 3) << 1);
        uint32_t hi, lo;
        split2(acc[nt][0] * inv0, acc[nt][1] * inv0, hi, lo);
        *(uint32_t*)(ohi + (size_t)tok0 * 1024 + col) = hi;
        *(uint32_t*)(olo + (size_t)tok0 * 1024 + col) = lo;
        split2(acc[nt][2] * inv1, acc[nt][3] * inv1, hi, lo);
        *(uint32_t*)(ohi + (size_t)(tok0 + 8) * 1024 + col) = hi;
        *(uint32_t*)(olo + (size_t)(tok0 + 8) * 1024 + col) = lo;
    }
}

// ---------------- LayerNorm + residual ----------------
template<bool SPLITO>
__global__ void ln_residual_kernel(const float* __restrict__ resid,
                                   const float* __restrict__ v,
                                   const float* __restrict__ g,
                                   const float* __restrict__ beta,
                                   float* __restrict__ out,
                                   __nv_bfloat16* __restrict__ ohi,
                                   __nv_bfloat16* __restrict__ olo) {
    __shared__ float red[16];
    const int row = blockIdx.x;
    const int t = threadIdx.x;
    const float* vr = v + (size_t)row * D_MODELc;
    float4 xv = *(const float4*)(vr + t * 4);
    float s  = xv.x + xv.y + xv.z + xv.w;
    float s2 = xv.x * xv.x + xv.y * xv.y + xv.z * xv.z + xv.w * xv.w;
#pragma unroll
    for (int o = 16; o; o >>= 1) {
        s  += __shfl_xor_sync(0xffffffffu, s,  o);
        s2 += __shfl_xor_sync(0xffffffffu, s2, o);
    }
    int wid = t >> 5;
    if ((t & 31) == 0) { red[wid] = s; red[8 + wid] = s2; }
    __syncthreads();
    float S = 0.f, S2 = 0.f;
#pragma unroll
    for (int i = 0; i < 8; i++) { S += red[i]; S2 += red[8 + i]; }
    float mu   = S * (1.f / D_MODELc);
    float var  = S2 * (1.f / D_MODELc) - mu * mu;
    float rstd = rsqrtf(var + LN_EPSc);

    int c = t * 4;
    float4 rr = *(const float4*)(resid + (size_t)row * D_MODELc + c);
    float4 gg = *(const float4*)(g + c);
    float4 bb = *(const float4*)(beta + c);
    float4 o;
    o.x = rr.x + (xv.x - mu) * rstd * gg.x + bb.x;
    o.y = rr.y + (xv.y - mu) * rstd * gg.y + bb.y;
    o.z = rr.z + (xv.z - mu) * rstd * gg.z + bb.z;
    o.w = rr.w + (xv.w - mu) * rstd * gg.w + bb.w;
    *(float4*)(out + (size_t)row * D_MODELc + c) = o;
    if (SPLITO) {
        uint32_t h0, l0, h1, l1;
        split2(o.x, o.y, h0, l0);
        split2(o.z, o.w, h1, l1);
        *(uint2*)(ohi + (size_t)row * D_MODELc + c) = make_uint2(h0, h1);
        *(uint2*)(olo + (size_t)row * D_MODELc + c) = make_uint2(l0, l1);
    }
}

// ---------------- launch ----------------
extern "C" void kernel_launch(void* const* d_in, const int* in_sizes, int n_in,
                              void* d_out, int out_size) {
    (void)in_sizes; (void)n_in; (void)out_size;
    const float* x     = (const float*)d_in[0];
    const float* wq    = (const float*)d_in[1];
    const float* wk    = (const float*)d_in[2];
    const float* wv    = (const float*)d_in[3];
    const float* wo    = (const float*)d_in[4];
    const float* w_in  = (const float*)d_in[5];
    const float* b_in  = (const float*)d_in[6];
    const float* w_out = (const float*)d_in[7];
    const float* b_out = (const float*)d_in[8];
    const float* g1    = (const float*)d_in[9];
    const float* bt1   = (const float*)d_in[10];
    const float* g2    = (const float*)d_in[11];
    const float* bt2   = (const float*)d_in[12];
    float* out = (float*)d_out;

    float *proj, *x1, *mlp;
    __nv_bfloat16 *qkvh, *qkvl, *ahi, *alo, *bhi, *blo, *mh, *ml;
    cudaGetSymbolAddress((void**)&proj, g_proj);
    cudaGetSymbolAddress((void**)&x1,   g_x1);
    cudaGetSymbolAddress((void**)&mlp,  g_mlp);
    cudaGetSymbolAddress((void**)&qkvh, g_qkvh);
    cudaGetSymbolAddress((void**)&qkvl, g_qkvl);
    cudaGetSymbolAddress((void**)&ahi,  g_ahi);
    cudaGetSymbolAddress((void**)&alo,  g_alo);
    cudaGetSymbolAddress((void**)&bhi,  g_bhi);
    cudaGetSymbolAddress((void**)&blo,  g_blo);
    cudaGetSymbolAddress((void**)&mh,   g_mlph_hi);
    cudaGetSymbolAddress((void**)&ml,   g_mlph_lo);

    cudaFuncSetAttribute(tc_gemm_kernel<false, false>, cudaFuncAttributeMaxDynamicSharedMemorySize, TG_SMEM);
    cudaFuncSetAttribute(tc_gemm_kernel<false, true>,  cudaFuncAttributeMaxDynamicSharedMemorySize, TG_SMEM);
    cudaFuncSetAttribute(tc_gemm_kernel<true,  true>,  cudaFuncAttributeMaxDynamicSharedMemorySize, TG_SMEM);
    cudaFuncSetAttribute(attn_mma_kernel, cudaFuncAttributeMaxDynamicSharedMemorySize, AT_SMEM);

    dim3 tsb(32, 8);

    // ---- QKV projection: [4096,1024] @ [1024,3072], split bf16 output ----
    qkv_tsplit_kernel<<<dim3(2, 32, 48), tsb>>>(wq, wk, wv, bhi, blo);
    asplit_kernel<<<(NTOK * D_MODELc / 4 + 255) / 256, 256>>>(x, ahi, alo, NTOK * D_MODELc / 4);
    tc_gemm_kernel<false, true><<<dim3(48, 32), 256, TG_SMEM>>>(
        ahi, alo, bhi, blo, nullptr, nullptr, qkvh, qkvl, NTOK, 3072, 1024);

    // ---- tensor-core causal flash attention -> bf16 hi/lo (overwrites ahi/alo) ----
    attn_mma_kernel<<<dim3(SEQc / 128, BATCHc * 16), 256, AT_SMEM>>>(qkvh, qkvl, ahi, alo);

    // ---- output projection: att @ wo ----
    tsplit_kernel<<<dim3(32, 32), tsb>>>(wo, bhi, blo, 1024, 1024);
    tc_gemm_kernel<false, false><<<dim3(16, 32), 256, TG_SMEM>>>(
        ahi, alo, bhi, blo, nullptr, proj, nullptr, nullptr, NTOK, 1024, 1024);

    // ---- x1 = x + LN(proj), fused split into ahi/alo ----
    ln_residual_kernel<true><<<NTOK, 256>>>(x, proj, g1, bt1, x1, ahi, alo);

    // ---- MLP in: relu(x1 @ w_in + b_in), fused split output ----
    tsplit_kernel<<<dim3(128, 32), tsb>>>(w_in, bhi, blo, 1024, 4096);
    tc_gemm_kernel<true, true><<<dim3(64, 32), 256, TG_SMEM>>>(
        ahi, alo, bhi, blo, b_in, nullptr, mh, ml, NTOK, 4096, 1024);

    // ---- MLP out: mlph @ w_out + b_out ----
    tsplit_kernel<<<dim3(32, 128), tsb>>>(w_out, bhi, blo, 4096, 1024);
    tc_gemm_kernel<false, false><<<dim3(16, 32), 256, TG_SMEM>>>(
        mh, ml, bhi, blo, b_out, mlp, nullptr, nullptr, NTOK, 1024, 4096);

    // ---- out = x1 + LN(mlp) ----
    ln_residual_kernel<false><<<NTOK, 256>>>(x1, mlp, g2, bt2, out, nullptr, nullptr);
}

// round 10
// speedup vs baseline: 2.6308x; 1.0638x over previous
#include <cuda_runtime.h>
#include <cuda_bf16.h>
#include <cstdint>
#include <math.h>

// ---------------- problem constants ----------------
#define D_MODELc 1024
#define SEQc     2048
#define BATCHc   2
#define NTOK     (BATCHc*SEQc)     // 4096 tokens
#define D_MLPc   4096
#define LN_EPSc  1e-5f

// ---------------- device scratch (no runtime allocation allowed) ----------------
__device__ float g_proj[(size_t)NTOK * D_MODELc];               // head_out @ wo
__device__ float g_x1  [(size_t)NTOK * D_MODELc];               // x + LN1(proj)
__device__ float g_mlp [(size_t)NTOK * D_MODELc];               // mlp output
__device__ __nv_bfloat16 g_qkvh[(size_t)NTOK * 3 * D_MODELc];   // qkv split hi
__device__ __nv_bfloat16 g_qkvl[(size_t)NTOK * 3 * D_MODELc];   // qkv split lo
__device__ __nv_bfloat16 g_mlph_hi[(size_t)NTOK * D_MLPc];      // relu(x1@w_in+b_in) split
__device__ __nv_bfloat16 g_mlph_lo[(size_t)NTOK * D_MLPc];
__device__ __nv_bfloat16 g_ahi[(size_t)NTOK * D_MODELc];        // activation split (reused)
__device__ __nv_bfloat16 g_alo[(size_t)NTOK * D_MODELc];
__device__ __nv_bfloat16 g_bhi[(size_t)D_MLPc * D_MODELc];      // weight split (reused)
__device__ __nv_bfloat16 g_blo[(size_t)D_MLPc * D_MODELc];

// ================= PTX helpers (baseline sm_80+ features only) =================
__device__ __forceinline__ uint32_t smem_u32(const void* p) {
    uint32_t a;
    asm("{ .reg .u64 t; cvta.to.shared.u64 t, %1; cvt.u32.u64 %0, t; }" : "=r"(a) : "l"(p));
    return a;
}
#define CP_ASYNC16(dst, src) \
    asm volatile("cp.async.cg.shared.global [%0], [%1], 16;" :: "r"(dst), "l"(src))
#define CP_COMMIT()  asm volatile("cp.async.commit_group;" ::: "memory")
#define CP_WAIT0()   asm volatile("cp.async.wait_group 0;" ::: "memory")
#define LDSM_X4(r0, r1, r2, r3, addr) \
    asm volatile("ldmatrix.sync.aligned.m8n8.x4.shared.b16 {%0,%1,%2,%3}, [%4];" \
        : "=r"(r0), "=r"(r1), "=r"(r2), "=r"(r3) : "r"(addr))
#define MMA_BF16(d, a, b) \
    asm volatile("mma.sync.aligned.m16n8k16.row.col.f32.bf16.bf16.f32 " \
        "{%0,%1,%2,%3},{%4,%5,%6,%7},{%8,%9},{%0,%1,%2,%3};" \
        : "+f"((d)[0]), "+f"((d)[1]), "+f"((d)[2]), "+f"((d)[3]) \
        : "r"((a)[0]), "r"((a)[1]), "r"((a)[2]), "r"((a)[3]), "r"((b)[0]), "r"((b)[1]))
#define PRMT(d, a, b, sel) \
    asm("prmt.b32 %0, %1, %2, %3;" : "=r"(d) : "r"(a), "r"(b), "r"(sel))

// split two fp32 into packed bf16 hi pair + lo (residual) pair
__device__ __forceinline__ void split2(float a, float b, uint32_t& hi, uint32_t& lo) {
    __nv_bfloat16 ha = __float2bfloat16(a), hb = __float2bfloat16(b);
    __nv_bfloat16 la = __float2bfloat16(a - __bfloat162float(ha));
    __nv_bfloat16 lb = __float2bfloat16(b - __bfloat162float(hb));
    __nv_bfloat162 H(ha, hb), L(la, lb);
    hi = *(uint32_t*)&H; lo = *(uint32_t*)&L;
}

// ================= split / transpose kernels =================
__global__ void asplit_kernel(const float* __restrict__ src,
                              __nv_bfloat16* __restrict__ dhi,
                              __nv_bfloat16* __restrict__ dlo, int n4) {
    int i = blockIdx.x * blockDim.x + threadIdx.x;
    if (i >= n4) return;
    float4 v = ((const float4*)src)[i];
    uint32_t h0, l0, h1, l1;
    split2(v.x, v.y, h0, l0);
    split2(v.z, v.w, h1, l1);
    ((uint2*)dhi)[i] = make_uint2(h0, h1);
    ((uint2*)dlo)[i] = make_uint2(l0, l1);
}

// tiled transpose+split: src [R][C] fp32 -> dst [C][R] bf16 hi/lo (vectorized stores)
__global__ void tsplit_kernel(const float* __restrict__ src,
                              __nv_bfloat16* __restrict__ dhi,
                              __nv_bfloat16* __restrict__ dlo, int R, int C) {
    __shared__ float t[32][33];
    int c0 = blockIdx.x * 32, r0 = blockIdx.y * 32;
    int tx = threadIdx.x, ty = threadIdx.y;   // (32, 8)
#pragma unroll
    for (int i = 0; i < 4; i++)
        t[ty + i*8][tx] = src[(size_t)(r0 + ty + i*8) * C + c0 + tx];
    __syncthreads();
    int tid = ty * 32 + tx;
    int sy = tid >> 3;        // 0..31 -> c
    int sx = tid & 7;         // 0..7  -> r group of 4
    float v0 = t[sx*4+0][sy], v1 = t[sx*4+1][sy];
    float v2 = t[sx*4+2][sy], v3 = t[sx*4+3][sy];
    uint32_t h0, l0, h1, l1;
    split2(v0, v1, h0, l0);
    split2(v2, v3, h1, l1);
    size_t o = (size_t)(c0 + sy) * R + r0 + sx * 4;
    *(uint2*)(dhi + o) = make_uint2(h0, h1);
    *(uint2*)(dlo + o) = make_uint2(l0, l1);
}

// wq/wk/wv [16][1024][64] -> Wt [3072][1024] bf16 hi/lo
__global__ void qkv_tsplit_kernel(const float* __restrict__ wq, const float* __restrict__ wk,
                                  const float* __restrict__ wv,
                                  __nv_bfloat16* __restrict__ dhi,
                                  __nv_bfloat16* __restrict__ dlo) {
    __shared__ float t[32][33];
    int z = blockIdx.z, p = z >> 4, h = z & 15;
    const float* src = (p == 0 ? wq : (p == 1 ? wk : wv)) + (size_t)h * 1024 * 64;
    int c0 = blockIdx.x * 32, r0 = blockIdx.y * 32;
    int tx = threadIdx.x, ty = threadIdx.y;
#pragma unroll
    for (int i = 0; i < 4; i++)
        t[ty + i*8][tx] = src[(size_t)(r0 + ty + i*8) * 64 + c0 + tx];
    __syncthreads();
    int nbase = (p << 10) + (h << 6);
    int tid = ty * 32 + tx;
    int sy = tid >> 3;
    int sx = tid & 7;
    float v0 = t[sx*4+0][sy], v1 = t[sx*4+1][sy];
    float v2 = t[sx*4+2][sy], v3 = t[sx*4+3][sy];
    uint32_t h0, l0, h1, l1;
    split2(v0, v1, h0, l0);
    split2(v2, v3, h1, l1);
    size_t o = (size_t)(nbase + c0 + sy) * 1024 + r0 + sx * 4;
    *(uint2*)(dhi + o) = make_uint2(h0, h1);
    *(uint2*)(dlo + o) = make_uint2(l0, l1);
}

// ================= HMMA split-bf16 GEMM (mma.sync m16n8k16) =================
// 128x128 CTA tile, 4 warps (64x64 each), BK=32, 2-stage cp.async, 2 CTAs/SM.
// smem: [Ahi][Alo][Bhi][Blo] per stage; 192 MMAs : 32 ldsm per warp-chunk (6:1).
#define TG_STRB  80
#define TG_MAT   10240      // 128*80
#define TG_STAGE 40960
#define TG_SMEM  81920      // 2 stages

__device__ __forceinline__ void tg_load(
        const __nv_bfloat16* __restrict__ Ah, const __nv_bfloat16* __restrict__ Al,
        const __nv_bfloat16* __restrict__ Bh, const __nv_bfloat16* __restrict__ Bl,
        int K, int k0, uint32_t sbase, int tid) {
#pragma unroll
    for (int j = 0; j < 4; j++) {
        int idx = tid + (j << 7);      // 128 threads, 512 chunks per matrix
        int row = idx >> 2, kc = idx & 3;
        uint32_t d = sbase + row * TG_STRB + (kc << 4);
        const size_t go = (size_t)row * K + k0 + (kc << 3);
        CP_ASYNC16(d,              Ah + go);
        CP_ASYNC16(d +     TG_MAT, Al + go);
        CP_ASYNC16(d + 2 * TG_MAT, Bh + go);
        CP_ASYNC16(d + 3 * TG_MAT, Bl + go);
    }
}

template<bool RELU, bool SPLITO>
__global__ __launch_bounds__(128, 2)
void tc_gemm_kernel(const __nv_bfloat16* __restrict__ Ahi, const __nv_bfloat16* __restrict__ Alo,
                    const __nv_bfloat16* __restrict__ Bhi, const __nv_bfloat16* __restrict__ Blo,
                    const float* __restrict__ bias, float* __restrict__ C,
                    __nv_bfloat16* __restrict__ Chi, __nv_bfloat16* __restrict__ Clo,
                    int M, int N, int K) {
    extern __shared__ char smem[];
    const uint32_t sb = smem_u32(smem);
    const int tid = threadIdx.x, wid = tid >> 5, lane = tid & 31;
    const int wm = wid >> 1, wn = wid & 1;           // warp grid 2(m) x 2(n), 64x64 each
    const int m0 = blockIdx.y * 128, n0 = blockIdx.x * 128;

    const __nv_bfloat16* pAh = Ahi + (size_t)m0 * K;
    const __nv_bfloat16* pAl = Alo + (size_t)m0 * K;
    const __nv_bfloat16* pBh = Bhi + (size_t)n0 * K;
    const __nv_bfloat16* pBl = Blo + (size_t)n0 * K;

    float acc[4][8][4];
#pragma unroll
    for (int i = 0; i < 4; i++)
#pragma unroll
        for (int j = 0; j < 8; j++)
#pragma unroll
            for (int r = 0; r < 4; r++) acc[i][j][r] = 0.f;

    const int nchunk = K >> 5;
    tg_load(pAh, pAl, pBh, pBl, K, 0, sb, tid);
    CP_COMMIT();

    const uint32_t a_row  = (uint32_t)(wm * 64 + (lane & 15));
    const uint32_t a_koff = (uint32_t)((lane >> 4) << 4);
    const uint32_t b_rowl = (uint32_t)(((lane >> 4) << 3) + (lane & 7));
    const uint32_t b_koff = (uint32_t)(((lane >> 3) & 1) << 4);

    for (int c = 0; c < nchunk; c++) {
        CP_WAIT0();
        __syncthreads();
        if (c + 1 < nchunk) {
            tg_load(pAh, pAl, pBh, pBl, K, (c + 1) << 5,
                    sb + (uint32_t)((c + 1) & 1) * TG_STAGE, tid);
            CP_COMMIT();
        }

        const uint32_t st = sb + (uint32_t)(c & 1) * TG_STAGE;
#pragma unroll
        for (int ks = 0; ks < 2; ks++) {
            uint32_t ah[4][4], al[4][4];
#pragma unroll
            for (int mt = 0; mt < 4; mt++) {
                uint32_t ad = st + (a_row + mt * 16) * TG_STRB + ks * 32 + a_koff;
                LDSM_X4(ah[mt][0], ah[mt][1], ah[mt][2], ah[mt][3], ad);
                LDSM_X4(al[mt][0], al[mt][1], al[mt][2], al[mt][3], ad + TG_MAT);
            }
#pragma unroll
            for (int p = 0; p < 4; p++) {
                uint32_t bh[2][2], bl[2][2];
                uint32_t bd = st + 2 * TG_MAT +
                              (wn * 64 + p * 16 + b_rowl) * TG_STRB + ks * 32 + b_koff;
                LDSM_X4(bh[0][0], bh[0][1], bh[1][0], bh[1][1], bd);
                LDSM_X4(bl[0][0], bl[0][1], bl[1][0], bl[1][1], bd + TG_MAT);
#pragma unroll
                for (int mt = 0; mt < 4; mt++)
#pragma unroll
                    for (int q = 0; q < 2; q++) {
                        const int nt = p * 2 + q;
                        MMA_BF16(acc[mt][nt], ah[mt], bh[q]);
                        MMA_BF16(acc[mt][nt], ah[mt], bl[q]);
                        MMA_BF16(acc[mt][nt], al[mt], bh[q]);
                    }
            }
        }
    }

#pragma unroll
    for (int mt = 0; mt < 4; mt++) {
        const int r0 = m0 + wm * 64 + mt * 16 + (lane >> 2);
#pragma unroll
        for (int nt = 0; nt < 8; nt++) {
            const int c0 = n0 + wn * 64 + nt * 8 + ((lane & 3) << 1);
            float bx = bias ? bias[c0]     : 0.f;
            float by = bias ? bias[c0 + 1] : 0.f;
            float v0 = acc[mt][nt][0] + bx, v1 = acc[mt][nt][1] + by;
            float v2 = acc[mt][nt][2] + bx, v3 = acc[mt][nt][3] + by;
            if (RELU) {
                v0 = fmaxf(v0, 0.f); v1 = fmaxf(v1, 0.f);
                v2 = fmaxf(v2, 0.f); v3 = fmaxf(v3, 0.f);
            }
            if (SPLITO) {
                uint32_t hi, lo;
                split2(v0, v1, hi, lo);
                *(uint32_t*)(Chi + (size_t)r0 * N + c0) = hi;
                *(uint32_t*)(Clo + (size_t)r0 * N + c0) = lo;
                split2(v2, v3, hi, lo);
                *(uint32_t*)(Chi + (size_t)(r0 + 8) * N + c0) = hi;
                *(uint32_t*)(Clo + (size_t)(r0 + 8) * N + c0) = lo;
            } else {
                *(float2*)(C + (size_t)r0 * N + c0)       = make_float2(v0, v1);
                *(float2*)(C + (size_t)(r0 + 8) * N + c0) = make_float2(v2, v3);
            }
        }
    }
}

// ================= tensor-core flash attention (causal, split-bf16) =================
// Br=128 rows per CTA, Bc=64 cols per iter, dh=64. 8 warps x 16 rows.
// Inputs are PRE-SPLIT bf16 hi/lo (from the QKV GEMM epilogue).
#define AT_STRB 144            // smem row stride bytes (72 bf16)
#define AT_K_HI 0
#define AT_K_LO 9216
#define AT_V_HI 18432
#define AT_V_LO 27648
#define AT_SMEM 36864          // Q staging reuses region: hi@0, lo@18432

struct KVPre { uint4 kh[2], kl[2]; uint2 vh[4], vl[4]; };

__device__ __forceinline__ void at_prefetch(
        const __nv_bfloat16* __restrict__ khg, const __nv_bfloat16* __restrict__ klg,
        const __nv_bfloat16* __restrict__ vhg, const __nv_bfloat16* __restrict__ vlg,
        int kc, int tid, KVPre& p) {
    const int rgv = tid >> 4, cgv = tid & 15;
#pragma unroll
    for (int i = 0; i < 2; i++) {
        int idx = tid + (i << 8);
        int row = idx >> 3, c16 = idx & 7;
        size_t o = (size_t)(kc * 64 + row) * 3072 + (c16 << 3);
        p.kh[i] = *(const uint4*)(khg + o);
        p.kl[i] = *(const uint4*)(klg + o);
    }
#pragma unroll
    for (int i = 0; i < 4; i++) {
        size_t o = (size_t)(kc * 64 + 4 * rgv + i) * 3072 + (cgv << 2);
        p.vh[i] = *(const uint2*)(vhg + o);
        p.vl[i] = *(const uint2*)(vlg + o);
    }
}

__global__ __launch_bounds__(256)
void attn_mma_kernel(const __nv_bfloat16* __restrict__ qkvh,
                     const __nv_bfloat16* __restrict__ qkvl,
                     __nv_bfloat16* __restrict__ ohi,
                     __nv_bfloat16* __restrict__ olo) {
    extern __shared__ char smc[];
    const uint32_t sb = smem_u32(smc);
    const int b = blockIdx.y >> 4, h = blockIdx.y & 15;
    const int it = (int)gridDim.x - 1 - (int)blockIdx.x;    // heavy tiles first
    const int r0 = it * 128;
    const int tid = threadIdx.x, w = tid >> 5, lane = tid & 31;

    const size_t base = (size_t)b * SEQc * 3072 + (size_t)(h * 64);
    const __nv_bfloat16* qhg = qkvh + base;
    const __nv_bfloat16* qlg = qkvl + base;
    const __nv_bfloat16* khg = qkvh + base + 1024;
    const __nv_bfloat16* klg = qkvl + base + 1024;
    const __nv_bfloat16* vhg = qkvh + base + 2048;
    const __nv_bfloat16* vlg = qkvl + base + 2048;

    // ---- stage Q (128x64 bf16 hi/lo) into smem: pure copies ----
#pragma unroll
    for (int i = 0; i < 4; i++) {
        int idx = tid + (i << 8);          // 0..1023
        int row = idx >> 3, c16 = idx & 7;
        size_t o = (size_t)(r0 + row) * 3072 + (c16 << 3);
        uint32_t off = (uint32_t)(row * AT_STRB + (c16 << 4));
        *(uint4*)(smc + off)         = *(const uint4*)(qhg + o);
        *(uint4*)(smc + 18432 + off) = *(const uint4*)(qlg + o);
    }
    __syncthreads();

    // Q fragments (register-resident for the whole row tile)
    uint32_t qh[4][4], ql[4][4];
    {
        uint32_t qa = sb + (uint32_t)((w * 16 + (lane & 15)) * AT_STRB) + (uint32_t)(((lane >> 4) << 4));
#pragma unroll
        for (int kt = 0; kt < 4; kt++) {
            LDSM_X4(qh[kt][0], qh[kt][1], qh[kt][2], qh[kt][3], qa + kt * 32);
            LDSM_X4(ql[kt][0], ql[kt][1], ql[kt][2], ql[kt][3], qa + 18432 + kt * 32);
        }
    }

    float acc[8][4];
#pragma unroll
    for (int nt = 0; nt < 8; nt++)
#pragma unroll
        for (int r = 0; r < 4; r++) acc[nt][r] = 0.f;
    float m0 = -1e30f, m1 = -1e30f, l0 = 0.f, l1 = 0.f;

    const int row0 = r0 + w * 16 + (lane >> 2);
    const int row1 = row0 + 8;
    const int ktiles = 2 * it + 2;
    const int diag0 = 2 * it;
    const uint32_t brow = (uint32_t)(((lane >> 4) << 3) + (lane & 7));
    const uint32_t bko  = (uint32_t)(((lane >> 3) & 1) << 4);
    const int rgv = tid >> 4, cgv = tid & 15;

    KVPre pre;
    at_prefetch(khg, klg, vhg, vlg, 0, tid, pre);

    for (int kc = 0; kc < ktiles; kc++) {
        __syncthreads();          // previous tile consumed (or Q frags loaded)

        // ---- store prefetched K (K-major) hi/lo: straight copies ----
#pragma unroll
        for (int i = 0; i < 2; i++) {
            int idx = tid + (i << 8);
            int row = idx >> 3, c16 = idx & 7;
            uint32_t off = (uint32_t)(row * AT_STRB + (c16 << 4));
            *(uint4*)(smc + AT_K_HI + off) = pre.kh[i];
            *(uint4*)(smc + AT_K_LO + off) = pre.kl[i];
        }
        // ---- store prefetched V transposed: PRMT 4x4 bf16 transpose ----
        {
            uint32_t inh[4][2] = {{pre.vh[0].x, pre.vh[0].y}, {pre.vh[1].x, pre.vh[1].y},
                                  {pre.vh[2].x, pre.vh[2].y}, {pre.vh[3].x, pre.vh[3].y}};
            uint32_t inl[4][2] = {{pre.vl[0].x, pre.vl[0].y}, {pre.vl[1].x, pre.vl[1].y},
                                  {pre.vl[2].x, pre.vl[2].y}, {pre.vl[3].x, pre.vl[3].y}};
#pragma unroll
            for (int dd = 0; dd < 4; dd++) {
                int col = (cgv << 2) + dd;
                int q = dd >> 1;
                uint32_t sel = (dd & 1) ? 0x7632u : 0x5410u;
                uint32_t h01, h23, l01, l23;
                PRMT(h01, inh[0][q], inh[1][q], sel);
                PRMT(h23, inh[2][q], inh[3][q], sel);
                PRMT(l01, inl[0][q], inl[1][q], sel);
                PRMT(l23, inl[2][q], inl[3][q], sel);
                uint32_t sw = (uint32_t)(((col >> 3) & 3) << 4);
                uint32_t byte = (uint32_t)(col * AT_STRB) + (((uint32_t)(rgv << 3)) ^ sw);
                *(uint2*)(smc + AT_V_HI + byte) = make_uint2(h01, h23);
                *(uint2*)(smc + AT_V_LO + byte) = make_uint2(l01, l23);
            }
        }
        __syncthreads();

        // prefetch next tile's gmem data (overlaps with MMAs below)
        if (kc + 1 < ktiles) at_prefetch(khg, klg, vhg, vlg, kc + 1, tid, pre);

        // ---- S = Q K^T (split, 3 terms) ----
        float s[8][4];
#pragma unroll
        for (int nt = 0; nt < 8; nt++)
#pragma unroll
            for (int r = 0; r < 4; r++) s[nt][r] = 0.f;
#pragma unroll
        for (int kt = 0; kt < 4; kt++) {
            uint32_t bh[8][2], bl[8][2];
#pragma unroll
            for (int p = 0; p < 4; p++) {
                uint32_t bd = sb + AT_K_HI + (p * 16 + brow) * AT_STRB + kt * 32 + bko;
                LDSM_X4(bh[2*p][0], bh[2*p][1], bh[2*p+1][0], bh[2*p+1][1], bd);
                LDSM_X4(bl[2*p][0], bl[2*p][1], bl[2*p+1][0], bl[2*p+1][1], bd + 9216);
            }
#pragma unroll
            for (int nt = 0; nt < 8; nt++) {
                MMA_BF16(s[nt], qh[kt], bh[nt]);
                MMA_BF16(s[nt], qh[kt], bl[nt]);
                MMA_BF16(s[nt], ql[kt], bh[nt]);
            }
        }
#pragma unroll
        for (int nt = 0; nt < 8; nt++)
#pragma unroll
            for (int r = 0; r < 4; r++) s[nt][r] *= 0.125f;

        // ---- causal mask (diagonal tiles only) ----
        if (kc >= diag0) {
            int colb = kc * 64 + ((lane & 3) << 1);
#pragma unroll
            for (int nt = 0; nt < 8; nt++) {
                int c0 = colb + nt * 8;
                if (c0     > row0) s[nt][0] = -1e30f;
                if (c0 + 1 > row0) s[nt][1] = -1e30f;
                if (c0     > row1) s[nt][2] = -1e30f;
                if (c0 + 1 > row1) s[nt][3] = -1e30f;
            }
        }

        // ---- online softmax (rows r and r+8; 4-lane group reductions) ----
        float mx0 = -1e30f, mx1 = -1e30f;
#pragma unroll
        for (int nt = 0; nt < 8; nt++) {
            mx0 = fmaxf(mx0, fmaxf(s[nt][0], s[nt][1]));
            mx1 = fmaxf(mx1, fmaxf(s[nt][2], s[nt][3]));
        }
        mx0 = fmaxf(mx0, __shfl_xor_sync(0xffffffffu, mx0, 1));
        mx0 = fmaxf(mx0, __shfl_xor_sync(0xffffffffu, mx0, 2));
        mx1 = fmaxf(mx1, __shfl_xor_sync(0xffffffffu, mx1, 1));
        mx1 = fmaxf(mx1, __shfl_xor_sync(0xffffffffu, mx1, 2));
        float nm0 = fmaxf(m0, mx0), nm1 = fmaxf(m1, mx1);
        float sum0 = 0.f, sum1 = 0.f;
#pragma unroll
        for (int nt = 0; nt < 8; nt++) {
            s[nt][0] = __expf(s[nt][0] - nm0); sum0 += s[nt][0];
            s[nt][1] = __expf(s[nt][1] - nm0); sum0 += s[nt][1];
            s[nt][2] = __expf(s[nt][2] - nm1); sum1 += s[nt][2];
            s[nt][3] = __expf(s[nt][3] - nm1); sum1 += s[nt][3];
        }
        sum0 += __shfl_xor_sync(0xffffffffu, sum0, 1);
        sum0 += __shfl_xor_sync(0xffffffffu, sum0, 2);
        sum1 += __shfl_xor_sync(0xffffffffu, sum1, 1);
        sum1 += __shfl_xor_sync(0xffffffffu, sum1, 2);
        float a0 = __expf(m0 - nm0), a1 = __expf(m1 - nm1);
        m0 = nm0; m1 = nm1;
        l0 = l0 * a0 + sum0; l1 = l1 * a1 + sum1;
#pragma unroll
        for (int nt = 0; nt < 8; nt++) {
            acc[nt][0] *= a0; acc[nt][1] *= a0;
            acc[nt][2] *= a1; acc[nt][3] *= a1;
        }

        // ---- repack S accumulator fragments into P A-fragments (hi/lo) ----
        uint32_t ph[4][4], pl[4][4];
#pragma unroll
        for (int kt = 0; kt < 4; kt++) {
            int e = 2 * kt, o = 2 * kt + 1;
            split2(s[e][0], s[e][1], ph[kt][0], pl[kt][0]);
            split2(s[e][2], s[e][3], ph[kt][1], pl[kt][1]);
            split2(s[o][0], s[o][1], ph[kt][2], pl[kt][2]);
            split2(s[o][2], s[o][3], ph[kt][3], pl[kt][3]);
        }

        // ---- O += P @ V (split, 3 terms; swizzled V reads) ----
#pragma unroll
        for (int kt = 0; kt < 4; kt++) {
            uint32_t vh[8][2], vl[8][2];
#pragma unroll
            for (int p = 0; p < 4; p++) {
                uint32_t dlane = (uint32_t)(p * 16) + brow;
                uint32_t sw = ((dlane >> 3) & 3) << 4;
                uint32_t bd = sb + AT_V_HI + dlane * AT_STRB + ((uint32_t)(kt * 32 + bko) ^ sw);
                LDSM_X4(vh[2*p][0], vh[2*p][1], vh[2*p+1][0], vh[2*p+1][1], bd);
                LDSM_X4(vl[2*p][0], vl[2*p][1], vl[2*p+1][0], vl[2*p+1][1], bd + 9216);
            }
#pragma unroll
            for (int nt = 0; nt < 8; nt++) {
                MMA_BF16(acc[nt], ph[kt], vh[nt]);
                MMA_BF16(acc[nt], ph[kt], vl[nt]);
                MMA_BF16(acc[nt], pl[kt], vh[nt]);
            }
        }
    }

    // ---- epilogue: normalize and write bf16 hi/lo (concat head layout) ----
    float inv0 = 1.f / l0, inv1 = 1.f / l1;
    const int tok0 = b * SEQc + row0;
#pragma unroll
    for (int nt = 0; nt < 8; nt++) {
        int col = h * 64 + nt * 8 + ((lane & 3) << 1);
        uint32_t hi, lo;
        split2(acc[nt][0] * inv0, acc[nt][1] * inv0, hi, lo);
        *(uint32_t*)(ohi + (size_t)tok0 * 1024 + col) = hi;
        *(uint32_t*)(olo + (size_t)tok0 * 1024 + col) = lo;
        split2(acc[nt][2] * inv1, acc[nt][3] * inv1, hi, lo);
        *(uint32_t*)(ohi + (size_t)(tok0 + 8) * 1024 + col) = hi;
        *(uint32_t*)(olo + (size_t)(tok0 + 8) * 1024 + col) = lo;
    }
}

// ---------------- LayerNorm + residual ----------------
template<bool SPLITO>
__global__ void ln_residual_kernel(const float* __restrict__ resid,
                                   const float* __restrict__ v,
                                   const float* __restrict__ g,
                                   const float* __restrict__ beta,
                                   float* __restrict__ out,
                                   __nv_bfloat16* __restrict__ ohi,
                                   __nv_bfloat16* __restrict__ olo) {
    __shared__ float red[16];
    const int row = blockIdx.x;
    const int t = threadIdx.x;
    const float* vr = v + (size_t)row * D_MODELc;
    float4 xv = *(const float4*)(vr + t * 4);
    float s  = xv.x + xv.y + xv.z + xv.w;
    float s2 = xv.x * xv.x + xv.y * xv.y + xv.z * xv.z + xv.w * xv.w;
#pragma unroll
    for (int o = 16; o; o >>= 1) {
        s  += __shfl_xor_sync(0xffffffffu, s,  o);
        s2 += __shfl_xor_sync(0xffffffffu, s2, o);
    }
    int wid = t >> 5;
    if ((t & 31) == 0) { red[wid] = s; red[8 + wid] = s2; }
    __syncthreads();
    float S = 0.f, S2 = 0.f;
#pragma unroll
    for (int i = 0; i < 8; i++) { S += red[i]; S2 += red[8 + i]; }
    float mu   = S * (1.f / D_MODELc);
    float var  = S2 * (1.f / D_MODELc) - mu * mu;
    float rstd = rsqrtf(var + LN_EPSc);

    int c = t * 4;
    float4 rr = *(const float4*)(resid + (size_t)row * D_MODELc + c);
    float4 gg = *(const float4*)(g + c);
    float4 bb = *(const float4*)(beta + c);
    float4 o;
    o.x = rr.x + (xv.x - mu) * rstd * gg.x + bb.x;
    o.y = rr.y + (xv.y - mu) * rstd * gg.y + bb.y;
    o.z = rr.z + (xv.z - mu) * rstd * gg.z + bb.z;
    o.w = rr.w + (xv.w - mu) * rstd * gg.w + bb.w;
    *(float4*)(out + (size_t)row * D_MODELc + c) = o;
    if (SPLITO) {
        uint32_t h0, l0, h1, l1;
        split2(o.x, o.y, h0, l0);
        split2(o.z, o.w, h1, l1);
        *(uint2*)(ohi + (size_t)row * D_MODELc + c) = make_uint2(h0, h1);
        *(uint2*)(olo + (size_t)row * D_MODELc + c) = make_uint2(l0, l1);
    }
}

// ---------------- launch ----------------
extern "C" void kernel_launch(void* const* d_in, const int* in_sizes, int n_in,
                              void* d_out, int out_size) {
    (void)in_sizes; (void)n_in; (void)out_size;
    const float* x     = (const float*)d_in[0];
    const float* wq    = (const float*)d_in[1];
    const float* wk    = (const float*)d_in[2];
    const float* wv    = (const float*)d_in[3];
    const float* wo    = (const float*)d_in[4];
    const float* w_in  = (const float*)d_in[5];
    const float* b_in  = (const float*)d_in[6];
    const float* w_out = (const float*)d_in[7];
    const float* b_out = (const float*)d_in[8];
    const float* g1    = (const float*)d_in[9];
    const float* bt1   = (const float*)d_in[10];
    const float* g2    = (const float*)d_in[11];
    const float* bt2   = (const float*)d_in[12];
    float* out = (float*)d_out;

    float *proj, *x1, *mlp;
    __nv_bfloat16 *qkvh, *qkvl, *ahi, *alo, *bhi, *blo, *mh, *ml;
    cudaGetSymbolAddress((void**)&proj, g_proj);
    cudaGetSymbolAddress((void**)&x1,   g_x1);
    cudaGetSymbolAddress((void**)&mlp,  g_mlp);
    cudaGetSymbolAddress((void**)&qkvh, g_qkvh);
    cudaGetSymbolAddress((void**)&qkvl, g_qkvl);
    cudaGetSymbolAddress((void**)&ahi,  g_ahi);
    cudaGetSymbolAddress((void**)&alo,  g_alo);
    cudaGetSymbolAddress((void**)&bhi,  g_bhi);
    cudaGetSymbolAddress((void**)&blo,  g_blo);
    cudaGetSymbolAddress((void**)&mh,   g_mlph_hi);
    cudaGetSymbolAddress((void**)&ml,   g_mlph_lo);

    cudaFuncSetAttribute(tc_gemm_kernel<false, false>, cudaFuncAttributeMaxDynamicSharedMemorySize, TG_SMEM);
    cudaFuncSetAttribute(tc_gemm_kernel<false, true>,  cudaFuncAttributeMaxDynamicSharedMemorySize, TG_SMEM);
    cudaFuncSetAttribute(tc_gemm_kernel<true,  true>,  cudaFuncAttributeMaxDynamicSharedMemorySize, TG_SMEM);
    cudaFuncSetAttribute(attn_mma_kernel, cudaFuncAttributeMaxDynamicSharedMemorySize, AT_SMEM);

    dim3 tsb(32, 8);

    // ---- QKV projection: [4096,1024] @ [1024,3072], split bf16 output ----
    qkv_tsplit_kernel<<<dim3(2, 32, 48), tsb>>>(wq, wk, wv, bhi, blo);
    asplit_kernel<<<(NTOK * D_MODELc / 4 + 255) / 256, 256>>>(x, ahi, alo, NTOK * D_MODELc / 4);
    tc_gemm_kernel<false, true><<<dim3(24, 32), 128, TG_SMEM>>>(
        ahi, alo, bhi, blo, nullptr, nullptr, qkvh, qkvl, NTOK, 3072, 1024);

    // ---- tensor-core causal flash attention -> bf16 hi/lo (overwrites ahi/alo) ----
    attn_mma_kernel<<<dim3(SEQc / 128, BATCHc * 16), 256, AT_SMEM>>>(qkvh, qkvl, ahi, alo);

    // ---- output projection: att @ wo ----
    tsplit_kernel<<<dim3(32, 32), tsb>>>(wo, bhi, blo, 1024, 1024);
    tc_gemm_kernel<false, false><<<dim3(8, 32), 128, TG_SMEM>>>(
        ahi, alo, bhi, blo, nullptr, proj, nullptr, nullptr, NTOK, 1024, 1024);

    // ---- x1 = x + LN(proj), fused split into ahi/alo ----
    ln_residual_kernel<true><<<NTOK, 256>>>(x, proj, g1, bt1, x1, ahi, alo);

    // ---- MLP in: relu(x1 @ w_in + b_in), fused split output ----
    tsplit_kernel<<<dim3(128, 32), tsb>>>(w_in, bhi, blo, 1024, 4096);
    tc_gemm_kernel<true, true><<<dim3(32, 32), 128, TG_SMEM>>>(
        ahi, alo, bhi, blo, b_in, nullptr, mh, ml, NTOK, 4096, 1024);

    // ---- MLP out: mlph @ w_out + b_out ----
    tsplit_kernel<<<dim3(32, 128), tsb>>>(w_out, bhi, blo, 4096, 1024);
    tc_gemm_kernel<false, false><<<dim3(8, 32), 128, TG_SMEM>>>(
        mh, ml, bhi, blo, b_out, mlp, nullptr, nullptr, NTOK, 1024, 4096);

    // ---- out = x1 + LN(mlp) ----
    ln_residual_kernel<false><<<NTOK, 256>>>(x1, mlp, g2, bt2, out, nullptr, nullptr);
}

// round 11
// speedup vs baseline: 2.7042x; 1.0279x over previous
#include <cuda_runtime.h>
#include <cuda_bf16.h>
#include <cstdint>
#include <math.h>

// ---------------- problem constants ----------------
#define D_MODELc 1024
#define SEQc     2048
#define BATCHc   2
#define NTOK     (BATCHc*SEQc)     // 4096 tokens
#define D_MLPc   4096
#define LN_EPSc  1e-5f

// ---------------- device scratch (no runtime allocation allowed) ----------------
__device__ float g_proj[(size_t)NTOK * D_MODELc];               // head_out @ wo
__device__ float g_x1  [(size_t)NTOK * D_MODELc];               // x + LN1(proj)
__device__ float g_mlp [(size_t)NTOK * D_MODELc];               // mlp output
__device__ __nv_bfloat16 g_qkvh[(size_t)NTOK * 3 * D_MODELc];   // qkv split hi
__device__ __nv_bfloat16 g_qkvl[(size_t)NTOK * 3 * D_MODELc];   // qkv split lo
__device__ __nv_bfloat16 g_mlph_hi[(size_t)NTOK * D_MLPc];      // relu(x1@w_in+b_in) split
__device__ __nv_bfloat16 g_mlph_lo[(size_t)NTOK * D_MLPc];
__device__ __nv_bfloat16 g_ahi[(size_t)NTOK * D_MODELc];        // activation split (reused)
__device__ __nv_bfloat16 g_alo[(size_t)NTOK * D_MODELc];
__device__ __nv_bfloat16 g_bhi[(size_t)D_MLPc * D_MODELc];      // weight split (reused)
__device__ __nv_bfloat16 g_blo[(size_t)D_MLPc * D_MODELc];

// ================= PTX helpers (baseline sm_80+ features only) =================
__device__ __forceinline__ uint32_t smem_u32(const void* p) {
    uint32_t a;
    asm("{ .reg .u64 t; cvta.to.shared.u64 t, %1; cvt.u32.u64 %0, t; }" : "=r"(a) : "l"(p));
    return a;
}
#define CP_ASYNC16(dst, src) \
    asm volatile("cp.async.cg.shared.global [%0], [%1], 16;" :: "r"(dst), "l"(src))
#define CP_COMMIT()  asm volatile("cp.async.commit_group;" ::: "memory")
#define CP_WAIT0()   asm volatile("cp.async.wait_group 0;" ::: "memory")
#define LDSM_X4(r0, r1, r2, r3, addr) \
    asm volatile("ldmatrix.sync.aligned.m8n8.x4.shared.b16 {%0,%1,%2,%3}, [%4];" \
        : "=r"(r0), "=r"(r1), "=r"(r2), "=r"(r3) : "r"(addr))
#define MMA_BF16(d, a, b) \
    asm volatile("mma.sync.aligned.m16n8k16.row.col.f32.bf16.bf16.f32 " \
        "{%0,%1,%2,%3},{%4,%5,%6,%7},{%8,%9},{%0,%1,%2,%3};" \
        : "+f"((d)[0]), "+f"((d)[1]), "+f"((d)[2]), "+f"((d)[3]) \
        : "r"((a)[0]), "r"((a)[1]), "r"((a)[2]), "r"((a)[3]), "r"((b)[0]), "r"((b)[1]))
#define PRMT(d, a, b, sel) \
    asm("prmt.b32 %0, %1, %2, %3;" : "=r"(d) : "r"(a), "r"(b), "r"(sel))

// split two fp32 into packed bf16 hi pair + lo (residual) pair
__device__ __forceinline__ void split2(float a, float b, uint32_t& hi, uint32_t& lo) {
    __nv_bfloat16 ha = __float2bfloat16(a), hb = __float2bfloat16(b);
    __nv_bfloat16 la = __float2bfloat16(a - __bfloat162float(ha));
    __nv_bfloat16 lb = __float2bfloat16(b - __bfloat162float(hb));
    __nv_bfloat162 H(ha, hb), L(la, lb);
    hi = *(uint32_t*)&H; lo = *(uint32_t*)&L;
}

// ================= split / transpose kernels =================
__global__ void asplit_kernel(const float* __restrict__ src,
                              __nv_bfloat16* __restrict__ dhi,
                              __nv_bfloat16* __restrict__ dlo, int n4) {
    int i = blockIdx.x * blockDim.x + threadIdx.x;
    if (i >= n4) return;
    float4 v = ((const float4*)src)[i];
    uint32_t h0, l0, h1, l1;
    split2(v.x, v.y, h0, l0);
    split2(v.z, v.w, h1, l1);
    ((uint2*)dhi)[i] = make_uint2(h0, h1);
    ((uint2*)dlo)[i] = make_uint2(l0, l1);
}

// tiled transpose+split: src [R][C] fp32 -> dst [C][R] bf16 hi/lo (vectorized stores)
__global__ void tsplit_kernel(const float* __restrict__ src,
                              __nv_bfloat16* __restrict__ dhi,
                              __nv_bfloat16* __restrict__ dlo, int R, int C) {
    __shared__ float t[32][33];
    int c0 = blockIdx.x * 32, r0 = blockIdx.y * 32;
    int tx = threadIdx.x, ty = threadIdx.y;   // (32, 8)
#pragma unroll
    for (int i = 0; i < 4; i++)
        t[ty + i*8][tx] = src[(size_t)(r0 + ty + i*8) * C + c0 + tx];
    __syncthreads();
    int tid = ty * 32 + tx;
    int sy = tid >> 3;        // 0..31 -> c
    int sx = tid & 7;         // 0..7  -> r group of 4
    float v0 = t[sx*4+0][sy], v1 = t[sx*4+1][sy];
    float v2 = t[sx*4+2][sy], v3 = t[sx*4+3][sy];
    uint32_t h0, l0, h1, l1;
    split2(v0, v1, h0, l0);
    split2(v2, v3, h1, l1);
    size_t o = (size_t)(c0 + sy) * R + r0 + sx * 4;
    *(uint2*)(dhi + o) = make_uint2(h0, h1);
    *(uint2*)(dlo + o) = make_uint2(l0, l1);
}

// wq/wk/wv [16][1024][64] -> Wt [3072][1024] bf16 hi/lo
__global__ void qkv_tsplit_kernel(const float* __restrict__ wq, const float* __restrict__ wk,
                                  const float* __restrict__ wv,
                                  __nv_bfloat16* __restrict__ dhi,
                                  __nv_bfloat16* __restrict__ dlo) {
    __shared__ float t[32][33];
    int z = blockIdx.z, p = z >> 4, h = z & 15;
    const float* src = (p == 0 ? wq : (p == 1 ? wk : wv)) + (size_t)h * 1024 * 64;
    int c0 = blockIdx.x * 32, r0 = blockIdx.y * 32;
    int tx = threadIdx.x, ty = threadIdx.y;
#pragma unroll
    for (int i = 0; i < 4; i++)
        t[ty + i*8][tx] = src[(size_t)(r0 + ty + i*8) * 64 + c0 + tx];
    __syncthreads();
    int nbase = (p << 10) + (h << 6);
    int tid = ty * 32 + tx;
    int sy = tid >> 3;
    int sx = tid & 7;
    float v0 = t[sx*4+0][sy], v1 = t[sx*4+1][sy];
    float v2 = t[sx*4+2][sy], v3 = t[sx*4+3][sy];
    uint32_t h0, l0, h1, l1;
    split2(v0, v1, h0, l0);
    split2(v2, v3, h1, l1);
    size_t o = (size_t)(nbase + c0 + sy) * 1024 + r0 + sx * 4;
    *(uint2*)(dhi + o) = make_uint2(h0, h1);
    *(uint2*)(dlo + o) = make_uint2(l0, l1);
}

// ================= HMMA split-bf16 GEMM (mma.sync m16n8k16) =================
// 128x128 CTA tile, 4 warps (64x64 each), BK=32, 2-stage cp.async, 2 CTAs/SM.
// Term-major MMA issue: all hh, then hl, then lh -> 32 independent MMAs
// between accumulator reuses (covers HMMA RAW latency). Per-accumulator
// contribution order is unchanged (hh->hl->lh per k-step): bit-identical.
#define TG_STRB  80
#define TG_MAT   10240      // 128*80
#define TG_STAGE 40960
#define TG_SMEM  81920      // 2 stages

__device__ __forceinline__ void tg_load(
        const __nv_bfloat16* __restrict__ Ah, const __nv_bfloat16* __restrict__ Al,
        const __nv_bfloat16* __restrict__ Bh, const __nv_bfloat16* __restrict__ Bl,
        int K, int k0, uint32_t sbase, int tid) {
#pragma unroll
    for (int j = 0; j < 4; j++) {
        int idx = tid + (j << 7);      // 128 threads, 512 chunks per matrix
        int row = idx >> 2, kc = idx & 3;
        uint32_t d = sbase + row * TG_STRB + (kc << 4);
        const size_t go = (size_t)row * K + k0 + (kc << 3);
        CP_ASYNC16(d,              Ah + go);
        CP_ASYNC16(d +     TG_MAT, Al + go);
        CP_ASYNC16(d + 2 * TG_MAT, Bh + go);
        CP_ASYNC16(d + 3 * TG_MAT, Bl + go);
    }
}

template<bool RELU, bool SPLITO>
__global__ __launch_bounds__(128, 2)
void tc_gemm_kernel(const __nv_bfloat16* __restrict__ Ahi, const __nv_bfloat16* __restrict__ Alo,
                    const __nv_bfloat16* __restrict__ Bhi, const __nv_bfloat16* __restrict__ Blo,
                    const float* __restrict__ bias, float* __restrict__ C,
                    __nv_bfloat16* __restrict__ Chi, __nv_bfloat16* __restrict__ Clo,
                    int M, int N, int K) {
    extern __shared__ char smem[];
    const uint32_t sb = smem_u32(smem);
    const int tid = threadIdx.x, wid = tid >> 5, lane = tid & 31;
    const int wm = wid >> 1, wn = wid & 1;           // warp grid 2(m) x 2(n), 64x64 each
    const int m0 = blockIdx.y * 128, n0 = blockIdx.x * 128;

    const __nv_bfloat16* pAh = Ahi + (size_t)m0 * K;
    const __nv_bfloat16* pAl = Alo + (size_t)m0 * K;
    const __nv_bfloat16* pBh = Bhi + (size_t)n0 * K;
    const __nv_bfloat16* pBl = Blo + (size_t)n0 * K;

    float acc[4][8][4];
#pragma unroll
    for (int i = 0; i < 4; i++)
#pragma unroll
        for (int j = 0; j < 8; j++)
#pragma unroll
            for (int r = 0; r < 4; r++) acc[i][j][r] = 0.f;

    const int nchunk = K >> 5;
    tg_load(pAh, pAl, pBh, pBl, K, 0, sb, tid);
    CP_COMMIT();

    const uint32_t a_row  = (uint32_t)(wm * 64 + (lane & 15));
    const uint32_t a_koff = (uint32_t)((lane >> 4) << 4);
    const uint32_t b_rowl = (uint32_t)(((lane >> 4) << 3) + (lane & 7));
    const uint32_t b_koff = (uint32_t)(((lane >> 3) & 1) << 4);

    for (int c = 0; c < nchunk; c++) {
        CP_WAIT0();
        __syncthreads();
        if (c + 1 < nchunk) {
            tg_load(pAh, pAl, pBh, pBl, K, (c + 1) << 5,
                    sb + (uint32_t)((c + 1) & 1) * TG_STAGE, tid);
            CP_COMMIT();
        }

        const uint32_t st = sb + (uint32_t)(c & 1) * TG_STAGE;
#pragma unroll
        for (int ks = 0; ks < 2; ks++) {
            uint32_t ah[4][4], al[4][4], bh[8][2], bl[8][2];
#pragma unroll
            for (int mt = 0; mt < 4; mt++) {
                uint32_t ad = st + (a_row + mt * 16) * TG_STRB + ks * 32 + a_koff;
                LDSM_X4(ah[mt][0], ah[mt][1], ah[mt][2], ah[mt][3], ad);
                LDSM_X4(al[mt][0], al[mt][1], al[mt][2], al[mt][3], ad + TG_MAT);
            }
#pragma unroll
            for (int p = 0; p < 4; p++) {
                uint32_t bd = st + 2 * TG_MAT +
                              (wn * 64 + p * 16 + b_rowl) * TG_STRB + ks * 32 + b_koff;
                LDSM_X4(bh[2*p][0], bh[2*p][1], bh[2*p+1][0], bh[2*p+1][1], bd);
                LDSM_X4(bl[2*p][0], bl[2*p][1], bl[2*p+1][0], bl[2*p+1][1], bd + TG_MAT);
            }
            // term-major: 32 independent MMAs between accumulator reuses
#pragma unroll
            for (int mt = 0; mt < 4; mt++)
#pragma unroll
                for (int nt = 0; nt < 8; nt++) MMA_BF16(acc[mt][nt], ah[mt], bh[nt]);
#pragma unroll
            for (int mt = 0; mt < 4; mt++)
#pragma unroll
                for (int nt = 0; nt < 8; nt++) MMA_BF16(acc[mt][nt], ah[mt], bl[nt]);
#pragma unroll
            for (int mt = 0; mt < 4; mt++)
#pragma unroll
                for (int nt = 0; nt < 8; nt++) MMA_BF16(acc[mt][nt], al[mt], bh[nt]);
        }
    }

#pragma unroll
    for (int mt = 0; mt < 4; mt++) {
        const int r0 = m0 + wm * 64 + mt * 16 + (lane >> 2);
#pragma unroll
        for (int nt = 0; nt < 8; nt++) {
            const int c0 = n0 + wn * 64 + nt * 8 + ((lane & 3) << 1);
            float bx = bias ? bias[c0]     : 0.f;
            float by = bias ? bias[c0 + 1] : 0.f;
            float v0 = acc[mt][nt][0] + bx, v1 = acc[mt][nt][1] + by;
            float v2 = acc[mt][nt][2] + bx, v3 = acc[mt][nt][3] + by;
            if (RELU) {
                v0 = fmaxf(v0, 0.f); v1 = fmaxf(v1, 0.f);
                v2 = fmaxf(v2, 0.f); v3 = fmaxf(v3, 0.f);
            }
            if (SPLITO) {
                uint32_t hi, lo;
                split2(v0, v1, hi, lo);
                *(uint32_t*)(Chi + (size_t)r0 * N + c0) = hi;
                *(uint32_t*)(Clo + (size_t)r0 * N + c0) = lo;
                split2(v2, v3, hi, lo);
                *(uint32_t*)(Chi + (size_t)(r0 + 8) * N + c0) = hi;
                *(uint32_t*)(Clo + (size_t)(r0 + 8) * N + c0) = lo;
            } else {
                *(float2*)(C + (size_t)r0 * N + c0)       = make_float2(v0, v1);
                *(float2*)(C + (size_t)(r0 + 8) * N + c0) = make_float2(v2, v3);
            }
        }
    }
}

// ================= tensor-core flash attention (causal, split-bf16) =================
// Br=128 rows per CTA, Bc=64 cols per iter, dh=64. 8 warps x 16 rows.
// Inputs are PRE-SPLIT bf16 hi/lo. Term-major MMA issue (8 independent MMAs
// between accumulator reuses); per-accumulator order unchanged -> bit-identical.
#define AT_STRB 144            // smem row stride bytes (72 bf16)
#define AT_K_HI 0
#define AT_K_LO 9216
#define AT_V_HI 18432
#define AT_V_LO 27648
#define AT_SMEM 36864          // Q staging reuses region: hi@0, lo@18432

struct KVPre { uint4 kh[2], kl[2]; uint2 vh[4], vl[4]; };

__device__ __forceinline__ void at_prefetch(
        const __nv_bfloat16* __restrict__ khg, const __nv_bfloat16* __restrict__ klg,
        const __nv_bfloat16* __restrict__ vhg, const __nv_bfloat16* __restrict__ vlg,
        int kc, int tid, KVPre& p) {
    const int rgv = tid >> 4, cgv = tid & 15;
#pragma unroll
    for (int i = 0; i < 2; i++) {
        int idx = tid + (i << 8);
        int row = idx >> 3, c16 = idx & 7;
        size_t o = (size_t)(kc * 64 + row) * 3072 + (c16 << 3);
        p.kh[i] = *(const uint4*)(khg + o);
        p.kl[i] = *(const uint4*)(klg + o);
    }
#pragma unroll
    for (int i = 0; i < 4; i++) {
        size_t o = (size_t)(kc * 64 + 4 * rgv + i) * 3072 + (cgv << 2);
        p.vh[i] = *(const uint2*)(vhg + o);
        p.vl[i] = *(const uint2*)(vlg + o);
    }
}

__global__ __launch_bounds__(256)
void attn_mma_kernel(const __nv_bfloat16* __restrict__ qkvh,
                     const __nv_bfloat16* __restrict__ qkvl,
                     __nv_bfloat16* __restrict__ ohi,
                     __nv_bfloat16* __restrict__ olo) {
    extern __shared__ char smc[];
    const uint32_t sb = smem_u32(smc);
    const int b = blockIdx.y >> 4, h = blockIdx.y & 15;
    const int it = (int)gridDim.x - 1 - (int)blockIdx.x;    // heavy tiles first
    const int r0 = it * 128;
    const int tid = threadIdx.x, w = tid >> 5, lane = tid & 31;

    const size_t base = (size_t)b * SEQc * 3072 + (size_t)(h * 64);
    const __nv_bfloat16* qhg = qkvh + base;
    const __nv_bfloat16* qlg = qkvl + base;
    const __nv_bfloat16* khg = qkvh + base + 1024;
    const __nv_bfloat16* klg = qkvl + base + 1024;
    const __nv_bfloat16* vhg = qkvh + base + 2048;
    const __nv_bfloat16* vlg = qkvl + base + 2048;

    // ---- stage Q (128x64 bf16 hi/lo) into smem: pure copies ----
#pragma unroll
    for (int i = 0; i < 4; i++) {
        int idx = tid + (i << 8);          // 0..1023
        int row = idx >> 3, c16 = idx & 7;
        size_t o = (size_t)(r0 + row) * 3072 + (c16 << 3);
        uint32_t off = (uint32_t)(row * AT_STRB + (c16 << 4));
        *(uint4*)(smc + off)         = *(const uint4*)(qhg + o);
        *(uint4*)(smc + 18432 + off) = *(const uint4*)(qlg + o);
    }
    __syncthreads();

    // Q fragments (register-resident for the whole row tile)
    uint32_t qh[4][4], ql[4][4];
    {
        uint32_t qa = sb + (uint32_t)((w * 16 + (lane & 15)) * AT_STRB) + (uint32_t)(((lane >> 4) << 4));
#pragma unroll
        for (int kt = 0; kt < 4; kt++) {
            LDSM_X4(qh[kt][0], qh[kt][1], qh[kt][2], qh[kt][3], qa + kt * 32);
            LDSM_X4(ql[kt][0], ql[kt][1], ql[kt][2], ql[kt][3], qa + 18432 + kt * 32);
        }
    }

    float acc[8][4];
#pragma unroll
    for (int nt = 0; nt < 8; nt++)
#pragma unroll
        for (int r = 0; r < 4; r++) acc[nt][r] = 0.f;
    float m0 = -1e30f, m1 = -1e30f, l0 = 0.f, l1 = 0.f;

    const int row0 = r0 + w * 16 + (lane >> 2);
    const int row1 = row0 + 8;
    const int ktiles = 2 * it + 2;
    const int diag0 = 2 * it;
    const uint32_t brow = (uint32_t)(((lane >> 4) << 3) + (lane & 7));
    const uint32_t bko  = (uint32_t)(((lane >> 3) & 1) << 4);
    const int rgv = tid >> 4, cgv = tid & 15;

    KVPre pre;
    at_prefetch(khg, klg, vhg, vlg, 0, tid, pre);

    for (int kc = 0; kc < ktiles; kc++) {
        __syncthreads();          // previous tile consumed (or Q frags loaded)

        // ---- store prefetched K (K-major) hi/lo: straight copies ----
#pragma unroll
        for (int i = 0; i < 2; i++) {
            int idx = tid + (i << 8);
            int row = idx >> 3, c16 = idx & 7;
            uint32_t off = (uint32_t)(row * AT_STRB + (c16 << 4));
            *(uint4*)(smc + AT_K_HI + off) = pre.kh[i];
            *(uint4*)(smc + AT_K_LO + off) = pre.kl[i];
        }
        // ---- store prefetched V transposed: PRMT 4x4 bf16 transpose ----
        {
            uint32_t inh[4][2] = {{pre.vh[0].x, pre.vh[0].y}, {pre.vh[1].x, pre.vh[1].y},
                                  {pre.vh[2].x, pre.vh[2].y}, {pre.vh[3].x, pre.vh[3].y}};
            uint32_t inl[4][2] = {{pre.vl[0].x, pre.vl[0].y}, {pre.vl[1].x, pre.vl[1].y},
                                  {pre.vl[2].x, pre.vl[2].y}, {pre.vl[3].x, pre.vl[3].y}};
#pragma unroll
            for (int dd = 0; dd < 4; dd++) {
                int col = (cgv << 2) + dd;
                int q = dd >> 1;
                uint32_t sel = (dd & 1) ? 0x7632u : 0x5410u;
                uint32_t h01, h23, l01, l23;
                PRMT(h01, inh[0][q], inh[1][q], sel);
                PRMT(h23, inh[2][q], inh[3][q], sel);
                PRMT(l01, inl[0][q], inl[1][q], sel);
                PRMT(l23, inl[2][q], inl[3][q], sel);
                uint32_t sw = (uint32_t)(((col >> 3) & 3) << 4);
                uint32_t byte = (uint32_t)(col * AT_STRB) + (((uint32_t)(rgv << 3)) ^ sw);
                *(uint2*)(smc + AT_V_HI + byte) = make_uint2(h01, h23);
                *(uint2*)(smc + AT_V_LO + byte) = make_uint2(l01, l23);
            }
        }
        __syncthreads();

        // prefetch next tile's gmem data (overlaps with MMAs below)
        if (kc + 1 < ktiles) at_prefetch(khg, klg, vhg, vlg, kc + 1, tid, pre);

        // ---- S = Q K^T (split, 3 terms, term-major issue) ----
        float s[8][4];
#pragma unroll
        for (int nt = 0; nt < 8; nt++)
#pragma unroll
            for (int r = 0; r < 4; r++) s[nt][r] = 0.f;
#pragma unroll
        for (int kt = 0; kt < 4; kt++) {
            uint32_t bh[8][2], bl[8][2];
#pragma unroll
            for (int p = 0; p < 4; p++) {
                uint32_t bd = sb + AT_K_HI + (p * 16 + brow) * AT_STRB + kt * 32 + bko;
                LDSM_X4(bh[2*p][0], bh[2*p][1], bh[2*p+1][0], bh[2*p+1][1], bd);
                LDSM_X4(bl[2*p][0], bl[2*p][1], bl[2*p+1][0], bl[2*p+1][1], bd + 9216);
            }
#pragma unroll
            for (int nt = 0; nt < 8; nt++) MMA_BF16(s[nt], qh[kt], bh[nt]);
#pragma unroll
            for (int nt = 0; nt < 8; nt++) MMA_BF16(s[nt], qh[kt], bl[nt]);
#pragma unroll
            for (int nt = 0; nt < 8; nt++) MMA_BF16(s[nt], ql[kt], bh[nt]);
        }
#pragma unroll
        for (int nt = 0; nt < 8; nt++)
#pragma unroll
            for (int r = 0; r < 4; r++) s[nt][r] *= 0.125f;

        // ---- causal mask (diagonal tiles only) ----
        if (kc >= diag0) {
            int colb = kc * 64 + ((lane & 3) << 1);
#pragma unroll
            for (int nt = 0; nt < 8; nt++) {
                int c0 = colb + nt * 8;
                if (c0     > row0) s[nt][0] = -1e30f;
                if (c0 + 1 > row0) s[nt][1] = -1e30f;
                if (c0     > row1) s[nt][2] = -1e30f;
                if (c0 + 1 > row1) s[nt][3] = -1e30f;
            }
        }

        // ---- online softmax (rows r and r+8; 4-lane group reductions) ----
        float mx0 = -1e30f, mx1 = -1e30f;
#pragma unroll
        for (int nt = 0; nt < 8; nt++) {
            mx0 = fmaxf(mx0, fmaxf(s[nt][0], s[nt][1]));
            mx1 = fmaxf(mx1, fmaxf(s[nt][2], s[nt][3]));
        }
        mx0 = fmaxf(mx0, __shfl_xor_sync(0xffffffffu, mx0, 1));
        mx0 = fmaxf(mx0, __shfl_xor_sync(0xffffffffu, mx0, 2));
        mx1 = fmaxf(mx1, __shfl_xor_sync(0xffffffffu, mx1, 1));
        mx1 = fmaxf(mx1, __shfl_xor_sync(0xffffffffu, mx1, 2));
        float nm0 = fmaxf(m0, mx0), nm1 = fmaxf(m1, mx1);
        float sum0 = 0.f, sum1 = 0.f;
#pragma unroll
        for (int nt = 0; nt < 8; nt++) {
            s[nt][0] = __expf(s[nt][0] - nm0); sum0 += s[nt][0];
            s[nt][1] = __expf(s[nt][1] - nm0); sum0 += s[nt][1];
            s[nt][2] = __expf(s[nt][2] - nm1); sum1 += s[nt][2];
            s[nt][3] = __expf(s[nt][3] - nm1); sum1 += s[nt][3];
        }
        sum0 += __shfl_xor_sync(0xffffffffu, sum0, 1);
        sum0 += __shfl_xor_sync(0xffffffffu, sum0, 2);
        sum1 += __shfl_xor_sync(0xffffffffu, sum1, 1);
        sum1 += __shfl_xor_sync(0xffffffffu, sum1, 2);
        float a0 = __expf(m0 - nm0), a1 = __expf(m1 - nm1);
        m0 = nm0; m1 = nm1;
        l0 = l0 * a0 + sum0; l1 = l1 * a1 + sum1;
#pragma unroll
        for (int nt = 0; nt < 8; nt++) {
            acc[nt][0] *= a0; acc[nt][1] *= a0;
            acc[nt][2] *= a1; acc[nt][3] *= a1;
        }

        // ---- repack S accumulator fragments into P A-fragments (hi/lo) ----
        uint32_t ph[4][4], pl[4][4];
#pragma unroll
        for (int kt = 0; kt < 4; kt++) {
            int e = 2 * kt, o = 2 * kt + 1;
            split2(s[e][0], s[e][1], ph[kt][0], pl[kt][0]);
            split2(s[e][2], s[e][3], ph[kt][1], pl[kt][1]);
            split2(s[o][0], s[o][1], ph[kt][2], pl[kt][2]);
            split2(s[o][2], s[o][3], ph[kt][3], pl[kt][3]);
        }

        // ---- O += P @ V (split, 3 terms, term-major issue; swizzled V reads) ----
#pragma unroll
        for (int kt = 0; kt < 4; kt++) {
            uint32_t vh[8][2], vl[8][2];
#pragma unroll
            for (int p = 0; p < 4; p++) {
                uint32_t dlane = (uint32_t)(p * 16) + brow;
                uint32_t sw = ((dlane >> 3) & 3) << 4;
                uint32_t bd = sb + AT_V_HI + dlane * AT_STRB + ((uint32_t)(kt * 32 + bko) ^ sw);
                LDSM_X4(vh[2*p][0], vh[2*p][1], vh[2*p+1][0], vh[2*p+1][1], bd);
                LDSM_X4(vl[2*p][0], vl[2*p][1], vl[2*p+1][0], vl[2*p+1][1], bd + 9216);
            }
#pragma unroll
            for (int nt = 0; nt < 8; nt++) MMA_BF16(acc[nt], ph[kt], vh[nt]);
#pragma unroll
            for (int nt = 0; nt < 8; nt++) MMA_BF16(acc[nt], ph[kt], vl[nt]);
#pragma unroll
            for (int nt = 0; nt < 8; nt++) MMA_BF16(acc[nt], pl[kt], vh[nt]);
        }
    }

    // ---- epilogue: normalize and write bf16 hi/lo (concat head layout) ----
    float inv0 = 1.f / l0, inv1 = 1.f / l1;
    const int tok0 = b * SEQc + row0;
#pragma unroll
    for (int nt = 0; nt < 8; nt++) {
        int col = h * 64 + nt * 8 + ((lane & 3) << 1);
        uint32_t hi, lo;
        split2(acc[nt][0] * inv0, acc[nt][1] * inv0, hi, lo);
        *(uint32_t*)(ohi + (size_t)tok0 * 1024 + col) = hi;
        *(uint32_t*)(olo + (size_t)tok0 * 1024 + col) = lo;
        split2(acc[nt][2] * inv1, acc[nt][3] * inv1, hi, lo);
        *(uint32_t*)(ohi + (size_t)(tok0 + 8) * 1024 + col) = hi;
        *(uint32_t*)(olo + (size_t)(tok0 + 8) * 1024 + col) = lo;
    }
}

// ---------------- LayerNorm + residual ----------------
template<bool SPLITO>
__global__ void ln_residual_kernel(const float* __restrict__ resid,
                                   const float* __restrict__ v,
                                   const float* __restrict__ g,
                                   const float* __restrict__ beta,
                                   float* __restrict__ out,
                                   __nv_bfloat16* __restrict__ ohi,
                                   __nv_bfloat16* __restrict__ olo) {
    __shared__ float red[16];
    const int row = blockIdx.x;
    const int t = threadIdx.x;
    const float* vr = v + (size_t)row * D_MODELc;
    float4 xv = *(const float4*)(vr + t * 4);
    float s  = xv.x + xv.y + xv.z + xv.w;
    float s2 = xv.x * xv.x + xv.y * xv.y + xv.z * xv.z + xv.w * xv.w;
#pragma unroll
    for (int o = 16; o; o >>= 1) {
        s  += __shfl_xor_sync(0xffffffffu, s,  o);
        s2 += __shfl_xor_sync(0xffffffffu, s2, o);
    }
    int wid = t >> 5;
    if ((t & 31) == 0) { red[wid] = s; red[8 + wid] = s2; }
    __syncthreads();
    float S = 0.f, S2 = 0.f;
#pragma unroll
    for (int i = 0; i < 8; i++) { S += red[i]; S2 += red[8 + i]; }
    float mu   = S * (1.f / D_MODELc);
    float var  = S2 * (1.f / D_MODELc) - mu * mu;
    float rstd = rsqrtf(var + LN_EPSc);

    int c = t * 4;
    float4 rr = *(const float4*)(resid + (size_t)row * D_MODELc + c);
    float4 gg = *(const float4*)(g + c);
    float4 bb = *(const float4*)(beta + c);
    float4 o;
    o.x = rr.x + (xv.x - mu) * rstd * gg.x + bb.x;
    o.y = rr.y + (xv.y - mu) * rstd * gg.y + bb.y;
    o.z = rr.z + (xv.z - mu) * rstd * gg.z + bb.z;
    o.w = rr.w + (xv.w - mu) * rstd * gg.w + bb.w;
    *(float4*)(out + (size_t)row * D_MODELc + c) = o;
    if (SPLITO) {
        uint32_t h0, l0, h1, l1;
        split2(o.x, o.y, h0, l0);
        split2(o.z, o.w, h1, l1);
        *(uint2*)(ohi + (size_t)row * D_MODELc + c) = make_uint2(h0, h1);
        *(uint2*)(olo + (size_t)row * D_MODELc + c) = make_uint2(l0, l1);
    }
}

// ---------------- launch ----------------
extern "C" void kernel_launch(void* const* d_in, const int* in_sizes, int n_in,
                              void* d_out, int out_size) {
    (void)in_sizes; (void)n_in; (void)out_size;
    const float* x     = (const float*)d_in[0];
    const float* wq    = (const float*)d_in[1];
    const float* wk    = (const float*)d_in[2];
    const float* wv    = (const float*)d_in[3];
    const float* wo    = (const float*)d_in[4];
    const float* w_in  = (const float*)d_in[5];
    const float* b_in  = (const float*)d_in[6];
    const float* w_out = (const float*)d_in[7];
    const float* b_out = (const float*)d_in[8];
    const float* g1    = (const float*)d_in[9];
    const float* bt1   = (const float*)d_in[10];
    const float* g2    = (const float*)d_in[11];
    const float* bt2   = (const float*)d_in[12];
    float* out = (float*)d_out;

    float *proj, *x1, *mlp;
    __nv_bfloat16 *qkvh, *qkvl, *ahi, *alo, *bhi, *blo, *mh, *ml;
    cudaGetSymbolAddress((void**)&proj, g_proj);
    cudaGetSymbolAddress((void**)&x1,   g_x1);
    cudaGetSymbolAddress((void**)&mlp,  g_mlp);
    cudaGetSymbolAddress((void**)&qkvh, g_qkvh);
    cudaGetSymbolAddress((void**)&qkvl, g_qkvl);
    cudaGetSymbolAddress((void**)&ahi,  g_ahi);
    cudaGetSymbolAddress((void**)&alo,  g_alo);
    cudaGetSymbolAddress((void**)&bhi,  g_bhi);
    cudaGetSymbolAddress((void**)&blo,  g_blo);
    cudaGetSymbolAddress((void**)&mh,   g_mlph_hi);
    cudaGetSymbolAddress((void**)&ml,   g_mlph_lo);

    cudaFuncSetAttribute(tc_gemm_kernel<false, false>, cudaFuncAttributeMaxDynamicSharedMemorySize, TG_SMEM);
    cudaFuncSetAttribute(tc_gemm_kernel<false, true>,  cudaFuncAttributeMaxDynamicSharedMemorySize, TG_SMEM);
    cudaFuncSetAttribute(tc_gemm_kernel<true,  true>,  cudaFuncAttributeMaxDynamicSharedMemorySize, TG_SMEM);
    cudaFuncSetAttribute(attn_mma_kernel, cudaFuncAttributeMaxDynamicSharedMemorySize, AT_SMEM);

    dim3 tsb(32, 8);

    // ---- QKV projection: [4096,1024] @ [1024,3072], split bf16 output ----
    qkv_tsplit_kernel<<<dim3(2, 32, 48), tsb>>>(wq, wk, wv, bhi, blo);
    asplit_kernel<<<(NTOK * D_MODELc / 4 + 255) / 256, 256>>>(x, ahi, alo, NTOK * D_MODELc / 4);
    tc_gemm_kernel<false, true><<<dim3(24, 32), 128, TG_SMEM>>>(
        ahi, alo, bhi, blo, nullptr, nullptr, qkvh, qkvl, NTOK, 3072, 1024);

    // ---- tensor-core causal flash attention -> bf16 hi/lo (overwrites ahi/alo) ----
    attn_mma_kernel<<<dim3(SEQc / 128, BATCHc * 16), 256, AT_SMEM>>>(qkvh, qkvl, ahi, alo);

    // ---- output projection: att @ wo ----
    tsplit_kernel<<<dim3(32, 32), tsb>>>(wo, bhi, blo, 1024, 1024);
    tc_gemm_kernel<false, false><<<dim3(8, 32), 128, TG_SMEM>>>(
        ahi, alo, bhi, blo, nullptr, proj, nullptr, nullptr, NTOK, 1024, 1024);

    // ---- x1 = x + LN(proj), fused split into ahi/alo ----
    ln_residual_kernel<true><<<NTOK, 256>>>(x, proj, g1, bt1, x1, ahi, alo);

    // ---- MLP in: relu(x1 @ w_in + b_in), fused split output ----
    tsplit_kernel<<<dim3(128, 32), tsb>>>(w_in, bhi, blo, 1024, 4096);
    tc_gemm_kernel<true, true><<<dim3(32, 32), 128, TG_SMEM>>>(
        ahi, alo, bhi, blo, b_in, nullptr, mh, ml, NTOK, 4096, 1024);

    // ---- MLP out: mlph @ w_out + b_out ----
    tsplit_kernel<<<dim3(32, 128), tsb>>>(w_out, bhi, blo, 4096, 1024);
    tc_gemm_kernel<false, false><<<dim3(8, 32), 128, TG_SMEM>>>(
        mh, ml, bhi, blo, b_out, mlp, nullptr, nullptr, NTOK, 1024, 4096);

    // ---- out = x1 + LN(mlp) ----
    ln_residual_kernel<false><<<NTOK, 256>>>(x1, mlp, g2, bt2, out, nullptr, nullptr);
}